// round 7
// baseline (speedup 1.0000x reference)
#include <cuda_runtime.h>
#include <math.h>
#include <stdint.h>

// Problem constants
#define Bsz 8
#define Hd  512
#define Ls  4096
#define Nm  32
#define CL  128            // chunk length
#define NC  (Ls / CL)      // 32 chunks

// Scratch (allocation-free rule: __device__ globals)
__device__ float    g_wr[Hd * Nm];
__device__ float    g_wi[Hd * Nm];
__device__ float    g_dtar[Hd * Nm];
__device__ float    g_dtai[Hd * Nm];

__device__ uint32_t g_Ktap[Hd * CL];       // Toeplitz taps, tf32 bits, D folded into tap 0
__device__ uint32_t g_PrF[Hd * 4096];      // P  = Re(w λ^{j+1}),  A-frag order (M=128,K=32)
__device__ uint32_t g_PinF[Hd * 4096];     // -Im(w λ^{j+1}),      A-frag order
__device__ uint32_t g_LrF[Hd * 4096];      // Re(λ^{127-i}),       A-frag order (M=32,K=128)
__device__ uint32_t g_LiF[Hd * 4096];      // Im(λ^{127-i})
__device__ float    g_l128r[Hd * Nm];      // Re(λ^128)
__device__ float    g_l128i[Hd * Nm];

__device__ uint32_t g_u[(size_t)Hd * NC * CL * 8];     // u, tf32 bits, [h][c][t][b]
__device__ float2   g_slocR2[(size_t)Hd * NC * 128];   // chunk summaries [h][c][n*4+b2]
__device__ float2   g_slocI2[(size_t)Hd * NC * 128];
__device__ uint2    g_carR2[(size_t)Hd * NC * 128];    // incoming carries, tf32 bits
__device__ uint2    g_carI2[(size_t)Hd * NC * 128];

__device__ uint32_t g_Wt[2 * Hd * Hd];                 // W tf32 bits (1024x512)
__device__ uint32_t g_y[(size_t)Bsz * Hd * Ls];        // post-snake2, tf32 bits (B,H,L)

__device__ __forceinline__ uint32_t f2tf32(float f) {
    uint32_t b;
    asm("cvt.rna.tf32.f32 %0, %1;" : "=r"(b) : "f"(f));
    return b;
}

// validated tf32 mma.sync fragment layout (R5/R6):
//  A: reg0=(g,t4) reg1=(g+8,t4) reg2=(g,t4+4) reg3=(g+8,t4+4)
//  B: reg0=B[k=t4][n=g] reg1=B[k=t4+4][n=g]
//  C: c0=(g,2t4) c1=(g,2t4+1) c2=(g+8,2t4) c3=(g+8,2t4+1)
__device__ __forceinline__ void mma_tf32(float* c,
                                         uint32_t a0, uint32_t a1, uint32_t a2, uint32_t a3,
                                         uint32_t b0, uint32_t b1)
{
    asm volatile(
        "mma.sync.aligned.m16n8k8.row.col.f32.tf32.tf32.f32 "
        "{%0,%1,%2,%3}, {%4,%5,%6,%7}, {%8,%9}, {%0,%1,%2,%3};\n"
        : "+f"(c[0]), "+f"(c[1]), "+f"(c[2]), "+f"(c[3])
        : "r"(a0), "r"(a1), "r"(a2), "r"(a3), "r"(b0), "r"(b1));
}

// ---------------------------------------------------------------------------
// Kernel 1: base discretization.  w = 2*C*(lambda-1)/A, dtA terms.
// ---------------------------------------------------------------------------
__global__ void param_kernel(const float* __restrict__ log_dt,
                             const float* __restrict__ Ar,
                             const float* __restrict__ Ai,
                             const float* __restrict__ Cr,
                             const float* __restrict__ Ci)
{
    int i = blockIdx.x * blockDim.x + threadIdx.x;
    if (i >= Hd * Nm) return;
    int h = i >> 5;
    float dt = expf(log_dt[h]);
    float ar = Ar[i], ai = Ai[i];
    float er = expf(dt * ar);
    float lr = er * cosf(dt * ai);
    float li = er * sinf(dt * ai);
    float nr = lr - 1.0f, ni = li;
    float inv = 1.0f / (ar * ar + ai * ai);
    float qr = (nr * ar + ni * ai) * inv;
    float qi = (ni * ar - nr * ai) * inv;
    float cr = Cr[i], ci = Ci[i];
    g_wr[i] = 2.0f * (cr * qr - ci * qi);
    g_wi[i] = 2.0f * (cr * qi + ci * qr);
    g_dtar[i] = dt * ar;
    g_dtai[i] = dt * ai;
}

// ---------------------------------------------------------------------------
// Kernel 1b: per-h frag-ordered matrices P, Lambda + taps + lambda^128.
// One block (256 thr) per h.
// ---------------------------------------------------------------------------
__global__ void param2_kernel(const float* __restrict__ Dp)
{
    int h = blockIdx.x;
    int tid = threadIdx.x;
    __shared__ float swr[32], swi[32], sar[32], sai[32];
    if (tid < 32) {
        swr[tid] = g_wr[h * 32 + tid];
        swi[tid] = g_wi[h * 32 + tid];
        sar[tid] = g_dtar[h * 32 + tid];
        sai[tid] = g_dtai[h * 32 + tid];
    }
    __syncthreads();

    // P: M=128 (j), K=32 (n): flat ((mt*4+kc)*4+reg)*32+lane
    for (int q = tid; q < 4096; q += 256) {
        int lane = q & 31, reg = (q >> 5) & 3, kc = (q >> 7) & 3, mt = q >> 9;
        int g = lane >> 2, t4 = lane & 3;
        int row = mt * 16 + g + (reg & 1) * 8;        // j
        int col = kc * 8 + t4 + (reg >> 1) * 4;       // n
        float p = (float)(row + 1);
        float e = expf(p * sar[col]);
        float ss, cc;
        sincosf(p * sai[col], &ss, &cc);
        float lpr = e * cc, lpi = e * ss;
        g_PrF[h * 4096 + q]  = f2tf32(swr[col] * lpr - swi[col] * lpi);
        g_PinF[h * 4096 + q] = f2tf32(-(swr[col] * lpi + swi[col] * lpr));
    }
    // Lambda: M=32 (n), K=128 (i): flat ((mt*16+kc)*4+reg)*32+lane
    for (int q = tid; q < 4096; q += 256) {
        int lane = q & 31, reg = (q >> 5) & 3, kc = (q >> 7) & 15, mt = q >> 11;
        int g = lane >> 2, t4 = lane & 3;
        int row = mt * 16 + g + (reg & 1) * 8;        // n
        int col = kc * 8 + t4 + (reg >> 1) * 4;       // i
        float p = (float)(CL - 1 - col);
        float e = expf(p * sar[row]);
        float ss, cc;
        sincosf(p * sai[row], &ss, &cc);
        g_LrF[h * 4096 + q] = f2tf32(e * cc);
        g_LiF[h * 4096 + q] = f2tf32(e * ss);
    }
    // taps K[d] = sum_n Re(w λ^d), D folded into tap 0
    if (tid < CL) {
        int d = tid;
        float acc = 0.0f;
        for (int n = 0; n < 32; ++n) {
            float e = expf((float)d * sar[n]);
            float ss, cc;
            sincosf((float)d * sai[n], &ss, &cc);
            acc += swr[n] * (e * cc) - swi[n] * (e * ss);
        }
        if (d == 0) acc += Dp[h];
        g_Ktap[h * CL + d] = f2tf32(acc);
    }
    if (tid < 32) {
        float e = expf((float)CL * sar[tid]);
        float ss, cc;
        sincosf((float)CL * sai[tid], &ss, &cc);
        g_l128r[h * 32 + tid] = e * cc;
        g_l128i[h * 32 + tid] = e * ss;
    }
}

// ---------------------------------------------------------------------------
// Kernel 1c: W -> tf32 once.
// ---------------------------------------------------------------------------
__global__ void wconv_kernel(const float* __restrict__ W)
{
    int i = blockIdx.x * blockDim.x + threadIdx.x;
    if (i >= 2 * Hd * Hd) return;
    g_Wt[i] = f2tf32(W[i]);
}

// ---------------------------------------------------------------------------
// Kernel A: per (h,c) warp: snake1, store u frags, chunk summary Lam@U.
// 8 warps/block = 8 chunks of one h.  Fully parallel (16384 warps).
// ---------------------------------------------------------------------------
__global__ __launch_bounds__(256)
void scanA_kernel(const float* __restrict__ x,
                  const float* __restrict__ alpha1)
{
    const int tid  = threadIdx.x;
    const int wp   = tid >> 5;
    const int lane = tid & 31;
    const int g    = lane >> 2;
    const int t4   = lane & 3;
    const int h    = blockIdx.x >> 2;
    const int c    = ((blockIdx.x & 3) << 3) + wp;

    const float a1v  = alpha1[h];
    const float inv1 = 1.0f / (a1v + 1e-9f);

    const size_t xbase = (size_t)g * (Hd * Ls) + (size_t)h * Ls + c * CL;
    const size_t ubase = ((size_t)(h * NC + c)) * (CL * 8);

    uint32_t uB[32];
    #pragma unroll
    for (int kc = 0; kc < 16; ++kc)
        #pragma unroll
        for (int r = 0; r < 2; ++r) {
            int t = kc * 8 + t4 + 4 * r;
            float xv = x[xbase + t];
            float sn = __sinf(a1v * xv);
            float u  = fmaf(sn * sn, inv1, xv);
            uint32_t bits = f2tf32(u);
            uB[kc * 2 + r] = bits;
            g_u[ubase + t * 8 + g] = bits;
        }

    const uint32_t* Lr = g_LrF + h * 4096;
    const uint32_t* Li = g_LiF + h * 4096;
    float AccR[2][4] = {}, AccI[2][4] = {};
    #pragma unroll
    for (int kc = 0; kc < 16; ++kc)
        #pragma unroll
        for (int mt = 0; mt < 2; ++mt) {
            int base = ((mt * 16 + kc) * 4) * 32 + lane;
            mma_tf32(AccR[mt], Lr[base], Lr[base + 32], Lr[base + 64], Lr[base + 96],
                     uB[kc * 2], uB[kc * 2 + 1]);
            mma_tf32(AccI[mt], Li[base], Li[base + 32], Li[base + 64], Li[base + 96],
                     uB[kc * 2], uB[kc * 2 + 1]);
        }

    // store chunk summary: C-frag (c0,c1)=(row g, cols 2t4,2t4+1), (c2,c3)=row g+8
    size_t sbase = (size_t)(h * NC + c) * 128;
    #pragma unroll
    for (int mt = 0; mt < 2; ++mt)
        #pragma unroll
        for (int rr = 0; rr < 2; ++rr) {
            int n = mt * 16 + rr * 8 + g;
            g_slocR2[sbase + n * 4 + t4] = make_float2(AccR[mt][rr * 2], AccR[mt][rr * 2 + 1]);
            g_slocI2[sbase + n * 4 + t4] = make_float2(AccI[mt][rr * 2], AccI[mt][rr * 2 + 1]);
        }
}

// ---------------------------------------------------------------------------
// Kernel B: exclusive scan of chunk carries.  Thread = (h, n, b-pair).
// carry[c] = l128 * carry[c-1] + sloc[c-1... ] (exclusive), fp32 chain,
// emitted as tf32 bits in frag-friendly [n*8+b] order.
// ---------------------------------------------------------------------------
__global__ __launch_bounds__(256)
void scanB_kernel()
{
    int gid = blockIdx.x * 256 + threadIdx.x;     // 0..65535
    int h   = gid >> 7;
    int idx = gid & 127;                          // n*4 + b2
    int n   = idx >> 2;

    float lr = g_l128r[h * 32 + n];
    float li = g_l128i[h * 32 + n];

    size_t base = (size_t)h * NC * 128 + idx;
    float cr0 = 0.f, ci0 = 0.f, cr1 = 0.f, ci1 = 0.f;

    #pragma unroll 1
    for (int c = 0; c < NC; ++c) {
        size_t k = base + (size_t)c * 128;
        g_carR2[k] = make_uint2(f2tf32(cr0), f2tf32(cr1));
        g_carI2[k] = make_uint2(f2tf32(ci0), f2tf32(ci1));
        float2 slr = g_slocR2[k];
        float2 sli = g_slocI2[k];
        float nr0 = fmaf(lr, cr0, fmaf(-li, ci0, slr.x));
        float ni0 = fmaf(lr, ci0, fmaf( li, cr0, sli.x));
        float nr1 = fmaf(lr, cr1, fmaf(-li, ci1, slr.y));
        float ni1 = fmaf(lr, ci1, fmaf( li, cr1, sli.y));
        cr0 = nr0; ci0 = ni0; cr1 = nr1; ci1 = ni1;
    }
}

// ---------------------------------------------------------------------------
// Kernel C: per (h,c) warp: Y = T@U + Pr@S + Pin@S, snake2, store y.
// D-skip folded into Toeplitz tap 0.  Fully parallel (16384 warps).
// ---------------------------------------------------------------------------
__global__ __launch_bounds__(256)
void scanC_kernel(const float* __restrict__ alpha2)
{
    __shared__ uint32_t sKt[CL];

    const int tid  = threadIdx.x;
    const int wp   = tid >> 5;
    const int lane = tid & 31;
    const int g    = lane >> 2;
    const int t4   = lane & 3;
    const int h    = blockIdx.x >> 2;
    const int c    = ((blockIdx.x & 3) << 3) + wp;

    if (tid < CL) sKt[tid] = g_Ktap[h * CL + tid];
    __syncthreads();

    // u fragments
    const size_t ubase = ((size_t)(h * NC + c)) * (CL * 8);
    uint32_t uB[32];
    #pragma unroll
    for (int kc = 0; kc < 16; ++kc)
        #pragma unroll
        for (int r = 0; r < 2; ++r)
            uB[kc * 2 + r] = g_u[ubase + (kc * 8 + t4 + 4 * r) * 8 + g];

    // carry fragments (B-operand: k = n, n-dim = b)
    const uint32_t* carR = (const uint32_t*)g_carR2 + (size_t)(h * NC + c) * 256;
    const uint32_t* carI = (const uint32_t*)g_carI2 + (size_t)(h * NC + c) * 256;
    uint32_t SrB[8], SiB[8];
    #pragma unroll
    for (int kc2 = 0; kc2 < 4; ++kc2)
        #pragma unroll
        for (int r = 0; r < 2; ++r) {
            int n = kc2 * 8 + t4 + 4 * r;
            SrB[kc2 * 2 + r] = carR[n * 8 + g];
            SiB[kc2 * 2 + r] = carI[n * 8 + g];
        }

    float yC[8][4] = {};

    // Toeplitz path (lower-triangular block skip)
    #pragma unroll
    for (int hh = 0; hh < 8; ++hh) {
        const int kmax = 2 * hh + 2;
        #pragma unroll
        for (int kc = 0; kc < 16; ++kc) {
            if (kc >= kmax) break;               // compile-time pruned
            int d0 = hh * 16 + g - (kc * 8 + t4);
            int d1 = d0 + 8, d2 = d0 - 4, d3 = d0 + 4;
            uint32_t a0 = (d0 >= 0) ? sKt[d0] : 0u;
            uint32_t a1 = (d1 >= 0) ? sKt[d1] : 0u;
            uint32_t a2 = (d2 >= 0) ? sKt[d2] : 0u;
            uint32_t a3 = (d3 >= 0) ? sKt[d3] : 0u;
            mma_tf32(yC[hh], a0, a1, a2, a3, uB[kc * 2], uB[kc * 2 + 1]);
        }
    }

    // carry path
    const uint32_t* PrF  = g_PrF  + h * 4096;
    const uint32_t* PinF = g_PinF + h * 4096;
    #pragma unroll
    for (int hh = 0; hh < 8; ++hh)
        #pragma unroll
        for (int kc2 = 0; kc2 < 4; ++kc2) {
            int base = ((hh * 4 + kc2) * 4) * 32 + lane;
            mma_tf32(yC[hh], PrF[base], PrF[base + 32], PrF[base + 64], PrF[base + 96],
                     SrB[kc2 * 2], SrB[kc2 * 2 + 1]);
            mma_tf32(yC[hh], PinF[base], PinF[base + 32], PinF[base + 64], PinF[base + 96],
                     SiB[kc2 * 2], SiB[kc2 * 2 + 1]);
        }

    // epilogue: snake2, store tf32 bits into (B,H,L) layout
    const float a2v  = alpha2[h];
    const float inv2 = 1.0f / (a2v + 1e-9f);
    #pragma unroll
    for (int hh = 0; hh < 8; ++hh)
        #pragma unroll
        for (int cc = 0; cc < 4; ++cc) {
            int j = hh * 16 + g + 8 * (cc >> 1);
            int b = 2 * t4 + (cc & 1);
            float yv = yC[hh][cc];
            float s2 = __sinf(a2v * yv);
            yv = fmaf(s2 * s2, inv2, yv);
            g_y[((size_t)b * Hd + h) * Ls + c * CL + j] = f2tf32(yv);
        }
}

// ---------------------------------------------------------------------------
// Kernel 3: fused 1x1 conv GEMM (tf32 mma.sync) + GLU + residual (unchanged)
// ---------------------------------------------------------------------------
#define BK 16
#define SWS (BK + 4)
#define SYS (128 + 8)

__device__ __forceinline__ void cp_async16(uint32_t smem, const void* gmem) {
    asm volatile("cp.async.cg.shared.global [%0], [%1], 16;\n" :: "r"(smem), "l"(gmem));
}
__device__ __forceinline__ void cp_commit() {
    asm volatile("cp.async.commit_group;\n");
}
template <int N> __device__ __forceinline__ void cp_wait() {
    asm volatile("cp.async.wait_group %0;\n" :: "n"(N));
}

__global__ __launch_bounds__(256, 2)
void gemm_glu_kernel(const float* __restrict__ bias,
                     const float* __restrict__ X,
                     float* __restrict__ out)
{
    __shared__ uint32_t sW[2][128][SWS];
    __shared__ uint32_t sY[2][BK][SYS];

    const int tid = threadIdx.x;
    const int lane = tid & 31;
    const int wid = tid >> 5;
    const int wm = wid >> 2;
    const int wn = wid & 3;
    const int t4 = lane & 3;
    const int g  = lane >> 2;

    const int l0 = blockIdx.x * 128;
    const int r0 = blockIdx.y * 64;
    const int bb = blockIdx.z;

    const uint32_t* Yb = g_y + (size_t)bb * Hd * Ls;

    const uint32_t swb = (uint32_t)__cvta_generic_to_shared(&sW[0][0][0]);
    const uint32_t syb = (uint32_t)__cvta_generic_to_shared(&sY[0][0][0]);

    int wf0 = tid, wf1 = tid + 256;
    int wrow0 = wf0 >> 2, wc0 = (wf0 & 3) << 2;
    int wrow1 = wf1 >> 2, wc1 = (wf1 & 3) << 2;
    int wsrc0 = (r0 + wrow0 + (wrow0 >= 64 ? 448 : 0)) * Hd;
    int wsrc1 = (r0 + wrow1 + (wrow1 >= 64 ? 448 : 0)) * Hd;
    int yk0 = wf0 >> 5, yc0 = (wf0 & 31) << 2;
    int yk1 = wf1 >> 5, yc1 = (wf1 & 31) << 2;

    float acc[2][2][4][4];
    #pragma unroll
    for (int a = 0; a < 2; ++a)
        #pragma unroll
        for (int m = 0; m < 2; ++m)
            #pragma unroll
            for (int n = 0; n < 4; ++n)
                #pragma unroll
                for (int q = 0; q < 4; ++q) acc[a][m][n][q] = 0.0f;

    #define LOAD_CHUNK(KC, BUF) do {                                              \
        int _k0 = (KC) * BK;                                                      \
        cp_async16(swb + (((BUF)*128 + wrow0) * SWS + wc0) * 4,                   \
                   g_Wt + wsrc0 + _k0 + wc0);                                     \
        cp_async16(swb + (((BUF)*128 + wrow1) * SWS + wc1) * 4,                   \
                   g_Wt + wsrc1 + _k0 + wc1);                                     \
        cp_async16(syb + (((BUF)*BK + yk0) * SYS + yc0) * 4,                      \
                   Yb + (size_t)(_k0 + yk0) * Ls + l0 + yc0);                     \
        cp_async16(syb + (((BUF)*BK + yk1) * SYS + yc1) * 4,                      \
                   Yb + (size_t)(_k0 + yk1) * Ls + l0 + yc1);                     \
    } while (0)

    LOAD_CHUNK(0, 0); cp_commit();
    LOAD_CHUNK(1, 1); cp_commit();

    const int NCH = Hd / BK;
    #pragma unroll 1
    for (int kc = 0; kc < NCH; ++kc) {
        if (kc < NCH - 1) cp_wait<1>(); else cp_wait<0>();
        __syncthreads();
        int buf = kc & 1;

        #pragma unroll
        for (int ks = 0; ks < 2; ++ks) {
            int kk = ks * 8 + t4;
            uint32_t B0[4], B1[4];
            #pragma unroll
            for (int ni = 0; ni < 4; ++ni) {
                int col = wn * 32 + ni * 8 + g;
                B0[ni] = sY[buf][kk][col];
                B1[ni] = sY[buf][kk + 4][col];
            }
            #pragma unroll
            for (int half = 0; half < 2; ++half) {
                #pragma unroll
                for (int mi = 0; mi < 2; ++mi) {
                    int rb = half * 64 + wm * 32 + mi * 16 + g;
                    uint32_t a0 = sW[buf][rb][kk];
                    uint32_t a1 = sW[buf][rb + 8][kk];
                    uint32_t a2 = sW[buf][rb][kk + 4];
                    uint32_t a3 = sW[buf][rb + 8][kk + 4];
                    #pragma unroll
                    for (int ni = 0; ni < 4; ++ni)
                        mma_tf32(acc[half][mi][ni], a0, a1, a2, a3, B0[ni], B1[ni]);
                }
            }
        }
        __syncthreads();
        if (kc + 2 < NCH) { LOAD_CHUNK(kc + 2, buf); cp_commit(); }
    }
    #undef LOAD_CHUNK

    const float* Xb = X   + (size_t)bb * Hd * Ls;
    float*       Ob = out + (size_t)bb * Hd * Ls;

    #pragma unroll
    for (int mi = 0; mi < 2; ++mi) {
        int o = r0 + wm * 32 + mi * 16 + g;
        float ba0 = bias[o];
        float bB0 = bias[o + 512];
        float ba8 = bias[o + 8];
        float bB8 = bias[o + 520];
        #pragma unroll
        for (int ni = 0; ni < 4; ++ni) {
            int l = l0 + wn * 32 + ni * 8 + 2 * t4;
            const float* A = acc[0][mi][ni];
            const float* Bc = acc[1][mi][ni];

            float2 xv0 = *(const float2*)(Xb + (size_t)o * Ls + l);
            float2 xv8 = *(const float2*)(Xb + (size_t)(o + 8) * Ls + l);

            float av, bv, sg;
            float2 ov0, ov8;
            av = A[0] + ba0; bv = Bc[0] + bB0; sg = 1.0f / (1.0f + expf(-bv));
            ov0.x = xv0.x + av * sg;
            av = A[1] + ba0; bv = Bc[1] + bB0; sg = 1.0f / (1.0f + expf(-bv));
            ov0.y = xv0.y + av * sg;
            av = A[2] + ba8; bv = Bc[2] + bB8; sg = 1.0f / (1.0f + expf(-bv));
            ov8.x = xv8.x + av * sg;
            av = A[3] + ba8; bv = Bc[3] + bB8; sg = 1.0f / (1.0f + expf(-bv));
            ov8.y = xv8.y + av * sg;

            *(float2*)(Ob + (size_t)o * Ls + l) = ov0;
            *(float2*)(Ob + (size_t)(o + 8) * Ls + l) = ov8;
        }
    }
}

// ---------------------------------------------------------------------------
extern "C" void kernel_launch(void* const* d_in, const int* in_sizes, int n_in,
                              void* d_out, int out_size)
{
    const float* x      = (const float*)d_in[0];
    const float* alpha1 = (const float*)d_in[1];
    const float* log_dt = (const float*)d_in[2];
    const float* Ar     = (const float*)d_in[3];
    const float* Ai     = (const float*)d_in[4];
    const float* Cr     = (const float*)d_in[5];
    const float* Ci     = (const float*)d_in[6];
    const float* D      = (const float*)d_in[7];
    const float* alpha2 = (const float*)d_in[8];
    const float* W      = (const float*)d_in[9];
    const float* bconv  = (const float*)d_in[10];
    float* out = (float*)d_out;

    param_kernel<<<(Hd * Nm + 255) / 256, 256>>>(log_dt, Ar, Ai, Cr, Ci);
    param2_kernel<<<Hd, 256>>>(D);
    wconv_kernel<<<(2 * Hd * Hd + 255) / 256, 256>>>(W);

    scanA_kernel<<<Hd * 4, 256>>>(x, alpha1);      // 16384 warps
    scanB_kernel<<<(Hd * 128) / 256, 256>>>();     // 65536 threads
    scanC_kernel<<<Hd * 4, 256>>>(alpha2);         // 16384 warps

    dim3 grid(Ls / 128, Hd / 64, Bsz);
    gemm_glu_kernel<<<grid, 256>>>(bconv, x, out);
}

// round 8
// speedup vs baseline: 1.1677x; 1.1677x over previous
#include <cuda_runtime.h>
#include <math.h>
#include <stdint.h>

// Problem constants
#define Bsz 8
#define Hd  512
#define Ls  4096
#define Nm  32
#define CL  128            // chunk length
#define NC  (Ls / CL)      // 32 chunks

// Scratch (allocation-free rule: __device__ globals)
__device__ float    g_wr[Hd * Nm];
__device__ float    g_wi[Hd * Nm];
__device__ float    g_dtar[Hd * Nm];
__device__ float    g_dtai[Hd * Nm];

__device__ uint32_t g_Ktap[Hd * CL];        // Toeplitz taps, tf32 bits, D folded into tap 0
// Fragment tables, reg-contiguous per lane: idx = (frag*32 + lane) -> uint4 of 4 regs
__device__ uint4    g_PrF4[Hd * 1024];      // P  = Re(w λ^{j+1}),  A-frag (M=128,K=32), 32 frags
__device__ uint4    g_PinF4[Hd * 1024];     // -Im(w λ^{j+1})
__device__ uint4    g_LrF4[Hd * 1024];      // Re(λ^{127-i}),       A-frag (M=32,K=128), 32 frags
__device__ uint4    g_LiF4[Hd * 1024];      // Im(λ^{127-i})
__device__ float    g_l128r[Hd * Nm];       // Re(λ^128)
__device__ float    g_l128i[Hd * Nm];

__device__ uint4    g_u4[(size_t)Hd * NC * 256];       // u frags, lane-linear uint4
__device__ float2   g_slocR2[(size_t)Hd * NC * 128];   // chunk summaries [h][c][n*4+b2]
__device__ float2   g_slocI2[(size_t)Hd * NC * 128];
__device__ uint2    g_carR2[(size_t)Hd * NC * 128];    // incoming carries, tf32 bits
__device__ uint2    g_carI2[(size_t)Hd * NC * 128];

__device__ uint32_t g_WtF[2 * Hd * Hd];                // W tf32 bits, A-frag order per 64-row tile
__device__ uint32_t g_y[(size_t)Bsz * Hd * Ls];        // post-snake2, tf32 bits (B,H,L)

__device__ __forceinline__ uint32_t f2tf32(float f) {
    uint32_t b;
    asm("cvt.rna.tf32.f32 %0, %1;" : "=r"(b) : "f"(f));
    return b;
}

// validated tf32 mma.sync fragment layout (R5-R7):
//  A: reg0=(g,t4) reg1=(g+8,t4) reg2=(g,t4+4) reg3=(g+8,t4+4)
//  B: reg0=B[k=t4][n=g] reg1=B[k=t4+4][n=g]
//  C: c0=(g,2t4) c1=(g,2t4+1) c2=(g+8,2t4) c3=(g+8,2t4+1)
__device__ __forceinline__ void mma_tf32(float* c,
                                         uint32_t a0, uint32_t a1, uint32_t a2, uint32_t a3,
                                         uint32_t b0, uint32_t b1)
{
    asm volatile(
        "mma.sync.aligned.m16n8k8.row.col.f32.tf32.tf32.f32 "
        "{%0,%1,%2,%3}, {%4,%5,%6,%7}, {%8,%9}, {%0,%1,%2,%3};\n"
        : "+f"(c[0]), "+f"(c[1]), "+f"(c[2]), "+f"(c[3])
        : "r"(a0), "r"(a1), "r"(a2), "r"(a3), "r"(b0), "r"(b1));
}

// ---------------------------------------------------------------------------
// Kernel 1: base discretization.  w = 2*C*(lambda-1)/A, dtA terms.
// ---------------------------------------------------------------------------
__global__ void param_kernel(const float* __restrict__ log_dt,
                             const float* __restrict__ Ar,
                             const float* __restrict__ Ai,
                             const float* __restrict__ Cr,
                             const float* __restrict__ Ci)
{
    int i = blockIdx.x * blockDim.x + threadIdx.x;
    if (i >= Hd * Nm) return;
    int h = i >> 5;
    float dt = expf(log_dt[h]);
    float ar = Ar[i], ai = Ai[i];
    float er = expf(dt * ar);
    float lr = er * cosf(dt * ai);
    float li = er * sinf(dt * ai);
    float nr = lr - 1.0f, ni = li;
    float inv = 1.0f / (ar * ar + ai * ai);
    float qr = (nr * ar + ni * ai) * inv;
    float qi = (ni * ar - nr * ai) * inv;
    float cr = Cr[i], ci = Ci[i];
    g_wr[i] = 2.0f * (cr * qr - ci * qi);
    g_wi[i] = 2.0f * (cr * qi + ci * qr);
    g_dtar[i] = dt * ar;
    g_dtai[i] = dt * ai;
}

// ---------------------------------------------------------------------------
// Kernel 1b: per-h frag tables P, Lambda (reg-contiguous per lane) + taps
// + lambda^128.  One block (256 thr) per h.
// ---------------------------------------------------------------------------
__global__ void param2_kernel(const float* __restrict__ Dp)
{
    int h = blockIdx.x;
    int tid = threadIdx.x;
    __shared__ float swr[32], swi[32], sar[32], sai[32];
    if (tid < 32) {
        swr[tid] = g_wr[h * 32 + tid];
        swi[tid] = g_wi[h * 32 + tid];
        sar[tid] = g_dtar[h * 32 + tid];
        sai[tid] = g_dtai[h * 32 + tid];
    }
    __syncthreads();

    // P: q = hh*512 + kcf*128 + lane*4 + reg  (frag = hh*4+kcf)
    for (int q = tid; q < 4096; q += 256) {
        int reg = q & 3, lane = (q >> 2) & 31, kcf = (q >> 7) & 3, hh = q >> 9;
        int g = lane >> 2, t4 = lane & 3;
        int row = hh * 16 + g + (reg & 1) * 8;        // j
        int col = kcf * 8 + t4 + (reg >> 1) * 4;      // n
        float p = (float)(row + 1);
        float e = expf(p * sar[col]);
        float ss, cc;
        sincosf(p * sai[col], &ss, &cc);
        float lpr = e * cc, lpi = e * ss;
        ((uint32_t*)g_PrF4)[h * 4096 + q]  = f2tf32(swr[col] * lpr - swi[col] * lpi);
        ((uint32_t*)g_PinF4)[h * 4096 + q] = f2tf32(-(swr[col] * lpi + swi[col] * lpr));
    }
    // Lambda: q = mt*2048 + kc*128 + lane*4 + reg  (frag = mt*16+kc)
    for (int q = tid; q < 4096; q += 256) {
        int reg = q & 3, lane = (q >> 2) & 31, kc = (q >> 7) & 15, mt = q >> 11;
        int g = lane >> 2, t4 = lane & 3;
        int row = mt * 16 + g + (reg & 1) * 8;        // n
        int col = kc * 8 + t4 + (reg >> 1) * 4;       // i
        float p = (float)(CL - 1 - col);
        float e = expf(p * sar[row]);
        float ss, cc;
        sincosf(p * sai[row], &ss, &cc);
        ((uint32_t*)g_LrF4)[h * 4096 + q] = f2tf32(e * cc);
        ((uint32_t*)g_LiF4)[h * 4096 + q] = f2tf32(e * ss);
    }
    // taps K[d] = sum_n Re(w λ^d), D folded into tap 0
    if (tid < CL) {
        int d = tid;
        float acc = 0.0f;
        for (int n = 0; n < 32; ++n) {
            float e = expf((float)d * sar[n]);
            float ss, cc;
            sincosf((float)d * sai[n], &ss, &cc);
            acc += swr[n] * (e * cc) - swi[n] * (e * ss);
        }
        if (d == 0) acc += Dp[h];
        g_Ktap[h * CL + d] = f2tf32(acc);
    }
    if (tid < 32) {
        float e = expf((float)CL * sar[tid]);
        float ss, cc;
        sincosf((float)CL * sai[tid], &ss, &cc);
        g_l128r[h * 32 + tid] = e * cc;
        g_l128i[h * 32 + tid] = e * ss;
    }
}

// ---------------------------------------------------------------------------
// Kernel 1c: W -> tf32 in A-fragment order.
// Per 64-row tile: q = kc*2048 + ks*1024 + m8*128 + lane*4 + reg
//   m8 = half*4 + wm*2 + mi; row = tile*64 + (m8&3)*16 + g + (reg&1)*8 + half*512
//   k = kc*16 + ks*8 + t4 + (reg>>1)*4
// ---------------------------------------------------------------------------
__global__ void wconv_kernel(const float* __restrict__ W)
{
    int i = blockIdx.x * blockDim.x + threadIdx.x;
    if (i >= 2 * Hd * Hd) return;
    int tile = i >> 16;
    int q = i & 65535;
    int reg = q & 3, lane = (q >> 2) & 31, m8 = (q >> 7) & 7, ks = (q >> 10) & 1, kc = q >> 11;
    int g = lane >> 2, t4 = lane & 3;
    int half = m8 >> 2, wmmi = m8 & 3;
    int row = tile * 64 + wmmi * 16 + g + (reg & 1) * 8 + half * 512;
    int k = kc * 16 + ks * 8 + t4 + (reg >> 1) * 4;
    g_WtF[i] = f2tf32(W[row * Hd + k]);
}

// ---------------------------------------------------------------------------
// Kernel A: per (h,c) warp: snake1 (x staged via smem), store u frags as
// lane-linear uint4, chunk summary Lam@U.  16384 warps.
// ---------------------------------------------------------------------------
__global__ __launch_bounds__(256)
void scanA_kernel(const float* __restrict__ x,
                  const float* __restrict__ alpha1)
{
    __shared__ float sX[8][8 * 132];     // per warp: 8 b-rows x 132 (pad)

    const int tid  = threadIdx.x;
    const int wp   = tid >> 5;
    const int lane = tid & 31;
    const int g    = lane >> 2;
    const int t4   = lane & 3;
    const int h    = blockIdx.x >> 2;
    const int c    = ((blockIdx.x & 3) << 3) + wp;

    const float a1v  = alpha1[h];
    const float inv1 = 1.0f / (a1v + 1e-9f);

    // coalesced x load: 8 rows x 128 floats, float4 per lane per row
    #pragma unroll
    for (int bb = 0; bb < 8; ++bb) {
        float4 v = *(const float4*)(x + ((size_t)bb * Hd + h) * Ls + c * CL + lane * 4);
        *(float4*)&sX[wp][bb * 132 + lane * 4] = v;
    }
    __syncwarp();

    // snake1 + frag build (conflict-free LDS gather) + coalesced u store
    uint32_t uB[32];
    #pragma unroll
    for (int kc = 0; kc < 16; ++kc)
        #pragma unroll
        for (int r = 0; r < 2; ++r) {
            int t = kc * 8 + t4 + 4 * r;
            float xv = sX[wp][g * 132 + t];
            float sn = __sinf(a1v * xv);
            float u  = fmaf(sn * sn, inv1, xv);
            uB[kc * 2 + r] = f2tf32(u);
        }
    const size_t ubase4 = (size_t)(h * NC + c) * 256;
    #pragma unroll
    for (int q = 0; q < 8; ++q)
        g_u4[ubase4 + q * 32 + lane] =
            make_uint4(uB[4 * q], uB[4 * q + 1], uB[4 * q + 2], uB[4 * q + 3]);

    // chunk summary: Lam @ U  (complex)
    const uint4* Lr = g_LrF4 + h * 1024;
    const uint4* Li = g_LiF4 + h * 1024;
    float AccR[2][4] = {}, AccI[2][4] = {};
    #pragma unroll
    for (int kc = 0; kc < 16; ++kc)
        #pragma unroll
        for (int mt = 0; mt < 2; ++mt) {
            uint4 ar = Lr[(mt * 16 + kc) * 32 + lane];
            uint4 ai = Li[(mt * 16 + kc) * 32 + lane];
            mma_tf32(AccR[mt], ar.x, ar.y, ar.z, ar.w, uB[kc * 2], uB[kc * 2 + 1]);
            mma_tf32(AccI[mt], ai.x, ai.y, ai.z, ai.w, uB[kc * 2], uB[kc * 2 + 1]);
        }

    // store chunk summary (C-frag layout)
    size_t sbase = (size_t)(h * NC + c) * 128;
    #pragma unroll
    for (int mt = 0; mt < 2; ++mt)
        #pragma unroll
        for (int rr = 0; rr < 2; ++rr) {
            int n = mt * 16 + rr * 8 + g;
            g_slocR2[sbase + n * 4 + t4] = make_float2(AccR[mt][rr * 2], AccR[mt][rr * 2 + 1]);
            g_slocI2[sbase + n * 4 + t4] = make_float2(AccI[mt][rr * 2], AccI[mt][rr * 2 + 1]);
        }
}

// ---------------------------------------------------------------------------
// Kernel B: exclusive scan of chunk carries (unchanged, validated R7).
// ---------------------------------------------------------------------------
__global__ __launch_bounds__(256)
void scanB_kernel()
{
    int gid = blockIdx.x * 256 + threadIdx.x;
    int h   = gid >> 7;
    int idx = gid & 127;
    int n   = idx >> 2;

    float lr = g_l128r[h * 32 + n];
    float li = g_l128i[h * 32 + n];

    size_t base = (size_t)h * NC * 128 + idx;
    float cr0 = 0.f, ci0 = 0.f, cr1 = 0.f, ci1 = 0.f;

    #pragma unroll 1
    for (int c = 0; c < NC; ++c) {
        size_t k = base + (size_t)c * 128;
        g_carR2[k] = make_uint2(f2tf32(cr0), f2tf32(cr1));
        g_carI2[k] = make_uint2(f2tf32(ci0), f2tf32(ci1));
        float2 slr = g_slocR2[k];
        float2 sli = g_slocI2[k];
        float nr0 = fmaf(lr, cr0, fmaf(-li, ci0, slr.x));
        float ni0 = fmaf(lr, ci0, fmaf( li, cr0, sli.x));
        float nr1 = fmaf(lr, cr1, fmaf(-li, ci1, slr.y));
        float ni1 = fmaf(lr, ci1, fmaf( li, cr1, sli.y));
        cr0 = nr0; ci0 = ni0; cr1 = nr1; ci1 = ni1;
    }
}

// ---------------------------------------------------------------------------
// Kernel C: per (h,c) warp: Y = T@U + Pr@S + Pin@S, snake2, store y.
// u via lane-linear uint4; P frags via LDG.128.  16384 warps.
// ---------------------------------------------------------------------------
__global__ __launch_bounds__(256)
void scanC_kernel(const float* __restrict__ alpha2)
{
    __shared__ uint32_t sKt[CL];

    const int tid  = threadIdx.x;
    const int wp   = tid >> 5;
    const int lane = tid & 31;
    const int g    = lane >> 2;
    const int t4   = lane & 3;
    const int h    = blockIdx.x >> 2;
    const int c    = ((blockIdx.x & 3) << 3) + wp;

    if (tid < CL) sKt[tid] = g_Ktap[h * CL + tid];
    __syncthreads();

    // u fragments (coalesced uint4)
    const size_t ubase4 = (size_t)(h * NC + c) * 256;
    uint32_t uB[32];
    #pragma unroll
    for (int q = 0; q < 8; ++q) {
        uint4 v = g_u4[ubase4 + q * 32 + lane];
        uB[4 * q] = v.x; uB[4 * q + 1] = v.y; uB[4 * q + 2] = v.z; uB[4 * q + 3] = v.w;
    }

    // carry fragments (B-operand: k = n, n-dim = b)
    const uint32_t* carR = (const uint32_t*)g_carR2 + (size_t)(h * NC + c) * 256;
    const uint32_t* carI = (const uint32_t*)g_carI2 + (size_t)(h * NC + c) * 256;
    uint32_t SrB[8], SiB[8];
    #pragma unroll
    for (int kc2 = 0; kc2 < 4; ++kc2)
        #pragma unroll
        for (int r = 0; r < 2; ++r) {
            int n = kc2 * 8 + t4 + 4 * r;
            SrB[kc2 * 2 + r] = carR[n * 8 + g];
            SiB[kc2 * 2 + r] = carI[n * 8 + g];
        }

    float yC[8][4] = {};

    // Toeplitz path (lower-triangular block skip)
    #pragma unroll
    for (int hh = 0; hh < 8; ++hh) {
        const int kmax = 2 * hh + 2;
        #pragma unroll
        for (int kc = 0; kc < 16; ++kc) {
            if (kc >= kmax) break;               // compile-time pruned
            int d0 = hh * 16 + g - (kc * 8 + t4);
            int d1 = d0 + 8, d2 = d0 - 4, d3 = d0 + 4;
            uint32_t a0 = (d0 >= 0) ? sKt[d0] : 0u;
            uint32_t a1 = (d1 >= 0) ? sKt[d1] : 0u;
            uint32_t a2 = (d2 >= 0) ? sKt[d2] : 0u;
            uint32_t a3 = (d3 >= 0) ? sKt[d3] : 0u;
            mma_tf32(yC[hh], a0, a1, a2, a3, uB[kc * 2], uB[kc * 2 + 1]);
        }
    }

    // carry path (frag LDG.128)
    const uint4* PrF  = g_PrF4  + h * 1024;
    const uint4* PinF = g_PinF4 + h * 1024;
    #pragma unroll
    for (int hh = 0; hh < 8; ++hh)
        #pragma unroll
        for (int kc2 = 0; kc2 < 4; ++kc2) {
            uint4 pa = PrF[(hh * 4 + kc2) * 32 + lane];
            uint4 pb = PinF[(hh * 4 + kc2) * 32 + lane];
            mma_tf32(yC[hh], pa.x, pa.y, pa.z, pa.w, SrB[kc2 * 2], SrB[kc2 * 2 + 1]);
            mma_tf32(yC[hh], pb.x, pb.y, pb.z, pb.w, SiB[kc2 * 2], SiB[kc2 * 2 + 1]);
        }

    // epilogue: snake2, store tf32 bits into (B,H,L) layout
    const float a2v  = alpha2[h];
    const float inv2 = 1.0f / (a2v + 1e-9f);
    #pragma unroll
    for (int hh = 0; hh < 8; ++hh)
        #pragma unroll
        for (int cc = 0; cc < 4; ++cc) {
            int j = hh * 16 + g + 8 * (cc >> 1);
            int b = 2 * t4 + (cc & 1);
            float yv = yC[hh][cc];
            float s2 = __sinf(a2v * yv);
            yv = fmaf(s2 * s2, inv2, yv);
            g_y[((size_t)b * Hd + h) * Ls + c * CL + j] = f2tf32(yv);
        }
}

// ---------------------------------------------------------------------------
// Kernel 3: fused 1x1 conv GEMM (tf32 mma.sync) + GLU + residual.
// W staged in A-frag order (LDS.128 per fragment).
// ---------------------------------------------------------------------------
#define BK 16
#define SYS (128 + 8)

__device__ __forceinline__ void cp_async16(uint32_t smem, const void* gmem) {
    asm volatile("cp.async.cg.shared.global [%0], [%1], 16;\n" :: "r"(smem), "l"(gmem));
}
__device__ __forceinline__ void cp_commit() {
    asm volatile("cp.async.commit_group;\n");
}
template <int N> __device__ __forceinline__ void cp_wait() {
    asm volatile("cp.async.wait_group %0;\n" :: "n"(N));
}

__global__ __launch_bounds__(256, 2)
void gemm_glu_kernel(const float* __restrict__ bias,
                     const float* __restrict__ X,
                     float* __restrict__ out)
{
    __shared__ uint4    sW4[2][512];          // frag-ordered W chunk (8KB per buf)
    __shared__ uint32_t sY[2][BK][SYS];

    const int tid = threadIdx.x;
    const int lane = tid & 31;
    const int wid = tid >> 5;
    const int wm = wid >> 2;
    const int wn = wid & 3;
    const int t4 = lane & 3;
    const int g  = lane >> 2;

    const int l0 = blockIdx.x * 128;
    const int r0 = blockIdx.y * 64;
    const int bb = blockIdx.z;

    const uint32_t* Yb = g_y + (size_t)bb * Hd * Ls;
    const uint32_t* Wtile = g_WtF + (size_t)blockIdx.y * 65536;

    const uint32_t swb = (uint32_t)__cvta_generic_to_shared(&sW4[0][0]);
    const uint32_t syb = (uint32_t)__cvta_generic_to_shared(&sY[0][0][0]);

    int wf0 = tid, wf1 = tid + 256;
    int yk0 = wf0 >> 5, yc0 = (wf0 & 31) << 2;
    int yk1 = wf1 >> 5, yc1 = (wf1 & 31) << 2;

    float acc[2][2][4][4];
    #pragma unroll
    for (int a = 0; a < 2; ++a)
        #pragma unroll
        for (int m = 0; m < 2; ++m)
            #pragma unroll
            for (int n = 0; n < 4; ++n)
                #pragma unroll
                for (int q = 0; q < 4; ++q) acc[a][m][n][q] = 0.0f;

    #define LOAD_CHUNK(KC, BUF) do {                                              \
        int _k0 = (KC) * BK;                                                      \
        cp_async16(swb + ((BUF) * 512 + tid) * 16,                                \
                   Wtile + (KC) * 2048 + tid * 4);                                \
        cp_async16(swb + ((BUF) * 512 + tid + 256) * 16,                          \
                   Wtile + (KC) * 2048 + (tid + 256) * 4);                        \
        cp_async16(syb + (((BUF) * BK + yk0) * SYS + yc0) * 4,                    \
                   Yb + (size_t)(_k0 + yk0) * Ls + l0 + yc0);                     \
        cp_async16(syb + (((BUF) * BK + yk1) * SYS + yc1) * 4,                    \
                   Yb + (size_t)(_k0 + yk1) * Ls + l0 + yc1);                     \
    } while (0)

    LOAD_CHUNK(0, 0); cp_commit();
    LOAD_CHUNK(1, 1); cp_commit();

    const int NCH = Hd / BK;
    #pragma unroll 1
    for (int kc = 0; kc < NCH; ++kc) {
        if (kc < NCH - 1) cp_wait<1>(); else cp_wait<0>();
        __syncthreads();
        int buf = kc & 1;

        #pragma unroll
        for (int ks = 0; ks < 2; ++ks) {
            int kk = ks * 8 + t4;
            uint32_t B0[4], B1[4];
            #pragma unroll
            for (int ni = 0; ni < 4; ++ni) {
                int col = wn * 32 + ni * 8 + g;
                B0[ni] = sY[buf][kk][col];
                B1[ni] = sY[buf][kk + 4][col];
            }
            #pragma unroll
            for (int half = 0; half < 2; ++half) {
                #pragma unroll
                for (int mi = 0; mi < 2; ++mi) {
                    uint4 av = sW4[buf][(ks * 8 + half * 4 + wm * 2 + mi) * 32 + lane];
                    #pragma unroll
                    for (int ni = 0; ni < 4; ++ni)
                        mma_tf32(acc[half][mi][ni], av.x, av.y, av.z, av.w, B0[ni], B1[ni]);
                }
            }
        }
        __syncthreads();
        if (kc + 2 < NCH) { LOAD_CHUNK(kc + 2, buf); cp_commit(); }
    }
    #undef LOAD_CHUNK

    const float* Xb = X   + (size_t)bb * Hd * Ls;
    float*       Ob = out + (size_t)bb * Hd * Ls;

    #pragma unroll
    for (int mi = 0; mi < 2; ++mi) {
        int o = r0 + wm * 32 + mi * 16 + g;
        float ba0 = bias[o];
        float bB0 = bias[o + 512];
        float ba8 = bias[o + 8];
        float bB8 = bias[o + 520];
        #pragma unroll
        for (int ni = 0; ni < 4; ++ni) {
            int l = l0 + wn * 32 + ni * 8 + 2 * t4;
            const float* A = acc[0][mi][ni];
            const float* Bc = acc[1][mi][ni];

            float2 xv0 = *(const float2*)(Xb + (size_t)o * Ls + l);
            float2 xv8 = *(const float2*)(Xb + (size_t)(o + 8) * Ls + l);

            float av, bv, sg;
            float2 ov0, ov8;
            av = A[0] + ba0; bv = Bc[0] + bB0; sg = 1.0f / (1.0f + expf(-bv));
            ov0.x = xv0.x + av * sg;
            av = A[1] + ba0; bv = Bc[1] + bB0; sg = 1.0f / (1.0f + expf(-bv));
            ov0.y = xv0.y + av * sg;
            av = A[2] + ba8; bv = Bc[2] + bB8; sg = 1.0f / (1.0f + expf(-bv));
            ov8.x = xv8.x + av * sg;
            av = A[3] + ba8; bv = Bc[3] + bB8; sg = 1.0f / (1.0f + expf(-bv));
            ov8.y = xv8.y + av * sg;

            *(float2*)(Ob + (size_t)o * Ls + l) = ov0;
            *(float2*)(Ob + (size_t)(o + 8) * Ls + l) = ov8;
        }
    }
}

// ---------------------------------------------------------------------------
extern "C" void kernel_launch(void* const* d_in, const int* in_sizes, int n_in,
                              void* d_out, int out_size)
{
    const float* x      = (const float*)d_in[0];
    const float* alpha1 = (const float*)d_in[1];
    const float* log_dt = (const float*)d_in[2];
    const float* Ar     = (const float*)d_in[3];
    const float* Ai     = (const float*)d_in[4];
    const float* Cr     = (const float*)d_in[5];
    const float* Ci     = (const float*)d_in[6];
    const float* D      = (const float*)d_in[7];
    const float* alpha2 = (const float*)d_in[8];
    const float* W      = (const float*)d_in[9];
    const float* bconv  = (const float*)d_in[10];
    float* out = (float*)d_out;

    param_kernel<<<(Hd * Nm + 255) / 256, 256>>>(log_dt, Ar, Ai, Cr, Ci);
    param2_kernel<<<Hd, 256>>>(D);
    wconv_kernel<<<(2 * Hd * Hd + 255) / 256, 256>>>(W);

    scanA_kernel<<<Hd * 4, 256>>>(x, alpha1);      // 16384 warps
    scanB_kernel<<<(Hd * 128) / 256, 256>>>();     // 65536 threads
    scanC_kernel<<<Hd * 4, 256>>>(alpha2);         // 16384 warps

    dim3 grid(Ls / 128, Hd / 64, Bsz);
    gemm_glu_kernel<<<grid, 256>>>(bconv, x, out);
}

// round 10
// speedup vs baseline: 1.2233x; 1.0476x over previous
#include <cuda_runtime.h>
#include <math.h>
#include <stdint.h>

// Problem constants
#define Bsz 8
#define Hd  512
#define Ls  4096
#define Nm  32
#define CL  64             // chunk length
#define NC  (Ls / CL)      // 64 chunks

// Scratch (allocation-free rule: __device__ globals)
__device__ float    g_wr[Hd * Nm];
__device__ float    g_wi[Hd * Nm];
__device__ float    g_dtar[Hd * Nm];
__device__ float    g_dtai[Hd * Nm];

__device__ uint32_t g_Ktap[Hd * CL];        // Toeplitz taps, tf32 bits, D folded into tap 0
// Fragment tables, reg-contiguous per lane: idx = (frag*32 + lane) -> uint4 of 4 regs
__device__ uint4    g_PrF4[Hd * 512];       // P  = Re(w λ^{j+1}),  A-frag (M=64,K=32), 16 frags
__device__ uint4    g_PinF4[Hd * 512];      // -Im(w λ^{j+1})
__device__ uint4    g_LrF4[Hd * 512];       // Re(λ^{63-i}),        A-frag (M=32,K=64), 16 frags
__device__ uint4    g_LiF4[Hd * 512];       // Im(λ^{63-i})
__device__ float    g_l64r[Hd * Nm];        // Re(λ^64)
__device__ float    g_l64i[Hd * Nm];

__device__ float2   g_slocR2[(size_t)Hd * NC * 128];   // chunk summaries [h][c][n*4+b2]
__device__ float2   g_slocI2[(size_t)Hd * NC * 128];
__device__ uint2    g_carR2[(size_t)Hd * NC * 128];    // incoming carries, tf32 bits
__device__ uint2    g_carI2[(size_t)Hd * NC * 128];

__device__ uint32_t g_WtF[2 * Hd * Hd];                // W tf32 bits, A-frag order per 64-row tile
__device__ uint32_t g_y[(size_t)Bsz * Hd * Ls];        // post-snake2, tf32 bits (B,H,L)

__device__ __forceinline__ uint32_t f2tf32(float f) {
    uint32_t b;
    asm("cvt.rna.tf32.f32 %0, %1;" : "=r"(b) : "f"(f));
    return b;
}

// validated tf32 mma.sync fragment layout (R5-R8):
//  A: reg0=(g,t4) reg1=(g+8,t4) reg2=(g,t4+4) reg3=(g+8,t4+4)
//  B: reg0=B[k=t4][n=g] reg1=B[k=t4+4][n=g]
//  C: c0=(g,2t4) c1=(g,2t4+1) c2=(g+8,2t4) c3=(g+8,2t4+1)
__device__ __forceinline__ void mma_tf32(float* c,
                                         uint32_t a0, uint32_t a1, uint32_t a2, uint32_t a3,
                                         uint32_t b0, uint32_t b1)
{
    asm volatile(
        "mma.sync.aligned.m16n8k8.row.col.f32.tf32.tf32.f32 "
        "{%0,%1,%2,%3}, {%4,%5,%6,%7}, {%8,%9}, {%0,%1,%2,%3};\n"
        : "+f"(c[0]), "+f"(c[1]), "+f"(c[2]), "+f"(c[3])
        : "r"(a0), "r"(a1), "r"(a2), "r"(a3), "r"(b0), "r"(b1));
}

// ---------------------------------------------------------------------------
// Kernel 1: base discretization.  w = 2*C*(lambda-1)/A, dtA terms.
// ---------------------------------------------------------------------------
__global__ void param_kernel(const float* __restrict__ log_dt,
                             const float* __restrict__ Ar,
                             const float* __restrict__ Ai,
                             const float* __restrict__ Cr,
                             const float* __restrict__ Ci)
{
    int i = blockIdx.x * blockDim.x + threadIdx.x;
    if (i >= Hd * Nm) return;
    int h = i >> 5;
    float dt = expf(log_dt[h]);
    float ar = Ar[i], ai = Ai[i];
    float er = expf(dt * ar);
    float lr = er * cosf(dt * ai);
    float li = er * sinf(dt * ai);
    float nr = lr - 1.0f, ni = li;
    float inv = 1.0f / (ar * ar + ai * ai);
    float qr = (nr * ar + ni * ai) * inv;
    float qi = (ni * ar - nr * ai) * inv;
    float cr = Cr[i], ci = Ci[i];
    g_wr[i] = 2.0f * (cr * qr - ci * qi);
    g_wi[i] = 2.0f * (cr * qi + ci * qr);
    g_dtar[i] = dt * ar;
    g_dtai[i] = dt * ai;
}

// ---------------------------------------------------------------------------
// Kernel 1b: per-h frag tables (CL=64) + taps + lambda^64.  One block per h.
// ---------------------------------------------------------------------------
__global__ void param2_kernel(const float* __restrict__ Dp)
{
    int h = blockIdx.x;
    int tid = threadIdx.x;
    __shared__ float swr[32], swi[32], sar[32], sai[32];
    if (tid < 32) {
        swr[tid] = g_wr[h * 32 + tid];
        swi[tid] = g_wi[h * 32 + tid];
        sar[tid] = g_dtar[h * 32 + tid];
        sai[tid] = g_dtai[h * 32 + tid];
    }
    __syncthreads();

    // P: frag = hh*4+kcf (hh 0..3 rows of 16, kcf 0..3 k-chunks of 8)
    // q = frag*128 + lane*4 + reg
    for (int q = tid; q < 2048; q += 256) {
        int reg = q & 3, lane = (q >> 2) & 31, frag = q >> 7;
        int hh = frag >> 2, kcf = frag & 3;
        int g = lane >> 2, t4 = lane & 3;
        int row = hh * 16 + g + (reg & 1) * 8;        // j 0..63
        int col = kcf * 8 + t4 + (reg >> 1) * 4;      // n 0..31
        float p = (float)(row + 1);
        float e = expf(p * sar[col]);
        float ss, cc;
        sincosf(p * sai[col], &ss, &cc);
        float lpr = e * cc, lpi = e * ss;
        ((uint32_t*)g_PrF4)[h * 2048 + q]  = f2tf32(swr[col] * lpr - swi[col] * lpi);
        ((uint32_t*)g_PinF4)[h * 2048 + q] = f2tf32(-(swr[col] * lpi + swi[col] * lpr));
    }
    // Lambda: frag = mt*8+kc (mt 0..1 rows of 16 over n, kc 0..7 k-chunks over i)
    for (int q = tid; q < 2048; q += 256) {
        int reg = q & 3, lane = (q >> 2) & 31, frag = q >> 7;
        int mt = frag >> 3, kc = frag & 7;
        int g = lane >> 2, t4 = lane & 3;
        int row = mt * 16 + g + (reg & 1) * 8;        // n 0..31
        int col = kc * 8 + t4 + (reg >> 1) * 4;       // i 0..63
        float p = (float)(CL - 1 - col);
        float e = expf(p * sar[row]);
        float ss, cc;
        sincosf(p * sai[row], &ss, &cc);
        ((uint32_t*)g_LrF4)[h * 2048 + q] = f2tf32(e * cc);
        ((uint32_t*)g_LiF4)[h * 2048 + q] = f2tf32(e * ss);
    }
    // taps K[d] = sum_n Re(w λ^d), D folded into tap 0
    if (tid < CL) {
        int d = tid;
        float acc = 0.0f;
        for (int n = 0; n < 32; ++n) {
            float e = expf((float)d * sar[n]);
            float ss, cc;
            sincosf((float)d * sai[n], &ss, &cc);
            acc += swr[n] * (e * cc) - swi[n] * (e * ss);
        }
        if (d == 0) acc += Dp[h];
        g_Ktap[h * CL + d] = f2tf32(acc);
    }
    if (tid < 32) {
        float e = expf((float)CL * sar[tid]);
        float ss, cc;
        sincosf((float)CL * sai[tid], &ss, &cc);
        g_l64r[h * 32 + tid] = e * cc;
        g_l64i[h * 32 + tid] = e * ss;
    }
}

// ---------------------------------------------------------------------------
// Kernel 1c: W -> tf32 in A-fragment order (unchanged, validated R8).
// ---------------------------------------------------------------------------
__global__ void wconv_kernel(const float* __restrict__ W)
{
    int i = blockIdx.x * blockDim.x + threadIdx.x;
    if (i >= 2 * Hd * Hd) return;
    int tile = i >> 16;
    int q = i & 65535;
    int reg = q & 3, lane = (q >> 2) & 31, m8 = (q >> 7) & 7, ks = (q >> 10) & 1, kc = q >> 11;
    int g = lane >> 2, t4 = lane & 3;
    int half = m8 >> 2, wmmi = m8 & 3;
    int row = tile * 64 + wmmi * 16 + g + (reg & 1) * 8 + half * 512;
    int k = kc * 16 + ks * 8 + t4 + (reg >> 1) * 4;
    g_WtF[i] = f2tf32(W[row * Hd + k]);
}

// ---------------------------------------------------------------------------
// snake1 frag builder: stage x chunk via smem (coalesced), gather frag order.
// sX row stride 68 words -> conflict-free gather (4g+t4 spans all banks).
// ---------------------------------------------------------------------------
__device__ __forceinline__ void build_u_frags(
    const float* __restrict__ x, float* sXw,
    int h, int c, int lane, int g, int t4,
    float a1v, float inv1, uint32_t* uB)
{
    #pragma unroll
    for (int bb = 0; bb < 8; ++bb) {
        float2 v = *(const float2*)(x + ((size_t)bb * Hd + h) * Ls + c * CL + lane * 2);
        *(float2*)&sXw[bb * 68 + lane * 2] = v;
    }
    __syncwarp();
    #pragma unroll
    for (int kc = 0; kc < 8; ++kc)
        #pragma unroll
        for (int r = 0; r < 2; ++r) {
            int t = kc * 8 + t4 + 4 * r;
            float xv = sXw[g * 68 + t];
            float sn = __sinf(a1v * xv);
            float u  = fmaf(sn * sn, inv1, xv);
            uB[kc * 2 + r] = f2tf32(u);
        }
}

// ---------------------------------------------------------------------------
// Kernel A: per (h,c) warp: snake1, chunk summary Lam@U.  32768 warps.
// ---------------------------------------------------------------------------
__global__ __launch_bounds__(256)
void scanA_kernel(const float* __restrict__ x,
                  const float* __restrict__ alpha1)
{
    __shared__ float sX[8][8 * 68];

    const int tid  = threadIdx.x;
    const int wp   = tid >> 5;
    const int lane = tid & 31;
    const int g    = lane >> 2;
    const int t4   = lane & 3;
    const int h    = blockIdx.x >> 3;
    const int c    = ((blockIdx.x & 7) << 3) + wp;

    const float a1v  = alpha1[h];
    const float inv1 = 1.0f / (a1v + 1e-9f);

    uint32_t uB[16];
    build_u_frags(x, sX[wp], h, c, lane, g, t4, a1v, inv1, uB);

    // chunk summary: Lam(32x64) @ U(64x8)  (complex)
    const uint4* Lr = g_LrF4 + h * 512;
    const uint4* Li = g_LiF4 + h * 512;
    float AccR[2][4] = {}, AccI[2][4] = {};
    #pragma unroll
    for (int kc = 0; kc < 8; ++kc)
        #pragma unroll
        for (int mt = 0; mt < 2; ++mt) {
            uint4 ar = Lr[(mt * 8 + kc) * 32 + lane];
            uint4 ai = Li[(mt * 8 + kc) * 32 + lane];
            mma_tf32(AccR[mt], ar.x, ar.y, ar.z, ar.w, uB[kc * 2], uB[kc * 2 + 1]);
            mma_tf32(AccI[mt], ai.x, ai.y, ai.z, ai.w, uB[kc * 2], uB[kc * 2 + 1]);
        }

    // store chunk summary (C-frag layout)
    size_t sbase = (size_t)(h * NC + c) * 128;
    #pragma unroll
    for (int mt = 0; mt < 2; ++mt)
        #pragma unroll
        for (int rr = 0; rr < 2; ++rr) {
            int n = mt * 16 + rr * 8 + g;
            g_slocR2[sbase + n * 4 + t4] = make_float2(AccR[mt][rr * 2], AccR[mt][rr * 2 + 1]);
            g_slocI2[sbase + n * 4 + t4] = make_float2(AccI[mt][rr * 2], AccI[mt][rr * 2 + 1]);
        }
}

// ---------------------------------------------------------------------------
// Kernel B: exclusive scan of chunk carries (64-chunk chain, λ^64).
// ---------------------------------------------------------------------------
__global__ __launch_bounds__(256)
void scanB_kernel()
{
    int gid = blockIdx.x * 256 + threadIdx.x;
    int h   = gid >> 7;
    int idx = gid & 127;
    int n   = idx >> 2;

    float lr = g_l64r[h * 32 + n];
    float li = g_l64i[h * 32 + n];

    size_t base = (size_t)h * NC * 128 + idx;
    float cr0 = 0.f, ci0 = 0.f, cr1 = 0.f, ci1 = 0.f;

    #pragma unroll 1
    for (int c = 0; c < NC; ++c) {
        size_t k = base + (size_t)c * 128;
        g_carR2[k] = make_uint2(f2tf32(cr0), f2tf32(cr1));
        g_carI2[k] = make_uint2(f2tf32(ci0), f2tf32(ci1));
        float2 slr = g_slocR2[k];
        float2 sli = g_slocI2[k];
        float nr0 = fmaf(lr, cr0, fmaf(-li, ci0, slr.x));
        float ni0 = fmaf(lr, ci0, fmaf( li, cr0, sli.x));
        float nr1 = fmaf(lr, cr1, fmaf(-li, ci1, slr.y));
        float ni1 = fmaf(lr, ci1, fmaf( li, cr1, sli.y));
        cr0 = nr0; ci0 = ni0; cr1 = nr1; ci1 = ni1;
    }
}

// ---------------------------------------------------------------------------
// Kernel C: per (h,c) warp: recompute u, Y = T@U + Pr@S + Pin@S, snake2.
// 32768 warps.  20 Toeplitz + 32 carry mmas.
// ---------------------------------------------------------------------------
__global__ __launch_bounds__(256)
void scanC_kernel(const float* __restrict__ x,
                  const float* __restrict__ alpha1,
                  const float* __restrict__ alpha2)
{
    __shared__ float    sX[8][8 * 68];
    __shared__ uint32_t sKt[CL];

    const int tid  = threadIdx.x;
    const int wp   = tid >> 5;
    const int lane = tid & 31;
    const int g    = lane >> 2;
    const int t4   = lane & 3;
    const int h    = blockIdx.x >> 3;
    const int c    = ((blockIdx.x & 7) << 3) + wp;

    if (tid < CL) sKt[tid] = g_Ktap[h * CL + tid];
    __syncthreads();

    const float a1v  = alpha1[h];
    const float inv1 = 1.0f / (a1v + 1e-9f);

    uint32_t uB[16];
    build_u_frags(x, sX[wp], h, c, lane, g, t4, a1v, inv1, uB);

    // carry fragments (B-operand: k = mode n, n-dim = batch)
    const uint32_t* carR = (const uint32_t*)g_carR2 + (size_t)(h * NC + c) * 256;
    const uint32_t* carI = (const uint32_t*)g_carI2 + (size_t)(h * NC + c) * 256;
    uint32_t SrB[8], SiB[8];
    #pragma unroll
    for (int kc2 = 0; kc2 < 4; ++kc2)
        #pragma unroll
        for (int r = 0; r < 2; ++r) {
            int n = kc2 * 8 + t4 + 4 * r;
            SrB[kc2 * 2 + r] = carR[n * 8 + g];
            SiB[kc2 * 2 + r] = carI[n * 8 + g];
        }

    float yC[4][4] = {};

    // Toeplitz path (lower-triangular block skip): 20 mmas
    #pragma unroll
    for (int hh = 0; hh < 4; ++hh) {
        const int kmax = 2 * hh + 2;
        #pragma unroll
        for (int kc = 0; kc < 8; ++kc) {
            if (kc >= kmax) break;               // compile-time pruned
            int d0 = hh * 16 + g - (kc * 8 + t4);
            int d1 = d0 + 8, d2 = d0 - 4, d3 = d0 + 4;
            uint32_t a0 = (d0 >= 0) ? sKt[d0] : 0u;
            uint32_t a1 = (d1 >= 0) ? sKt[d1] : 0u;
            uint32_t a2 = (d2 >= 0) ? sKt[d2] : 0u;
            uint32_t a3 = (d3 >= 0) ? sKt[d3] : 0u;
            mma_tf32(yC[hh], a0, a1, a2, a3, uB[kc * 2], uB[kc * 2 + 1]);
        }
    }

    // carry path (frag LDG.128): 32 mmas
    const uint4* PrF  = g_PrF4  + h * 512;
    const uint4* PinF = g_PinF4 + h * 512;
    #pragma unroll
    for (int hh = 0; hh < 4; ++hh)
        #pragma unroll
        for (int kc2 = 0; kc2 < 4; ++kc2) {
            uint4 pa = PrF[(hh * 4 + kc2) * 32 + lane];
            uint4 pb = PinF[(hh * 4 + kc2) * 32 + lane];
            mma_tf32(yC[hh], pa.x, pa.y, pa.z, pa.w, SrB[kc2 * 2], SrB[kc2 * 2 + 1]);
            mma_tf32(yC[hh], pb.x, pb.y, pb.z, pb.w, SiB[kc2 * 2], SiB[kc2 * 2 + 1]);
        }

    // epilogue: snake2, store tf32 bits into (B,H,L) layout
    const float a2v  = alpha2[h];
    const float inv2 = 1.0f / (a2v + 1e-9f);
    #pragma unroll
    for (int hh = 0; hh < 4; ++hh)
        #pragma unroll
        for (int cc = 0; cc < 4; ++cc) {
            int j = hh * 16 + g + 8 * (cc >> 1);
            int b = 2 * t4 + (cc & 1);
            float yv = yC[hh][cc];
            float s2 = __sinf(a2v * yv);
            yv = fmaf(s2 * s2, inv2, yv);
            g_y[((size_t)b * Hd + h) * Ls + c * CL + j] = f2tf32(yv);
        }
}

// ---------------------------------------------------------------------------
// Kernel 3: fused 1x1 conv GEMM (tf32 mma.sync) + GLU + residual
// (byte-identical to validated R8 version).
// ---------------------------------------------------------------------------
#define BK 16
#define SYS (128 + 8)

__device__ __forceinline__ void cp_async16(uint32_t smem, const void* gmem) {
    asm volatile("cp.async.cg.shared.global [%0], [%1], 16;\n" :: "r"(smem), "l"(gmem));
}
__device__ __forceinline__ void cp_commit() {
    asm volatile("cp.async.commit_group;\n");
}
template <int N> __device__ __forceinline__ void cp_wait() {
    asm volatile("cp.async.wait_group %0;\n" :: "n"(N));
}

__global__ __launch_bounds__(256, 2)
void gemm_glu_kernel(const float* __restrict__ bias,
                     const float* __restrict__ X,
                     float* __restrict__ out)
{
    __shared__ uint4    sW4[2][512];          // frag-ordered W chunk (8KB per buf)
    __shared__ uint32_t sY[2][BK][SYS];

    const int tid = threadIdx.x;
    const int lane = tid & 31;
    const int wid = tid >> 5;
    const int wm = wid >> 2;
    const int wn = wid & 3;
    const int t4 = lane & 3;
    const int g  = lane >> 2;

    const int l0 = blockIdx.x * 128;
    const int r0 = blockIdx.y * 64;
    const int bb = blockIdx.z;

    const uint32_t* Yb = g_y + (size_t)bb * Hd * Ls;
    const uint32_t* Wtile = g_WtF + (size_t)blockIdx.y * 65536;

    const uint32_t swb = (uint32_t)__cvta_generic_to_shared(&sW4[0][0]);
    const uint32_t syb = (uint32_t)__cvta_generic_to_shared(&sY[0][0][0]);

    int wf0 = tid, wf1 = tid + 256;
    int yk0 = wf0 >> 5, yc0 = (wf0 & 31) << 2;
    int yk1 = wf1 >> 5, yc1 = (wf1 & 31) << 2;

    float acc[2][2][4][4];
    #pragma unroll
    for (int a = 0; a < 2; ++a)
        #pragma unroll
        for (int m = 0; m < 2; ++m)
            #pragma unroll
            for (int n = 0; n < 4; ++n)
                #pragma unroll
                for (int q = 0; q < 4; ++q) acc[a][m][n][q] = 0.0f;

    #define LOAD_CHUNK(KC, BUF) do {                                              \
        int _k0 = (KC) * BK;                                                      \
        cp_async16(swb + ((BUF) * 512 + tid) * 16,                                \
                   Wtile + (KC) * 2048 + tid * 4);                                \
        cp_async16(swb + ((BUF) * 512 + tid + 256) * 16,                          \
                   Wtile + (KC) * 2048 + (tid + 256) * 4);                        \
        cp_async16(syb + (((BUF) * BK + yk0) * SYS + yc0) * 4,                    \
                   Yb + (size_t)(_k0 + yk0) * Ls + l0 + yc0);                     \
        cp_async16(syb + (((BUF) * BK + yk1) * SYS + yc1) * 4,                    \
                   Yb + (size_t)(_k0 + yk1) * Ls + l0 + yc1);                     \
    } while (0)

    LOAD_CHUNK(0, 0); cp_commit();
    LOAD_CHUNK(1, 1); cp_commit();

    const int NCH = Hd / BK;
    #pragma unroll 1
    for (int kc = 0; kc < NCH; ++kc) {
        if (kc < NCH - 1) cp_wait<1>(); else cp_wait<0>();
        __syncthreads();
        int buf = kc & 1;

        #pragma unroll
        for (int ks = 0; ks < 2; ++ks) {
            int kk = ks * 8 + t4;
            uint32_t B0[4], B1[4];
            #pragma unroll
            for (int ni = 0; ni < 4; ++ni) {
                int col = wn * 32 + ni * 8 + g;
                B0[ni] = sY[buf][kk][col];
                B1[ni] = sY[buf][kk + 4][col];
            }
            #pragma unroll
            for (int half = 0; half < 2; ++half) {
                #pragma unroll
                for (int mi = 0; mi < 2; ++mi) {
                    uint4 av = sW4[buf][(ks * 8 + half * 4 + wm * 2 + mi) * 32 + lane];
                    #pragma unroll
                    for (int ni = 0; ni < 4; ++ni)
                        mma_tf32(acc[half][mi][ni], av.x, av.y, av.z, av.w, B0[ni], B1[ni]);
                }
            }
        }
        __syncthreads();
        if (kc + 2 < NCH) { LOAD_CHUNK(kc + 2, buf); cp_commit(); }
    }
    #undef LOAD_CHUNK

    const float* Xb = X   + (size_t)bb * Hd * Ls;
    float*       Ob = out + (size_t)bb * Hd * Ls;

    #pragma unroll
    for (int mi = 0; mi < 2; ++mi) {
        int o = r0 + wm * 32 + mi * 16 + g;
        float ba0 = bias[o];
        float bB0 = bias[o + 512];
        float ba8 = bias[o + 8];
        float bB8 = bias[o + 520];
        #pragma unroll
        for (int ni = 0; ni < 4; ++ni) {
            int l = l0 + wn * 32 + ni * 8 + 2 * t4;
            const float* A = acc[0][mi][ni];
            const float* Bc = acc[1][mi][ni];

            float2 xv0 = *(const float2*)(Xb + (size_t)o * Ls + l);
            float2 xv8 = *(const float2*)(Xb + (size_t)(o + 8) * Ls + l);

            float av, bv, sg;
            float2 ov0, ov8;
            av = A[0] + ba0; bv = Bc[0] + bB0; sg = 1.0f / (1.0f + expf(-bv));
            ov0.x = xv0.x + av * sg;
            av = A[1] + ba0; bv = Bc[1] + bB0; sg = 1.0f / (1.0f + expf(-bv));
            ov0.y = xv0.y + av * sg;
            av = A[2] + ba8; bv = Bc[2] + bB8; sg = 1.0f / (1.0f + expf(-bv));
            ov8.x = xv8.x + av * sg;
            av = A[3] + ba8; bv = Bc[3] + bB8; sg = 1.0f / (1.0f + expf(-bv));
            ov8.y = xv8.y + av * sg;

            *(float2*)(Ob + (size_t)o * Ls + l) = ov0;
            *(float2*)(Ob + (size_t)(o + 8) * Ls + l) = ov8;
        }
    }
}

// ---------------------------------------------------------------------------
extern "C" void kernel_launch(void* const* d_in, const int* in_sizes, int n_in,
                              void* d_out, int out_size)
{
    const float* x      = (const float*)d_in[0];
    const float* alpha1 = (const float*)d_in[1];
    const float* log_dt = (const float*)d_in[2];
    const float* Ar     = (const float*)d_in[3];
    const float* Ai     = (const float*)d_in[4];
    const float* Cr     = (const float*)d_in[5];
    const float* Ci     = (const float*)d_in[6];
    const float* D      = (const float*)d_in[7];
    const float* alpha2 = (const float*)d_in[8];
    const float* W      = (const float*)d_in[9];
    const float* bconv  = (const float*)d_in[10];
    float* out = (float*)d_out;

    param_kernel<<<(Hd * Nm + 255) / 256, 256>>>(log_dt, Ar, Ai, Cr, Ci);
    param2_kernel<<<Hd, 256>>>(D);
    wconv_kernel<<<(2 * Hd * Hd + 255) / 256, 256>>>(W);

    scanA_kernel<<<Hd * 8, 256>>>(x, alpha1);        // 32768 warps
    scanB_kernel<<<(Hd * 128) / 256, 256>>>();       // 65536 threads
    scanC_kernel<<<Hd * 8, 256>>>(x, alpha1, alpha2);// 32768 warps

    dim3 grid(Ls / 128, Hd / 64, Bsz);
    gemm_glu_kernel<<<grid, 256>>>(bconv, x, out);
}

// round 11
// speedup vs baseline: 1.3060x; 1.0677x over previous
#include <cuda_runtime.h>
#include <math.h>
#include <stdint.h>

// Problem constants
#define Bsz 8
#define Hd  512
#define Ls  4096
#define Nm  32
#define CL  64             // chunk length
#define NC  (Ls / CL)      // 64 chunks

// Scratch (allocation-free rule: __device__ globals)
__device__ float    g_wr[Hd * Nm];
__device__ float    g_wi[Hd * Nm];
__device__ float    g_dtar[Hd * Nm];
__device__ float    g_dtai[Hd * Nm];

__device__ uint32_t g_Ktap[Hd * CL];        // Toeplitz taps, tf32 bits, D folded into tap 0
// Fragment tables, reg-contiguous per lane: idx = (frag*32 + lane) -> uint4 of 4 regs
__device__ uint4    g_PrF4[Hd * 512];       // P  = Re(w λ^{j+1}),  A-frag (M=64,K=32), 16 frags
__device__ uint4    g_PinF4[Hd * 512];      // -Im(w λ^{j+1})
__device__ uint4    g_LrF4[Hd * 512];       // Re(λ^{63-i}),        A-frag (M=32,K=64), 16 frags
__device__ uint4    g_LiF4[Hd * 512];       // Im(λ^{63-i})
__device__ float    g_l64r[Hd * Nm];        // Re(λ^64)
__device__ float    g_l64i[Hd * Nm];

__device__ float2   g_slocR2[(size_t)Hd * NC * 128];   // chunk summaries [h][c][n*4+b2]
__device__ float2   g_slocI2[(size_t)Hd * NC * 128];
__device__ uint2    g_carR2[(size_t)Hd * NC * 128];    // incoming carries, tf32 bits
__device__ uint2    g_carI2[(size_t)Hd * NC * 128];

__device__ uint32_t g_WtF[2 * Hd * Hd];                // W tf32 bits, A-frag order per 64-row tile
__device__ uint32_t g_y[(size_t)Bsz * Hd * Ls];        // post-snake2, tf32 bits (B,H,L)

__device__ __forceinline__ uint32_t f2tf32(float f) {
    uint32_t b;
    asm("cvt.rna.tf32.f32 %0, %1;" : "=r"(b) : "f"(f));
    return b;
}

// validated tf32 mma.sync fragment layout (R5-R10):
//  A: reg0=(g,t4) reg1=(g+8,t4) reg2=(g,t4+4) reg3=(g+8,t4+4)
//  B: reg0=B[k=t4][n=g] reg1=B[k=t4+4][n=g]
//  C: c0=(g,2t4) c1=(g,2t4+1) c2=(g+8,2t4) c3=(g+8,2t4+1)
__device__ __forceinline__ void mma_tf32(float* c,
                                         uint32_t a0, uint32_t a1, uint32_t a2, uint32_t a3,
                                         uint32_t b0, uint32_t b1)
{
    asm volatile(
        "mma.sync.aligned.m16n8k8.row.col.f32.tf32.tf32.f32 "
        "{%0,%1,%2,%3}, {%4,%5,%6,%7}, {%8,%9}, {%0,%1,%2,%3};\n"
        : "+f"(c[0]), "+f"(c[1]), "+f"(c[2]), "+f"(c[3])
        : "r"(a0), "r"(a1), "r"(a2), "r"(a3), "r"(b0), "r"(b1));
}

// ---------------------------------------------------------------------------
// Kernel 1: base discretization.  w = 2*C*(lambda-1)/A, dtA terms.
// ---------------------------------------------------------------------------
__global__ void param_kernel(const float* __restrict__ log_dt,
                             const float* __restrict__ Ar,
                             const float* __restrict__ Ai,
                             const float* __restrict__ Cr,
                             const float* __restrict__ Ci)
{
    int i = blockIdx.x * blockDim.x + threadIdx.x;
    if (i >= Hd * Nm) return;
    int h = i >> 5;
    float dt = expf(log_dt[h]);
    float ar = Ar[i], ai = Ai[i];
    float er = expf(dt * ar);
    float lr = er * cosf(dt * ai);
    float li = er * sinf(dt * ai);
    float nr = lr - 1.0f, ni = li;
    float inv = 1.0f / (ar * ar + ai * ai);
    float qr = (nr * ar + ni * ai) * inv;
    float qi = (ni * ar - nr * ai) * inv;
    float cr = Cr[i], ci = Ci[i];
    g_wr[i] = 2.0f * (cr * qr - ci * qi);
    g_wi[i] = 2.0f * (cr * qi + ci * qr);
    g_dtar[i] = dt * ar;
    g_dtai[i] = dt * ai;
}

// ---------------------------------------------------------------------------
// Kernel 1b: per-h frag tables (CL=64) + taps + lambda^64.  One block per h.
// ---------------------------------------------------------------------------
__global__ void param2_kernel(const float* __restrict__ Dp)
{
    int h = blockIdx.x;
    int tid = threadIdx.x;
    __shared__ float swr[32], swi[32], sar[32], sai[32];
    if (tid < 32) {
        swr[tid] = g_wr[h * 32 + tid];
        swi[tid] = g_wi[h * 32 + tid];
        sar[tid] = g_dtar[h * 32 + tid];
        sai[tid] = g_dtai[h * 32 + tid];
    }
    __syncthreads();

    // P: frag = hh*4+kcf;  q = frag*128 + lane*4 + reg
    for (int q = tid; q < 2048; q += 256) {
        int reg = q & 3, lane = (q >> 2) & 31, frag = q >> 7;
        int hh = frag >> 2, kcf = frag & 3;
        int g = lane >> 2, t4 = lane & 3;
        int row = hh * 16 + g + (reg & 1) * 8;        // j 0..63
        int col = kcf * 8 + t4 + (reg >> 1) * 4;      // n 0..31
        float p = (float)(row + 1);
        float e = expf(p * sar[col]);
        float ss, cc;
        sincosf(p * sai[col], &ss, &cc);
        float lpr = e * cc, lpi = e * ss;
        ((uint32_t*)g_PrF4)[h * 2048 + q]  = f2tf32(swr[col] * lpr - swi[col] * lpi);
        ((uint32_t*)g_PinF4)[h * 2048 + q] = f2tf32(-(swr[col] * lpi + swi[col] * lpr));
    }
    // Lambda: frag = mt*8+kc
    for (int q = tid; q < 2048; q += 256) {
        int reg = q & 3, lane = (q >> 2) & 31, frag = q >> 7;
        int mt = frag >> 3, kc = frag & 7;
        int g = lane >> 2, t4 = lane & 3;
        int row = mt * 16 + g + (reg & 1) * 8;        // n 0..31
        int col = kc * 8 + t4 + (reg >> 1) * 4;       // i 0..63
        float p = (float)(CL - 1 - col);
        float e = expf(p * sar[row]);
        float ss, cc;
        sincosf(p * sai[row], &ss, &cc);
        ((uint32_t*)g_LrF4)[h * 2048 + q] = f2tf32(e * cc);
        ((uint32_t*)g_LiF4)[h * 2048 + q] = f2tf32(e * ss);
    }
    // taps K[d] = sum_n Re(w λ^d), D folded into tap 0
    if (tid < CL) {
        int d = tid;
        float acc = 0.0f;
        for (int n = 0; n < 32; ++n) {
            float e = expf((float)d * sar[n]);
            float ss, cc;
            sincosf((float)d * sai[n], &ss, &cc);
            acc += swr[n] * (e * cc) - swi[n] * (e * ss);
        }
        if (d == 0) acc += Dp[h];
        g_Ktap[h * CL + d] = f2tf32(acc);
    }
    if (tid < 32) {
        float e = expf((float)CL * sar[tid]);
        float ss, cc;
        sincosf((float)CL * sai[tid], &ss, &cc);
        g_l64r[h * 32 + tid] = e * cc;
        g_l64i[h * 32 + tid] = e * ss;
    }
}

// ---------------------------------------------------------------------------
// Kernel 1c: W -> tf32 in A-fragment order (unchanged, validated R8).
// ---------------------------------------------------------------------------
__global__ void wconv_kernel(const float* __restrict__ W)
{
    int i = blockIdx.x * blockDim.x + threadIdx.x;
    if (i >= 2 * Hd * Hd) return;
    int tile = i >> 16;
    int q = i & 65535;
    int reg = q & 3, lane = (q >> 2) & 31, m8 = (q >> 7) & 7, ks = (q >> 10) & 1, kc = q >> 11;
    int g = lane >> 2, t4 = lane & 3;
    int half = m8 >> 2, wmmi = m8 & 3;
    int row = tile * 64 + wmmi * 16 + g + (reg & 1) * 8 + half * 512;
    int k = kc * 16 + ks * 8 + t4 + (reg >> 1) * 4;
    g_WtF[i] = f2tf32(W[row * Hd + k]);
}

// ---------------------------------------------------------------------------
// snake1 frag builder: stage x chunk via smem (coalesced), gather frag order.
// ---------------------------------------------------------------------------
__device__ __forceinline__ void build_u_frags(
    const float* __restrict__ x, float* sXw,
    int h, int c, int lane, int g, int t4,
    float a1v, float inv1, uint32_t* uB)
{
    #pragma unroll
    for (int bb = 0; bb < 8; ++bb) {
        float2 v = *(const float2*)(x + ((size_t)bb * Hd + h) * Ls + c * CL + lane * 2);
        *(float2*)&sXw[bb * 68 + lane * 2] = v;
    }
    __syncwarp();
    #pragma unroll
    for (int kc = 0; kc < 8; ++kc)
        #pragma unroll
        for (int r = 0; r < 2; ++r) {
            int t = kc * 8 + t4 + 4 * r;
            float xv = sXw[g * 68 + t];
            float sn = __sinf(a1v * xv);
            float u  = fmaf(sn * sn, inv1, xv);
            uB[kc * 2 + r] = f2tf32(u);
        }
}

// ---------------------------------------------------------------------------
// Kernel A: per (h,c) warp: snake1, chunk summary Lam@U.  32768 warps.
// Lambda tables staged in smem once per block (8 warps share h).
// ---------------------------------------------------------------------------
__global__ __launch_bounds__(256)
void scanA_kernel(const float* __restrict__ x,
                  const float* __restrict__ alpha1)
{
    __shared__ uint4 sLr[512];
    __shared__ uint4 sLi[512];
    __shared__ float sX[8][8 * 68];

    const int tid  = threadIdx.x;
    const int wp   = tid >> 5;
    const int lane = tid & 31;
    const int g    = lane >> 2;
    const int t4   = lane & 3;
    const int h    = blockIdx.x >> 3;
    const int c    = ((blockIdx.x & 7) << 3) + wp;

    // cooperative table stage: 16KB, coalesced, L2-hot
    #pragma unroll
    for (int i = tid; i < 512; i += 256) {
        sLr[i] = g_LrF4[h * 512 + i];
        sLi[i] = g_LiF4[h * 512 + i];
    }
    __syncthreads();

    const float a1v  = alpha1[h];
    const float inv1 = 1.0f / (a1v + 1e-9f);

    uint32_t uB[16];
    build_u_frags(x, sX[wp], h, c, lane, g, t4, a1v, inv1, uB);

    // chunk summary: Lam(32x64) @ U(64x8)  (complex), frags via LDS.128
    float AccR[2][4] = {}, AccI[2][4] = {};
    #pragma unroll
    for (int kc = 0; kc < 8; ++kc)
        #pragma unroll
        for (int mt = 0; mt < 2; ++mt) {
            uint4 ar = sLr[(mt * 8 + kc) * 32 + lane];
            uint4 ai = sLi[(mt * 8 + kc) * 32 + lane];
            mma_tf32(AccR[mt], ar.x, ar.y, ar.z, ar.w, uB[kc * 2], uB[kc * 2 + 1]);
            mma_tf32(AccI[mt], ai.x, ai.y, ai.z, ai.w, uB[kc * 2], uB[kc * 2 + 1]);
        }

    // store chunk summary (C-frag layout)
    size_t sbase = (size_t)(h * NC + c) * 128;
    #pragma unroll
    for (int mt = 0; mt < 2; ++mt)
        #pragma unroll
        for (int rr = 0; rr < 2; ++rr) {
            int n = mt * 16 + rr * 8 + g;
            g_slocR2[sbase + n * 4 + t4] = make_float2(AccR[mt][rr * 2], AccR[mt][rr * 2 + 1]);
            g_slocI2[sbase + n * 4 + t4] = make_float2(AccI[mt][rr * 2], AccI[mt][rr * 2 + 1]);
        }
}

// ---------------------------------------------------------------------------
// Kernel B: exclusive scan of chunk carries (64-chunk chain, λ^64).
// ---------------------------------------------------------------------------
__global__ __launch_bounds__(256)
void scanB_kernel()
{
    int gid = blockIdx.x * 256 + threadIdx.x;
    int h   = gid >> 7;
    int idx = gid & 127;
    int n   = idx >> 2;

    float lr = g_l64r[h * 32 + n];
    float li = g_l64i[h * 32 + n];

    size_t base = (size_t)h * NC * 128 + idx;
    float cr0 = 0.f, ci0 = 0.f, cr1 = 0.f, ci1 = 0.f;

    #pragma unroll 1
    for (int c = 0; c < NC; ++c) {
        size_t k = base + (size_t)c * 128;
        g_carR2[k] = make_uint2(f2tf32(cr0), f2tf32(cr1));
        g_carI2[k] = make_uint2(f2tf32(ci0), f2tf32(ci1));
        float2 slr = g_slocR2[k];
        float2 sli = g_slocI2[k];
        float nr0 = fmaf(lr, cr0, fmaf(-li, ci0, slr.x));
        float ni0 = fmaf(lr, ci0, fmaf( li, cr0, sli.x));
        float nr1 = fmaf(lr, cr1, fmaf(-li, ci1, slr.y));
        float ni1 = fmaf(lr, ci1, fmaf( li, cr1, sli.y));
        cr0 = nr0; ci0 = ni0; cr1 = nr1; ci1 = ni1;
    }
}

// ---------------------------------------------------------------------------
// Kernel C: per (h,c) warp: recompute u, Y = T@U + Pr@S + Pin@S, snake2.
// P tables staged in smem once per block.  32768 warps.
// ---------------------------------------------------------------------------
__global__ __launch_bounds__(256)
void scanC_kernel(const float* __restrict__ x,
                  const float* __restrict__ alpha1,
                  const float* __restrict__ alpha2)
{
    __shared__ uint4    sPr[512];
    __shared__ uint4    sPin[512];
    __shared__ float    sX[8][8 * 68];
    __shared__ uint32_t sKt[CL];

    const int tid  = threadIdx.x;
    const int wp   = tid >> 5;
    const int lane = tid & 31;
    const int g    = lane >> 2;
    const int t4   = lane & 3;
    const int h    = blockIdx.x >> 3;
    const int c    = ((blockIdx.x & 7) << 3) + wp;

    #pragma unroll
    for (int i = tid; i < 512; i += 256) {
        sPr[i]  = g_PrF4[h * 512 + i];
        sPin[i] = g_PinF4[h * 512 + i];
    }
    if (tid < CL) sKt[tid] = g_Ktap[h * CL + tid];
    __syncthreads();

    const float a1v  = alpha1[h];
    const float inv1 = 1.0f / (a1v + 1e-9f);

    uint32_t uB[16];
    build_u_frags(x, sX[wp], h, c, lane, g, t4, a1v, inv1, uB);

    // carry fragments (B-operand: k = mode n, n-dim = batch)
    const uint32_t* carR = (const uint32_t*)g_carR2 + (size_t)(h * NC + c) * 256;
    const uint32_t* carI = (const uint32_t*)g_carI2 + (size_t)(h * NC + c) * 256;
    uint32_t SrB[8], SiB[8];
    #pragma unroll
    for (int kc2 = 0; kc2 < 4; ++kc2)
        #pragma unroll
        for (int r = 0; r < 2; ++r) {
            int n = kc2 * 8 + t4 + 4 * r;
            SrB[kc2 * 2 + r] = carR[n * 8 + g];
            SiB[kc2 * 2 + r] = carI[n * 8 + g];
        }

    float yC[4][4] = {};

    // Toeplitz path (lower-triangular block skip): 20 mmas
    #pragma unroll
    for (int hh = 0; hh < 4; ++hh) {
        const int kmax = 2 * hh + 2;
        #pragma unroll
        for (int kc = 0; kc < 8; ++kc) {
            if (kc >= kmax) break;               // compile-time pruned
            int d0 = hh * 16 + g - (kc * 8 + t4);
            int d1 = d0 + 8, d2 = d0 - 4, d3 = d0 + 4;
            uint32_t a0 = (d0 >= 0) ? sKt[d0] : 0u;
            uint32_t a1 = (d1 >= 0) ? sKt[d1] : 0u;
            uint32_t a2 = (d2 >= 0) ? sKt[d2] : 0u;
            uint32_t a3 = (d3 >= 0) ? sKt[d3] : 0u;
            mma_tf32(yC[hh], a0, a1, a2, a3, uB[kc * 2], uB[kc * 2 + 1]);
        }
    }

    // carry path (frags via LDS.128): 32 mmas
    #pragma unroll
    for (int hh = 0; hh < 4; ++hh)
        #pragma unroll
        for (int kc2 = 0; kc2 < 4; ++kc2) {
            uint4 pa = sPr[(hh * 4 + kc2) * 32 + lane];
            uint4 pb = sPin[(hh * 4 + kc2) * 32 + lane];
            mma_tf32(yC[hh], pa.x, pa.y, pa.z, pa.w, SrB[kc2 * 2], SrB[kc2 * 2 + 1]);
            mma_tf32(yC[hh], pb.x, pb.y, pb.z, pb.w, SiB[kc2 * 2], SiB[kc2 * 2 + 1]);
        }

    // epilogue: snake2, store tf32 bits into (B,H,L) layout
    const float a2v  = alpha2[h];
    const float inv2 = 1.0f / (a2v + 1e-9f);
    #pragma unroll
    for (int hh = 0; hh < 4; ++hh)
        #pragma unroll
        for (int cc = 0; cc < 4; ++cc) {
            int j = hh * 16 + g + 8 * (cc >> 1);
            int b = 2 * t4 + (cc & 1);
            float yv = yC[hh][cc];
            float s2 = __sinf(a2v * yv);
            yv = fmaf(s2 * s2, inv2, yv);
            g_y[((size_t)b * Hd + h) * Ls + c * CL + j] = f2tf32(yv);
        }
}

// ---------------------------------------------------------------------------
// Kernel 3: fused 1x1 conv GEMM (tf32 mma.sync) + GLU + residual
// (byte-identical to validated R8/R10 version).
// ---------------------------------------------------------------------------
#define BK 16
#define SYS (128 + 8)

__device__ __forceinline__ void cp_async16(uint32_t smem, const void* gmem) {
    asm volatile("cp.async.cg.shared.global [%0], [%1], 16;\n" :: "r"(smem), "l"(gmem));
}
__device__ __forceinline__ void cp_commit() {
    asm volatile("cp.async.commit_group;\n");
}
template <int N> __device__ __forceinline__ void cp_wait() {
    asm volatile("cp.async.wait_group %0;\n" :: "n"(N));
}

__global__ __launch_bounds__(256, 2)
void gemm_glu_kernel(const float* __restrict__ bias,
                     const float* __restrict__ X,
                     float* __restrict__ out)
{
    __shared__ uint4    sW4[2][512];          // frag-ordered W chunk (8KB per buf)
    __shared__ uint32_t sY[2][BK][SYS];

    const int tid = threadIdx.x;
    const int lane = tid & 31;
    const int wid = tid >> 5;
    const int wm = wid >> 2;
    const int wn = wid & 3;
    const int t4 = lane & 3;
    const int g  = lane >> 2;

    const int l0 = blockIdx.x * 128;
    const int r0 = blockIdx.y * 64;
    const int bb = blockIdx.z;

    const uint32_t* Yb = g_y + (size_t)bb * Hd * Ls;
    const uint32_t* Wtile = g_WtF + (size_t)blockIdx.y * 65536;

    const uint32_t swb = (uint32_t)__cvta_generic_to_shared(&sW4[0][0]);
    const uint32_t syb = (uint32_t)__cvta_generic_to_shared(&sY[0][0][0]);

    int wf0 = tid, wf1 = tid + 256;
    int yk0 = wf0 >> 5, yc0 = (wf0 & 31) << 2;
    int yk1 = wf1 >> 5, yc1 = (wf1 & 31) << 2;

    float acc[2][2][4][4];
    #pragma unroll
    for (int a = 0; a < 2; ++a)
        #pragma unroll
        for (int m = 0; m < 2; ++m)
            #pragma unroll
            for (int n = 0; n < 4; ++n)
                #pragma unroll
                for (int q = 0; q < 4; ++q) acc[a][m][n][q] = 0.0f;

    #define LOAD_CHUNK(KC, BUF) do {                                              \
        int _k0 = (KC) * BK;                                                      \
        cp_async16(swb + ((BUF) * 512 + tid) * 16,                                \
                   Wtile + (KC) * 2048 + tid * 4);                                \
        cp_async16(swb + ((BUF) * 512 + tid + 256) * 16,                          \
                   Wtile + (KC) * 2048 + (tid + 256) * 4);                        \
        cp_async16(syb + (((BUF) * BK + yk0) * SYS + yc0) * 4,                    \
                   Yb + (size_t)(_k0 + yk0) * Ls + l0 + yc0);                     \
        cp_async16(syb + (((BUF) * BK + yk1) * SYS + yc1) * 4,                    \
                   Yb + (size_t)(_k0 + yk1) * Ls + l0 + yc1);                     \
    } while (0)

    LOAD_CHUNK(0, 0); cp_commit();
    LOAD_CHUNK(1, 1); cp_commit();

    const int NCH = Hd / BK;
    #pragma unroll 1
    for (int kc = 0; kc < NCH; ++kc) {
        if (kc < NCH - 1) cp_wait<1>(); else cp_wait<0>();
        __syncthreads();
        int buf = kc & 1;

        #pragma unroll
        for (int ks = 0; ks < 2; ++ks) {
            int kk = ks * 8 + t4;
            uint32_t B0[4], B1[4];
            #pragma unroll
            for (int ni = 0; ni < 4; ++ni) {
                int col = wn * 32 + ni * 8 + g;
                B0[ni] = sY[buf][kk][col];
                B1[ni] = sY[buf][kk + 4][col];
            }
            #pragma unroll
            for (int half = 0; half < 2; ++half) {
                #pragma unroll
                for (int mi = 0; mi < 2; ++mi) {
                    uint4 av = sW4[buf][(ks * 8 + half * 4 + wm * 2 + mi) * 32 + lane];
                    #pragma unroll
                    for (int ni = 0; ni < 4; ++ni)
                        mma_tf32(acc[half][mi][ni], av.x, av.y, av.z, av.w, B0[ni], B1[ni]);
                }
            }
        }
        __syncthreads();
        if (kc + 2 < NCH) { LOAD_CHUNK(kc + 2, buf); cp_commit(); }
    }
    #undef LOAD_CHUNK

    const float* Xb = X   + (size_t)bb * Hd * Ls;
    float*       Ob = out + (size_t)bb * Hd * Ls;

    #pragma unroll
    for (int mi = 0; mi < 2; ++mi) {
        int o = r0 + wm * 32 + mi * 16 + g;
        float ba0 = bias[o];
        float bB0 = bias[o + 512];
        float ba8 = bias[o + 8];
        float bB8 = bias[o + 520];
        #pragma unroll
        for (int ni = 0; ni < 4; ++ni) {
            int l = l0 + wn * 32 + ni * 8 + 2 * t4;
            const float* A = acc[0][mi][ni];
            const float* Bc = acc[1][mi][ni];

            float2 xv0 = *(const float2*)(Xb + (size_t)o * Ls + l);
            float2 xv8 = *(const float2*)(Xb + (size_t)(o + 8) * Ls + l);

            float av, bv, sg;
            float2 ov0, ov8;
            av = A[0] + ba0; bv = Bc[0] + bB0; sg = 1.0f / (1.0f + expf(-bv));
            ov0.x = xv0.x + av * sg;
            av = A[1] + ba0; bv = Bc[1] + bB0; sg = 1.0f / (1.0f + expf(-bv));
            ov0.y = xv0.y + av * sg;
            av = A[2] + ba8; bv = Bc[2] + bB8; sg = 1.0f / (1.0f + expf(-bv));
            ov8.x = xv8.x + av * sg;
            av = A[3] + ba8; bv = Bc[3] + bB8; sg = 1.0f / (1.0f + expf(-bv));
            ov8.y = xv8.y + av * sg;

            *(float2*)(Ob + (size_t)o * Ls + l) = ov0;
            *(float2*)(Ob + (size_t)(o + 8) * Ls + l) = ov8;
        }
    }
}

// ---------------------------------------------------------------------------
extern "C" void kernel_launch(void* const* d_in, const int* in_sizes, int n_in,
                              void* d_out, int out_size)
{
    const float* x      = (const float*)d_in[0];
    const float* alpha1 = (const float*)d_in[1];
    const float* log_dt = (const float*)d_in[2];
    const float* Ar     = (const float*)d_in[3];
    const float* Ai     = (const float*)d_in[4];
    const float* Cr     = (const float*)d_in[5];
    const float* Ci     = (const float*)d_in[6];
    const float* D      = (const float*)d_in[7];
    const float* alpha2 = (const float*)d_in[8];
    const float* W      = (const float*)d_in[9];
    const float* bconv  = (const float*)d_in[10];
    float* out = (float*)d_out;

    param_kernel<<<(Hd * Nm + 255) / 256, 256>>>(log_dt, Ar, Ai, Cr, Ci);
    param2_kernel<<<Hd, 256>>>(D);
    wconv_kernel<<<(2 * Hd * Hd + 255) / 256, 256>>>(W);

    scanA_kernel<<<Hd * 8, 256>>>(x, alpha1);        // 32768 warps
    scanB_kernel<<<(Hd * 128) / 256, 256>>>();       // 65536 threads
    scanC_kernel<<<Hd * 8, 256>>>(x, alpha1, alpha2);// 32768 warps

    dim3 grid(Ls / 128, Hd / 64, Bsz);
    gemm_glu_kernel<<<grid, 256>>>(bconv, x, out);
}

// round 12
// speedup vs baseline: 1.3521x; 1.0353x over previous
#include <cuda_runtime.h>
#include <math.h>
#include <stdint.h>

// Problem constants
#define Bsz 8
#define Hd  512
#define Ls  4096
#define Nm  32
#define CL  64             // chunk length
#define NC  (Ls / CL)      // 64 chunks

// Scratch (allocation-free rule: __device__ globals)
__device__ float    g_wr[Hd * Nm];
__device__ float    g_wi[Hd * Nm];
__device__ float    g_dtar[Hd * Nm];
__device__ float    g_dtai[Hd * Nm];

__device__ uint32_t g_Ktap[Hd * CL];        // Toeplitz taps, tf32 bits, D folded into tap 0
// Fragment tables, reg-contiguous per lane: idx = (frag*32 + lane) -> uint4 of 4 regs
__device__ uint4    g_PrF4[Hd * 512];       // P  = Re(w λ^{j+1}),  A-frag (M=64,K=32), 16 frags
__device__ uint4    g_PinF4[Hd * 512];      // -Im(w λ^{j+1})
__device__ uint4    g_LrF4[Hd * 512];       // Re(λ^{63-i}),        A-frag (M=32,K=64), 16 frags
__device__ uint4    g_LiF4[Hd * 512];       // Im(λ^{63-i})
__device__ float    g_l64r[Hd * Nm];        // Re(λ^64)
__device__ float    g_l64i[Hd * Nm];

__device__ float2   g_slocR2[(size_t)Hd * NC * 128];   // chunk summaries [h][c][n*4+b2]
__device__ float2   g_slocI2[(size_t)Hd * NC * 128];
__device__ uint2    g_carR2[(size_t)Hd * NC * 128];    // incoming carries, tf32 bits
__device__ uint2    g_carI2[(size_t)Hd * NC * 128];

__device__ uint32_t g_WtF[2 * Hd * Hd];                // W tf32 bits, A-frag order per 64-row tile
__device__ uint32_t g_y[(size_t)Bsz * Hd * Ls];        // post-snake2, tf32 bits (B,H,L)

__device__ __forceinline__ uint32_t f2tf32(float f) {
    uint32_t b;
    asm("cvt.rna.tf32.f32 %0, %1;" : "=r"(b) : "f"(f));
    return b;
}

// validated tf32 mma.sync fragment layout (R5-R11):
//  A: reg0=(g,t4) reg1=(g+8,t4) reg2=(g,t4+4) reg3=(g+8,t4+4)
//  B: reg0=B[k=t4][n=g] reg1=B[k=t4+4][n=g]
//  C: c0=(g,2t4) c1=(g,2t4+1) c2=(g+8,2t4) c3=(g+8,2t4+1)
__device__ __forceinline__ void mma_tf32(float* c,
                                         uint32_t a0, uint32_t a1, uint32_t a2, uint32_t a3,
                                         uint32_t b0, uint32_t b1)
{
    asm volatile(
        "mma.sync.aligned.m16n8k8.row.col.f32.tf32.tf32.f32 "
        "{%0,%1,%2,%3}, {%4,%5,%6,%7}, {%8,%9}, {%0,%1,%2,%3};\n"
        : "+f"(c[0]), "+f"(c[1]), "+f"(c[2]), "+f"(c[3])
        : "r"(a0), "r"(a1), "r"(a2), "r"(a3), "r"(b0), "r"(b1));
}

// ---------------------------------------------------------------------------
// Kernel 1: base discretization.  w = 2*C*(lambda-1)/A, dtA terms.
// ---------------------------------------------------------------------------
__global__ void param_kernel(const float* __restrict__ log_dt,
                             const float* __restrict__ Ar,
                             const float* __restrict__ Ai,
                             const float* __restrict__ Cr,
                             const float* __restrict__ Ci)
{
    int i = blockIdx.x * blockDim.x + threadIdx.x;
    if (i >= Hd * Nm) return;
    int h = i >> 5;
    float dt = expf(log_dt[h]);
    float ar = Ar[i], ai = Ai[i];
    float er = expf(dt * ar);
    float lr = er * cosf(dt * ai);
    float li = er * sinf(dt * ai);
    float nr = lr - 1.0f, ni = li;
    float inv = 1.0f / (ar * ar + ai * ai);
    float qr = (nr * ar + ni * ai) * inv;
    float qi = (ni * ar - nr * ai) * inv;
    float cr = Cr[i], ci = Ci[i];
    g_wr[i] = 2.0f * (cr * qr - ci * qi);
    g_wi[i] = 2.0f * (cr * qi + ci * qr);
    g_dtar[i] = dt * ar;
    g_dtai[i] = dt * ai;
}

// ---------------------------------------------------------------------------
// Kernel 1b: per-h frag tables (CL=64) + taps + lambda^64.  One block per h.
// ---------------------------------------------------------------------------
__global__ void param2_kernel(const float* __restrict__ Dp)
{
    int h = blockIdx.x;
    int tid = threadIdx.x;
    __shared__ float swr[32], swi[32], sar[32], sai[32];
    if (tid < 32) {
        swr[tid] = g_wr[h * 32 + tid];
        swi[tid] = g_wi[h * 32 + tid];
        sar[tid] = g_dtar[h * 32 + tid];
        sai[tid] = g_dtai[h * 32 + tid];
    }
    __syncthreads();

    // P: frag = hh*4+kcf;  q = frag*128 + lane*4 + reg
    for (int q = tid; q < 2048; q += 256) {
        int reg = q & 3, lane = (q >> 2) & 31, frag = q >> 7;
        int hh = frag >> 2, kcf = frag & 3;
        int g = lane >> 2, t4 = lane & 3;
        int row = hh * 16 + g + (reg & 1) * 8;        // j 0..63
        int col = kcf * 8 + t4 + (reg >> 1) * 4;      // n 0..31
        float p = (float)(row + 1);
        float e = expf(p * sar[col]);
        float ss, cc;
        sincosf(p * sai[col], &ss, &cc);
        float lpr = e * cc, lpi = e * ss;
        ((uint32_t*)g_PrF4)[h * 2048 + q]  = f2tf32(swr[col] * lpr - swi[col] * lpi);
        ((uint32_t*)g_PinF4)[h * 2048 + q] = f2tf32(-(swr[col] * lpi + swi[col] * lpr));
    }
    // Lambda: frag = mt*8+kc
    for (int q = tid; q < 2048; q += 256) {
        int reg = q & 3, lane = (q >> 2) & 31, frag = q >> 7;
        int mt = frag >> 3, kc = frag & 7;
        int g = lane >> 2, t4 = lane & 3;
        int row = mt * 16 + g + (reg & 1) * 8;        // n 0..31
        int col = kc * 8 + t4 + (reg >> 1) * 4;       // i 0..63
        float p = (float)(CL - 1 - col);
        float e = expf(p * sar[row]);
        float ss, cc;
        sincosf(p * sai[row], &ss, &cc);
        ((uint32_t*)g_LrF4)[h * 2048 + q] = f2tf32(e * cc);
        ((uint32_t*)g_LiF4)[h * 2048 + q] = f2tf32(e * ss);
    }
    // taps K[d] = sum_n Re(w λ^d), D folded into tap 0
    if (tid < CL) {
        int d = tid;
        float acc = 0.0f;
        for (int n = 0; n < 32; ++n) {
            float e = expf((float)d * sar[n]);
            float ss, cc;
            sincosf((float)d * sai[n], &ss, &cc);
            acc += swr[n] * (e * cc) - swi[n] * (e * ss);
        }
        if (d == 0) acc += Dp[h];
        g_Ktap[h * CL + d] = f2tf32(acc);
    }
    if (tid < 32) {
        float e = expf((float)CL * sar[tid]);
        float ss, cc;
        sincosf((float)CL * sai[tid], &ss, &cc);
        g_l64r[h * 32 + tid] = e * cc;
        g_l64i[h * 32 + tid] = e * ss;
    }
}

// ---------------------------------------------------------------------------
// Kernel 1c: W -> tf32 in A-fragment order (unchanged, validated R8).
// ---------------------------------------------------------------------------
__global__ void wconv_kernel(const float* __restrict__ W)
{
    int i = blockIdx.x * blockDim.x + threadIdx.x;
    if (i >= 2 * Hd * Hd) return;
    int tile = i >> 16;
    int q = i & 65535;
    int reg = q & 3, lane = (q >> 2) & 31, m8 = (q >> 7) & 7, ks = (q >> 10) & 1, kc = q >> 11;
    int g = lane >> 2, t4 = lane & 3;
    int half = m8 >> 2, wmmi = m8 & 3;
    int row = tile * 64 + wmmi * 16 + g + (reg & 1) * 8 + half * 512;
    int k = kc * 16 + ks * 8 + t4 + (reg >> 1) * 4;
    g_WtF[i] = f2tf32(W[row * Hd + k]);
}

// ---------------------------------------------------------------------------
// snake1 frag builder for a chunk PAIR: stage 128 cols of x per batch row
// (stride 132 words -> conflict-free gather), build both chunks' fragments.
// ---------------------------------------------------------------------------
__device__ __forceinline__ void build_u_frags2(
    const float* __restrict__ x, float* sXw,
    int h, int c0, int lane, int g, int t4,
    float a1v, float inv1, uint32_t* uB0, uint32_t* uB1)
{
    #pragma unroll
    for (int bb = 0; bb < 8; ++bb) {
        float4 v = *(const float4*)(x + ((size_t)bb * Hd + h) * Ls + c0 * CL + lane * 4);
        *(float4*)&sXw[bb * 132 + lane * 4] = v;
    }
    __syncwarp();
    #pragma unroll
    for (int kc = 0; kc < 8; ++kc)
        #pragma unroll
        for (int r = 0; r < 2; ++r) {
            int t = kc * 8 + t4 + 4 * r;
            float xv0 = sXw[g * 132 + t];
            float sn0 = __sinf(a1v * xv0);
            uB0[kc * 2 + r] = f2tf32(fmaf(sn0 * sn0, inv1, xv0));
            float xv1 = sXw[g * 132 + 64 + t];
            float sn1 = __sinf(a1v * xv1);
            uB1[kc * 2 + r] = f2tf32(fmaf(sn1 * sn1, inv1, xv1));
        }
}

// ---------------------------------------------------------------------------
// Kernel A: per warp: TWO chunks (c0, c0+1): snake1, summaries Lam@U.
// Table LDS shared across the pair.  16384 warps, 2048 blocks.
// ---------------------------------------------------------------------------
__global__ __launch_bounds__(256)
void scanA_kernel(const float* __restrict__ x,
                  const float* __restrict__ alpha1)
{
    __shared__ uint4 sLr[512];
    __shared__ uint4 sLi[512];
    __shared__ float sX[8][8 * 132];

    const int tid  = threadIdx.x;
    const int wp   = tid >> 5;
    const int lane = tid & 31;
    const int g    = lane >> 2;
    const int t4   = lane & 3;
    const int h    = blockIdx.x >> 2;
    const int c0   = (((blockIdx.x & 3) << 3) + wp) * 2;

    #pragma unroll
    for (int i = tid; i < 512; i += 256) {
        sLr[i] = g_LrF4[h * 512 + i];
        sLi[i] = g_LiF4[h * 512 + i];
    }
    __syncthreads();

    const float a1v  = alpha1[h];
    const float inv1 = 1.0f / (a1v + 1e-9f);

    uint32_t uB0[16], uB1[16];
    build_u_frags2(x, sX[wp], h, c0, lane, g, t4, a1v, inv1, uB0, uB1);

    float AccR0[2][4] = {}, AccI0[2][4] = {};
    float AccR1[2][4] = {}, AccI1[2][4] = {};
    #pragma unroll
    for (int kc = 0; kc < 8; ++kc)
        #pragma unroll
        for (int mt = 0; mt < 2; ++mt) {
            uint4 ar = sLr[(mt * 8 + kc) * 32 + lane];
            uint4 ai = sLi[(mt * 8 + kc) * 32 + lane];
            mma_tf32(AccR0[mt], ar.x, ar.y, ar.z, ar.w, uB0[kc * 2], uB0[kc * 2 + 1]);
            mma_tf32(AccI0[mt], ai.x, ai.y, ai.z, ai.w, uB0[kc * 2], uB0[kc * 2 + 1]);
            mma_tf32(AccR1[mt], ar.x, ar.y, ar.z, ar.w, uB1[kc * 2], uB1[kc * 2 + 1]);
            mma_tf32(AccI1[mt], ai.x, ai.y, ai.z, ai.w, uB1[kc * 2], uB1[kc * 2 + 1]);
        }

    #pragma unroll
    for (int ch = 0; ch < 2; ++ch) {
        size_t sbase = (size_t)(h * NC + c0 + ch) * 128;
        float (*AR)[4] = ch ? AccR1 : AccR0;
        float (*AI)[4] = ch ? AccI1 : AccI0;
        #pragma unroll
        for (int mt = 0; mt < 2; ++mt)
            #pragma unroll
            for (int rr = 0; rr < 2; ++rr) {
                int n = mt * 16 + rr * 8 + g;
                g_slocR2[sbase + n * 4 + t4] = make_float2(AR[mt][rr * 2], AR[mt][rr * 2 + 1]);
                g_slocI2[sbase + n * 4 + t4] = make_float2(AI[mt][rr * 2], AI[mt][rr * 2 + 1]);
            }
    }
}

// ---------------------------------------------------------------------------
// Kernel B: exclusive scan of chunk carries (64-chunk chain, λ^64).
// ---------------------------------------------------------------------------
__global__ __launch_bounds__(256)
void scanB_kernel()
{
    int gid = blockIdx.x * 256 + threadIdx.x;
    int h   = gid >> 7;
    int idx = gid & 127;
    int n   = idx >> 2;

    float lr = g_l64r[h * 32 + n];
    float li = g_l64i[h * 32 + n];

    size_t base = (size_t)h * NC * 128 + idx;
    float cr0 = 0.f, ci0 = 0.f, cr1 = 0.f, ci1 = 0.f;

    #pragma unroll 1
    for (int c = 0; c < NC; ++c) {
        size_t k = base + (size_t)c * 128;
        g_carR2[k] = make_uint2(f2tf32(cr0), f2tf32(cr1));
        g_carI2[k] = make_uint2(f2tf32(ci0), f2tf32(ci1));
        float2 slr = g_slocR2[k];
        float2 sli = g_slocI2[k];
        float nr0 = fmaf(lr, cr0, fmaf(-li, ci0, slr.x));
        float ni0 = fmaf(lr, ci0, fmaf( li, cr0, sli.x));
        float nr1 = fmaf(lr, cr1, fmaf(-li, ci1, slr.y));
        float ni1 = fmaf(lr, ci1, fmaf( li, cr1, sli.y));
        cr0 = nr0; ci0 = ni0; cr1 = nr1; ci1 = ni1;
    }
}

// ---------------------------------------------------------------------------
// Kernel C: per warp: TWO chunks: recompute u, Y = T@U + Pr@S + Pin@S, snake2.
// P-table/tap LDS shared across the pair.  16384 warps, 2048 blocks.
// ---------------------------------------------------------------------------
__global__ __launch_bounds__(256)
void scanC_kernel(const float* __restrict__ x,
                  const float* __restrict__ alpha1,
                  const float* __restrict__ alpha2)
{
    __shared__ uint4    sPr[512];
    __shared__ uint4    sPin[512];
    __shared__ float    sX[8][8 * 132];
    __shared__ uint32_t sKt[CL];

    const int tid  = threadIdx.x;
    const int wp   = tid >> 5;
    const int lane = tid & 31;
    const int g    = lane >> 2;
    const int t4   = lane & 3;
    const int h    = blockIdx.x >> 2;
    const int c0   = (((blockIdx.x & 3) << 3) + wp) * 2;

    #pragma unroll
    for (int i = tid; i < 512; i += 256) {
        sPr[i]  = g_PrF4[h * 512 + i];
        sPin[i] = g_PinF4[h * 512 + i];
    }
    if (tid < CL) sKt[tid] = g_Ktap[h * CL + tid];
    __syncthreads();

    const float a1v  = alpha1[h];
    const float inv1 = 1.0f / (a1v + 1e-9f);

    uint32_t uB0[16], uB1[16];
    build_u_frags2(x, sX[wp], h, c0, lane, g, t4, a1v, inv1, uB0, uB1);

    // carry fragments for both chunks (B-operand: k = mode n, n-dim = batch)
    const uint32_t* carR = (const uint32_t*)g_carR2 + (size_t)(h * NC + c0) * 256;
    const uint32_t* carI = (const uint32_t*)g_carI2 + (size_t)(h * NC + c0) * 256;
    uint32_t SrB0[8], SiB0[8], SrB1[8], SiB1[8];
    #pragma unroll
    for (int kc2 = 0; kc2 < 4; ++kc2)
        #pragma unroll
        for (int r = 0; r < 2; ++r) {
            int n = kc2 * 8 + t4 + 4 * r;
            SrB0[kc2 * 2 + r] = carR[n * 8 + g];
            SiB0[kc2 * 2 + r] = carI[n * 8 + g];
            SrB1[kc2 * 2 + r] = carR[256 + n * 8 + g];
            SiB1[kc2 * 2 + r] = carI[256 + n * 8 + g];
        }

    float yC0[4][4] = {}, yC1[4][4] = {};

    // Toeplitz path (taps shared between chunks): 2x20 mmas
    #pragma unroll
    for (int hh = 0; hh < 4; ++hh) {
        const int kmax = 2 * hh + 2;
        #pragma unroll
        for (int kc = 0; kc < 8; ++kc) {
            if (kc >= kmax) break;               // compile-time pruned
            int d0 = hh * 16 + g - (kc * 8 + t4);
            int d1 = d0 + 8, d2 = d0 - 4, d3 = d0 + 4;
            uint32_t a0 = (d0 >= 0) ? sKt[d0] : 0u;
            uint32_t a1 = (d1 >= 0) ? sKt[d1] : 0u;
            uint32_t a2 = (d2 >= 0) ? sKt[d2] : 0u;
            uint32_t a3 = (d3 >= 0) ? sKt[d3] : 0u;
            mma_tf32(yC0[hh], a0, a1, a2, a3, uB0[kc * 2], uB0[kc * 2 + 1]);
            mma_tf32(yC1[hh], a0, a1, a2, a3, uB1[kc * 2], uB1[kc * 2 + 1]);
        }
    }

    // carry path (P frags shared between chunks): 2x32 mmas
    #pragma unroll
    for (int hh = 0; hh < 4; ++hh)
        #pragma unroll
        for (int kc2 = 0; kc2 < 4; ++kc2) {
            uint4 pa = sPr[(hh * 4 + kc2) * 32 + lane];
            uint4 pb = sPin[(hh * 4 + kc2) * 32 + lane];
            mma_tf32(yC0[hh], pa.x, pa.y, pa.z, pa.w, SrB0[kc2 * 2], SrB0[kc2 * 2 + 1]);
            mma_tf32(yC0[hh], pb.x, pb.y, pb.z, pb.w, SiB0[kc2 * 2], SiB0[kc2 * 2 + 1]);
            mma_tf32(yC1[hh], pa.x, pa.y, pa.z, pa.w, SrB1[kc2 * 2], SrB1[kc2 * 2 + 1]);
            mma_tf32(yC1[hh], pb.x, pb.y, pb.z, pb.w, SiB1[kc2 * 2], SiB1[kc2 * 2 + 1]);
        }

    // epilogue: snake2, store tf32 bits into (B,H,L) layout, both chunks
    const float a2v  = alpha2[h];
    const float inv2 = 1.0f / (a2v + 1e-9f);
    #pragma unroll
    for (int ch = 0; ch < 2; ++ch) {
        float (*yC)[4] = ch ? yC1 : yC0;
        int cbase = (c0 + ch) * CL;
        #pragma unroll
        for (int hh = 0; hh < 4; ++hh)
            #pragma unroll
            for (int cc = 0; cc < 4; ++cc) {
                int j = hh * 16 + g + 8 * (cc >> 1);
                int b = 2 * t4 + (cc & 1);
                float yv = yC[hh][cc];
                float s2 = __sinf(a2v * yv);
                yv = fmaf(s2 * s2, inv2, yv);
                g_y[((size_t)b * Hd + h) * Ls + cbase + j] = f2tf32(yv);
            }
    }
}

// ---------------------------------------------------------------------------
// Kernel 3: fused 1x1 conv GEMM (tf32 mma.sync) + GLU + residual.
// 4-stage cp.async pipeline, ONE barrier per k-chunk.
// ---------------------------------------------------------------------------
#define BK 16
#define SYS (128 + 8)
#define STG 4

__device__ __forceinline__ void cp_async16(uint32_t smem, const void* gmem) {
    asm volatile("cp.async.cg.shared.global [%0], [%1], 16;\n" :: "r"(smem), "l"(gmem));
}
__device__ __forceinline__ void cp_commit() {
    asm volatile("cp.async.commit_group;\n");
}
template <int N> __device__ __forceinline__ void cp_wait() {
    asm volatile("cp.async.wait_group %0;\n" :: "n"(N));
}

__global__ __launch_bounds__(256, 2)
void gemm_glu_kernel(const float* __restrict__ bias,
                     const float* __restrict__ X,
                     float* __restrict__ out)
{
    __shared__ uint4    sW4[STG][512];        // frag-ordered W chunk (8KB per stage)
    __shared__ uint32_t sY[STG][BK][SYS];

    const int tid = threadIdx.x;
    const int lane = tid & 31;
    const int wid = tid >> 5;
    const int wm = wid >> 2;
    const int wn = wid & 3;
    const int t4 = lane & 3;
    const int g  = lane >> 2;

    const int l0 = blockIdx.x * 128;
    const int r0 = blockIdx.y * 64;
    const int bb = blockIdx.z;

    const uint32_t* Yb = g_y + (size_t)bb * Hd * Ls;
    const uint32_t* Wtile = g_WtF + (size_t)blockIdx.y * 65536;

    const uint32_t swb = (uint32_t)__cvta_generic_to_shared(&sW4[0][0]);
    const uint32_t syb = (uint32_t)__cvta_generic_to_shared(&sY[0][0][0]);

    int wf0 = tid, wf1 = tid + 256;
    int yk0 = wf0 >> 5, yc0 = (wf0 & 31) << 2;
    int yk1 = wf1 >> 5, yc1 = (wf1 & 31) << 2;

    float acc[2][2][4][4];
    #pragma unroll
    for (int a = 0; a < 2; ++a)
        #pragma unroll
        for (int m = 0; m < 2; ++m)
            #pragma unroll
            for (int n = 0; n < 4; ++n)
                #pragma unroll
                for (int q = 0; q < 4; ++q) acc[a][m][n][q] = 0.0f;

    #define LOAD_CHUNK(KC, BUF) do {                                              \
        int _k0 = (KC) * BK;                                                      \
        cp_async16(swb + ((BUF) * 512 + tid) * 16,                                \
                   Wtile + (KC) * 2048 + tid * 4);                                \
        cp_async16(swb + ((BUF) * 512 + tid + 256) * 16,                          \
                   Wtile + (KC) * 2048 + (tid + 256) * 4);                        \
        cp_async16(syb + (((BUF) * BK + yk0) * SYS + yc0) * 4,                    \
                   Yb + (size_t)(_k0 + yk0) * Ls + l0 + yc0);                     \
        cp_async16(syb + (((BUF) * BK + yk1) * SYS + yc1) * 4,                    \
                   Yb + (size_t)(_k0 + yk1) * Ls + l0 + yc1);                     \
    } while (0)

    LOAD_CHUNK(0, 0); cp_commit();
    LOAD_CHUNK(1, 1); cp_commit();
    LOAD_CHUNK(2, 2); cp_commit();

    const int NCH = Hd / BK;   // 32
    #pragma unroll 1
    for (int kc = 0; kc < NCH; ++kc) {
        // oldest pending group must finish: pending = min(3, NCH-kc)
        if (kc <= NCH - 3)      cp_wait<2>();
        else if (kc == NCH - 2) cp_wait<1>();
        else                    cp_wait<0>();
        __syncthreads();
        if (kc + 3 < NCH) { LOAD_CHUNK(kc + 3, (kc + 3) & 3); cp_commit(); }
        int buf = kc & 3;

        #pragma unroll
        for (int ks = 0; ks < 2; ++ks) {
            int kk = ks * 8 + t4;
            uint32_t B0[4], B1[4];
            #pragma unroll
            for (int ni = 0; ni < 4; ++ni) {
                int col = wn * 32 + ni * 8 + g;
                B0[ni] = sY[buf][kk][col];
                B1[ni] = sY[buf][kk + 4][col];
            }
            #pragma unroll
            for (int half = 0; half < 2; ++half) {
                #pragma unroll
                for (int mi = 0; mi < 2; ++mi) {
                    uint4 av = sW4[buf][(ks * 8 + half * 4 + wm * 2 + mi) * 32 + lane];
                    #pragma unroll
                    for (int ni = 0; ni < 4; ++ni)
                        mma_tf32(acc[half][mi][ni], av.x, av.y, av.z, av.w, B0[ni], B1[ni]);
                }
            }
        }
    }
    #undef LOAD_CHUNK

    const float* Xb = X   + (size_t)bb * Hd * Ls;
    float*       Ob = out + (size_t)bb * Hd * Ls;

    #pragma unroll
    for (int mi = 0; mi < 2; ++mi) {
        int o = r0 + wm * 32 + mi * 16 + g;
        float ba0 = bias[o];
        float bB0 = bias[o + 512];
        float ba8 = bias[o + 8];
        float bB8 = bias[o + 520];
        #pragma unroll
        for (int ni = 0; ni < 4; ++ni) {
            int l = l0 + wn * 32 + ni * 8 + 2 * t4;
            const float* A = acc[0][mi][ni];
            const float* Bc = acc[1][mi][ni];

            float2 xv0 = *(const float2*)(Xb + (size_t)o * Ls + l);
            float2 xv8 = *(const float2*)(Xb + (size_t)(o + 8) * Ls + l);

            float av, bv, sg;
            float2 ov0, ov8;
            av = A[0] + ba0; bv = Bc[0] + bB0; sg = 1.0f / (1.0f + expf(-bv));
            ov0.x = xv0.x + av * sg;
            av = A[1] + ba0; bv = Bc[1] + bB0; sg = 1.0f / (1.0f + expf(-bv));
            ov0.y = xv0.y + av * sg;
            av = A[2] + ba8; bv = Bc[2] + bB8; sg = 1.0f / (1.0f + expf(-bv));
            ov8.x = xv8.x + av * sg;
            av = A[3] + ba8; bv = Bc[3] + bB8; sg = 1.0f / (1.0f + expf(-bv));
            ov8.y = xv8.y + av * sg;

            *(float2*)(Ob + (size_t)o * Ls + l) = ov0;
            *(float2*)(Ob + (size_t)(o + 8) * Ls + l) = ov8;
        }
    }
}

// ---------------------------------------------------------------------------
extern "C" void kernel_launch(void* const* d_in, const int* in_sizes, int n_in,
                              void* d_out, int out_size)
{
    const float* x      = (const float*)d_in[0];
    const float* alpha1 = (const float*)d_in[1];
    const float* log_dt = (const float*)d_in[2];
    const float* Ar     = (const float*)d_in[3];
    const float* Ai     = (const float*)d_in[4];
    const float* Cr     = (const float*)d_in[5];
    const float* Ci     = (const float*)d_in[6];
    const float* D      = (const float*)d_in[7];
    const float* alpha2 = (const float*)d_in[8];
    const float* W      = (const float*)d_in[9];
    const float* bconv  = (const float*)d_in[10];
    float* out = (float*)d_out;

    param_kernel<<<(Hd * Nm + 255) / 256, 256>>>(log_dt, Ar, Ai, Cr, Ci);
    param2_kernel<<<Hd, 256>>>(D);
    wconv_kernel<<<(2 * Hd * Hd + 255) / 256, 256>>>(W);

    scanA_kernel<<<Hd * 4, 256>>>(x, alpha1);        // 2 chunks/warp
    scanB_kernel<<<(Hd * 128) / 256, 256>>>();       // 65536 threads
    scanC_kernel<<<Hd * 4, 256>>>(x, alpha1, alpha2);// 2 chunks/warp

    dim3 grid(Ls / 128, Hd / 64, Bsz);
    gemm_glu_kernel<<<grid, 256>>>(bconv, x, out);
}

// round 14
// speedup vs baseline: 1.3704x; 1.0135x over previous
#include <cuda_runtime.h>
#include <math.h>
#include <stdint.h>

// Problem constants
#define Bsz 8
#define Hd  512
#define Ls  4096
#define Nm  32
#define CL  64             // chunk length
#define NC  (Ls / CL)      // 64 chunks

// Scratch (allocation-free rule: __device__ globals)
__device__ float    g_wr[Hd * Nm];
__device__ float    g_wi[Hd * Nm];
__device__ float    g_dtar[Hd * Nm];
__device__ float    g_dtai[Hd * Nm];

__device__ uint32_t g_Ktap[Hd * CL];        // Toeplitz taps, tf32 bits, D folded into tap 0
// Fragment tables, reg-contiguous per lane: idx = (frag*32 + lane) -> uint4 of 4 regs
__device__ uint4    g_PrF4[Hd * 512];       // P  = Re(w λ^{j+1}),  A-frag (M=64,K=32), 16 frags
__device__ uint4    g_PinF4[Hd * 512];      // -Im(w λ^{j+1})
__device__ uint4    g_LrF4[Hd * 512];       // Re(λ^{63-i}),        A-frag (M=32,K=64), 16 frags
__device__ uint4    g_LiF4[Hd * 512];       // Im(λ^{63-i})
__device__ float    g_l64r[Hd * Nm];        // Re(λ^64)
__device__ float    g_l64i[Hd * Nm];

__device__ float2   g_slocR2[(size_t)Hd * NC * 128];   // chunk summaries [h][c][n*4+b2]
__device__ float2   g_slocI2[(size_t)Hd * NC * 128];
__device__ uint2    g_carR2[(size_t)Hd * NC * 128];    // incoming carries, tf32 bits
__device__ uint2    g_carI2[(size_t)Hd * NC * 128];

__device__ uint32_t g_WtF[2 * Hd * Hd];                // W tf32 bits, A-frag order per 64-row tile
__device__ uint32_t g_y[(size_t)Bsz * Hd * Ls];        // post-snake2, tf32 bits (B,H,L)

__device__ __forceinline__ uint32_t f2tf32(float f) {
    uint32_t b;
    asm("cvt.rna.tf32.f32 %0, %1;" : "=r"(b) : "f"(f));
    return b;
}

// validated tf32 mma.sync fragment layout (R5-R12):
//  A: reg0=(g,t4) reg1=(g+8,t4) reg2=(g,t4+4) reg3=(g+8,t4+4)
//  B: reg0=B[k=t4][n=g] reg1=B[k=t4+4][n=g]
//  C: c0=(g,2t4) c1=(g,2t4+1) c2=(g+8,2t4) c3=(g+8,2t4+1)
__device__ __forceinline__ void mma_tf32(float* c,
                                         uint32_t a0, uint32_t a1, uint32_t a2, uint32_t a3,
                                         uint32_t b0, uint32_t b1)
{
    asm volatile(
        "mma.sync.aligned.m16n8k8.row.col.f32.tf32.tf32.f32 "
        "{%0,%1,%2,%3}, {%4,%5,%6,%7}, {%8,%9}, {%0,%1,%2,%3};\n"
        : "+f"(c[0]), "+f"(c[1]), "+f"(c[2]), "+f"(c[3])
        : "r"(a0), "r"(a1), "r"(a2), "r"(a3), "r"(b0), "r"(b1));
}

// ---------------------------------------------------------------------------
// Kernel 1: base discretization.  w = 2*C*(lambda-1)/A, dtA terms.
// ---------------------------------------------------------------------------
__global__ void param_kernel(const float* __restrict__ log_dt,
                             const float* __restrict__ Ar,
                             const float* __restrict__ Ai,
                             const float* __restrict__ Cr,
                             const float* __restrict__ Ci)
{
    int i = blockIdx.x * blockDim.x + threadIdx.x;
    if (i >= Hd * Nm) return;
    int h = i >> 5;
    float dt = expf(log_dt[h]);
    float ar = Ar[i], ai = Ai[i];
    float er = expf(dt * ar);
    float lr = er * cosf(dt * ai);
    float li = er * sinf(dt * ai);
    float nr = lr - 1.0f, ni = li;
    float inv = 1.0f / (ar * ar + ai * ai);
    float qr = (nr * ar + ni * ai) * inv;
    float qi = (ni * ar - nr * ai) * inv;
    float cr = Cr[i], ci = Ci[i];
    g_wr[i] = 2.0f * (cr * qr - ci * qi);
    g_wi[i] = 2.0f * (cr * qi + ci * qr);
    g_dtar[i] = dt * ar;
    g_dtai[i] = dt * ai;
}

// ---------------------------------------------------------------------------
// Kernel 1b: per-h frag tables (CL=64) + taps + lambda^64.  One block per h.
// ---------------------------------------------------------------------------
__global__ void param2_kernel(const float* __restrict__ Dp)
{
    int h = blockIdx.x;
    int tid = threadIdx.x;
    __shared__ float swr[32], swi[32], sar[32], sai[32];
    if (tid < 32) {
        swr[tid] = g_wr[h * 32 + tid];
        swi[tid] = g_wi[h * 32 + tid];
        sar[tid] = g_dtar[h * 32 + tid];
        sai[tid] = g_dtai[h * 32 + tid];
    }
    __syncthreads();

    // P: frag = hh*4+kcf;  q = frag*128 + lane*4 + reg
    for (int q = tid; q < 2048; q += 256) {
        int reg = q & 3, lane = (q >> 2) & 31, frag = q >> 7;
        int hh = frag >> 2, kcf = frag & 3;
        int g = lane >> 2, t4 = lane & 3;
        int row = hh * 16 + g + (reg & 1) * 8;        // j 0..63
        int col = kcf * 8 + t4 + (reg >> 1) * 4;      // n 0..31
        float p = (float)(row + 1);
        float e = expf(p * sar[col]);
        float ss, cc;
        sincosf(p * sai[col], &ss, &cc);
        float lpr = e * cc, lpi = e * ss;
        ((uint32_t*)g_PrF4)[h * 2048 + q]  = f2tf32(swr[col] * lpr - swi[col] * lpi);
        ((uint32_t*)g_PinF4)[h * 2048 + q] = f2tf32(-(swr[col] * lpi + swi[col] * lpr));
    }
    // Lambda: frag = mt*8+kc
    for (int q = tid; q < 2048; q += 256) {
        int reg = q & 3, lane = (q >> 2) & 31, frag = q >> 7;
        int mt = frag >> 3, kc = frag & 7;
        int g = lane >> 2, t4 = lane & 3;
        int row = mt * 16 + g + (reg & 1) * 8;        // n 0..31
        int col = kc * 8 + t4 + (reg >> 1) * 4;       // i 0..63
        float p = (float)(CL - 1 - col);
        float e = expf(p * sar[row]);
        float ss, cc;
        sincosf(p * sai[row], &ss, &cc);
        ((uint32_t*)g_LrF4)[h * 2048 + q] = f2tf32(e * cc);
        ((uint32_t*)g_LiF4)[h * 2048 + q] = f2tf32(e * ss);
    }
    // taps K[d] = sum_n Re(w λ^d), D folded into tap 0
    if (tid < CL) {
        int d = tid;
        float acc = 0.0f;
        for (int n = 0; n < 32; ++n) {
            float e = expf((float)d * sar[n]);
            float ss, cc;
            sincosf((float)d * sai[n], &ss, &cc);
            acc += swr[n] * (e * cc) - swi[n] * (e * ss);
        }
        if (d == 0) acc += Dp[h];
        g_Ktap[h * CL + d] = f2tf32(acc);
    }
    if (tid < 32) {
        float e = expf((float)CL * sar[tid]);
        float ss, cc;
        sincosf((float)CL * sai[tid], &ss, &cc);
        g_l64r[h * 32 + tid] = e * cc;
        g_l64i[h * 32 + tid] = e * ss;
    }
}

// ---------------------------------------------------------------------------
// Kernel 1c: W -> tf32 in A-fragment order (unchanged, validated R8).
// ---------------------------------------------------------------------------
__global__ void wconv_kernel(const float* __restrict__ W)
{
    int i = blockIdx.x * blockDim.x + threadIdx.x;
    if (i >= 2 * Hd * Hd) return;
    int tile = i >> 16;
    int q = i & 65535;
    int reg = q & 3, lane = (q >> 2) & 31, m8 = (q >> 7) & 7, ks = (q >> 10) & 1, kc = q >> 11;
    int g = lane >> 2, t4 = lane & 3;
    int half = m8 >> 2, wmmi = m8 & 3;
    int row = tile * 64 + wmmi * 16 + g + (reg & 1) * 8 + half * 512;
    int k = kc * 16 + ks * 8 + t4 + (reg >> 1) * 4;
    g_WtF[i] = f2tf32(W[row * Hd + k]);
}

// ---------------------------------------------------------------------------
// snake1 frag builder for a chunk PAIR (validated R12).
// ---------------------------------------------------------------------------
__device__ __forceinline__ void build_u_frags2(
    const float* __restrict__ x, float* sXw,
    int h, int c0, int lane, int g, int t4,
    float a1v, float inv1, uint32_t* uB0, uint32_t* uB1)
{
    #pragma unroll
    for (int bb = 0; bb < 8; ++bb) {
        float4 v = *(const float4*)(x + ((size_t)bb * Hd + h) * Ls + c0 * CL + lane * 4);
        *(float4*)&sXw[bb * 132 + lane * 4] = v;
    }
    __syncwarp();
    #pragma unroll
    for (int kc = 0; kc < 8; ++kc)
        #pragma unroll
        for (int r = 0; r < 2; ++r) {
            int t = kc * 8 + t4 + 4 * r;
            float xv0 = sXw[g * 132 + t];
            float sn0 = __sinf(a1v * xv0);
            uB0[kc * 2 + r] = f2tf32(fmaf(sn0 * sn0, inv1, xv0));
            float xv1 = sXw[g * 132 + 64 + t];
            float sn1 = __sinf(a1v * xv1);
            uB1[kc * 2 + r] = f2tf32(fmaf(sn1 * sn1, inv1, xv1));
        }
}

// ---------------------------------------------------------------------------
// Kernel A: per warp: TWO chunks: snake1, summaries Lam@U (validated R12).
// ---------------------------------------------------------------------------
__global__ __launch_bounds__(256)
void scanA_kernel(const float* __restrict__ x,
                  const float* __restrict__ alpha1)
{
    __shared__ uint4 sLr[512];
    __shared__ uint4 sLi[512];
    __shared__ float sX[8][8 * 132];

    const int tid  = threadIdx.x;
    const int wp   = tid >> 5;
    const int lane = tid & 31;
    const int g    = lane >> 2;
    const int t4   = lane & 3;
    const int h    = blockIdx.x >> 2;
    const int c0   = (((blockIdx.x & 3) << 3) + wp) * 2;

    #pragma unroll
    for (int i = tid; i < 512; i += 256) {
        sLr[i] = g_LrF4[h * 512 + i];
        sLi[i] = g_LiF4[h * 512 + i];
    }
    __syncthreads();

    const float a1v  = alpha1[h];
    const float inv1 = 1.0f / (a1v + 1e-9f);

    uint32_t uB0[16], uB1[16];
    build_u_frags2(x, sX[wp], h, c0, lane, g, t4, a1v, inv1, uB0, uB1);

    float AccR0[2][4] = {}, AccI0[2][4] = {};
    float AccR1[2][4] = {}, AccI1[2][4] = {};
    #pragma unroll
    for (int kc = 0; kc < 8; ++kc)
        #pragma unroll
        for (int mt = 0; mt < 2; ++mt) {
            uint4 ar = sLr[(mt * 8 + kc) * 32 + lane];
            uint4 ai = sLi[(mt * 8 + kc) * 32 + lane];
            mma_tf32(AccR0[mt], ar.x, ar.y, ar.z, ar.w, uB0[kc * 2], uB0[kc * 2 + 1]);
            mma_tf32(AccI0[mt], ai.x, ai.y, ai.z, ai.w, uB0[kc * 2], uB0[kc * 2 + 1]);
            mma_tf32(AccR1[mt], ar.x, ar.y, ar.z, ar.w, uB1[kc * 2], uB1[kc * 2 + 1]);
            mma_tf32(AccI1[mt], ai.x, ai.y, ai.z, ai.w, uB1[kc * 2], uB1[kc * 2 + 1]);
        }

    #pragma unroll
    for (int ch = 0; ch < 2; ++ch) {
        size_t sbase = (size_t)(h * NC + c0 + ch) * 128;
        float (*AR)[4] = ch ? AccR1 : AccR0;
        float (*AI)[4] = ch ? AccI1 : AccI0;
        #pragma unroll
        for (int mt = 0; mt < 2; ++mt)
            #pragma unroll
            for (int rr = 0; rr < 2; ++rr) {
                int n = mt * 16 + rr * 8 + g;
                g_slocR2[sbase + n * 4 + t4] = make_float2(AR[mt][rr * 2], AR[mt][rr * 2 + 1]);
                g_slocI2[sbase + n * 4 + t4] = make_float2(AI[mt][rr * 2], AI[mt][rr * 2 + 1]);
            }
    }
}

// ---------------------------------------------------------------------------
// Kernel B: exclusive scan of chunk carries (64-chunk chain, λ^64).
// ---------------------------------------------------------------------------
__global__ __launch_bounds__(256)
void scanB_kernel()
{
    int gid = blockIdx.x * 256 + threadIdx.x;
    int h   = gid >> 7;
    int idx = gid & 127;
    int n   = idx >> 2;

    float lr = g_l64r[h * 32 + n];
    float li = g_l64i[h * 32 + n];

    size_t base = (size_t)h * NC * 128 + idx;
    float cr0 = 0.f, ci0 = 0.f, cr1 = 0.f, ci1 = 0.f;

    #pragma unroll 1
    for (int c = 0; c < NC; ++c) {
        size_t k = base + (size_t)c * 128;
        g_carR2[k] = make_uint2(f2tf32(cr0), f2tf32(cr1));
        g_carI2[k] = make_uint2(f2tf32(ci0), f2tf32(ci1));
        float2 slr = g_slocR2[k];
        float2 sli = g_slocI2[k];
        float nr0 = fmaf(lr, cr0, fmaf(-li, ci0, slr.x));
        float ni0 = fmaf(lr, ci0, fmaf( li, cr0, sli.x));
        float nr1 = fmaf(lr, cr1, fmaf(-li, ci1, slr.y));
        float ni1 = fmaf(lr, ci1, fmaf( li, cr1, sli.y));
        cr0 = nr0; ci0 = ni0; cr1 = nr1; ci1 = ni1;
    }
}

// ---------------------------------------------------------------------------
// Kernel C: per warp: TWO chunks: recompute u, Y = T@U + Pr@S + Pin@S,
// snake2 (validated R12).
// ---------------------------------------------------------------------------
__global__ __launch_bounds__(256)
void scanC_kernel(const float* __restrict__ x,
                  const float* __restrict__ alpha1,
                  const float* __restrict__ alpha2)
{
    __shared__ uint4    sPr[512];
    __shared__ uint4    sPin[512];
    __shared__ float    sX[8][8 * 132];
    __shared__ uint32_t sKt[CL];

    const int tid  = threadIdx.x;
    const int wp   = tid >> 5;
    const int lane = tid & 31;
    const int g    = lane >> 2;
    const int t4   = lane & 3;
    const int h    = blockIdx.x >> 2;
    const int c0   = (((blockIdx.x & 3) << 3) + wp) * 2;

    #pragma unroll
    for (int i = tid; i < 512; i += 256) {
        sPr[i]  = g_PrF4[h * 512 + i];
        sPin[i] = g_PinF4[h * 512 + i];
    }
    if (tid < CL) sKt[tid] = g_Ktap[h * CL + tid];
    __syncthreads();

    const float a1v  = alpha1[h];
    const float inv1 = 1.0f / (a1v + 1e-9f);

    uint32_t uB0[16], uB1[16];
    build_u_frags2(x, sX[wp], h, c0, lane, g, t4, a1v, inv1, uB0, uB1);

    const uint32_t* carR = (const uint32_t*)g_carR2 + (size_t)(h * NC + c0) * 256;
    const uint32_t* carI = (const uint32_t*)g_carI2 + (size_t)(h * NC + c0) * 256;
    uint32_t SrB0[8], SiB0[8], SrB1[8], SiB1[8];
    #pragma unroll
    for (int kc2 = 0; kc2 < 4; ++kc2)
        #pragma unroll
        for (int r = 0; r < 2; ++r) {
            int n = kc2 * 8 + t4 + 4 * r;
            SrB0[kc2 * 2 + r] = carR[n * 8 + g];
            SiB0[kc2 * 2 + r] = carI[n * 8 + g];
            SrB1[kc2 * 2 + r] = carR[256 + n * 8 + g];
            SiB1[kc2 * 2 + r] = carI[256 + n * 8 + g];
        }

    float yC0[4][4] = {}, yC1[4][4] = {};

    // Toeplitz path (taps shared between chunks): 2x20 mmas
    #pragma unroll
    for (int hh = 0; hh < 4; ++hh) {
        const int kmax = 2 * hh + 2;
        #pragma unroll
        for (int kc = 0; kc < 8; ++kc) {
            if (kc >= kmax) break;               // compile-time pruned
            int d0 = hh * 16 + g - (kc * 8 + t4);
            int d1 = d0 + 8, d2 = d0 - 4, d3 = d0 + 4;
            uint32_t a0 = (d0 >= 0) ? sKt[d0] : 0u;
            uint32_t a1 = (d1 >= 0) ? sKt[d1] : 0u;
            uint32_t a2 = (d2 >= 0) ? sKt[d2] : 0u;
            uint32_t a3 = (d3 >= 0) ? sKt[d3] : 0u;
            mma_tf32(yC0[hh], a0, a1, a2, a3, uB0[kc * 2], uB0[kc * 2 + 1]);
            mma_tf32(yC1[hh], a0, a1, a2, a3, uB1[kc * 2], uB1[kc * 2 + 1]);
        }
    }

    // carry path (P frags shared between chunks): 2x32 mmas
    #pragma unroll
    for (int hh = 0; hh < 4; ++hh)
        #pragma unroll
        for (int kc2 = 0; kc2 < 4; ++kc2) {
            uint4 pa = sPr[(hh * 4 + kc2) * 32 + lane];
            uint4 pb = sPin[(hh * 4 + kc2) * 32 + lane];
            mma_tf32(yC0[hh], pa.x, pa.y, pa.z, pa.w, SrB0[kc2 * 2], SrB0[kc2 * 2 + 1]);
            mma_tf32(yC0[hh], pb.x, pb.y, pb.z, pb.w, SiB0[kc2 * 2], SiB0[kc2 * 2 + 1]);
            mma_tf32(yC1[hh], pa.x, pa.y, pa.z, pa.w, SrB1[kc2 * 2], SrB1[kc2 * 2 + 1]);
            mma_tf32(yC1[hh], pb.x, pb.y, pb.z, pb.w, SiB1[kc2 * 2], SiB1[kc2 * 2 + 1]);
        }

    // epilogue: snake2, store tf32 bits into (B,H,L) layout, both chunks
    const float a2v  = alpha2[h];
    const float inv2 = 1.0f / (a2v + 1e-9f);
    #pragma unroll
    for (int ch = 0; ch < 2; ++ch) {
        float (*yC)[4] = ch ? yC1 : yC0;
        int cbase = (c0 + ch) * CL;
        #pragma unroll
        for (int hh = 0; hh < 4; ++hh)
            #pragma unroll
            for (int cc = 0; cc < 4; ++cc) {
                int j = hh * 16 + g + 8 * (cc >> 1);
                int b = 2 * t4 + (cc & 1);
                float yv = yC[hh][cc];
                float s2 = __sinf(a2v * yv);
                yv = fmaf(s2 * s2, inv2, yv);
                g_y[((size_t)b * Hd + h) * Ls + cbase + j] = f2tf32(yv);
            }
    }
}

// ---------------------------------------------------------------------------
// Kernel 3: fused 1x1 conv GEMM (tf32 mma.sync) + GLU + residual.
// BK=32, 3-stage cp.async pipeline, ONE barrier per 32-K chunk (16 total).
// ---------------------------------------------------------------------------
#define BK 32
#define SYS (128 + 8)
#define STG 3

__device__ __forceinline__ void cp_async16(uint32_t smem, const void* gmem) {
    asm volatile("cp.async.cg.shared.global [%0], [%1], 16;\n" :: "r"(smem), "l"(gmem));
}
__device__ __forceinline__ void cp_commit() {
    asm volatile("cp.async.commit_group;\n");
}
template <int N> __device__ __forceinline__ void cp_wait() {
    asm volatile("cp.async.wait_group %0;\n" :: "n"(N));
}

__global__ __launch_bounds__(256, 2)
void gemm_glu_kernel(const float* __restrict__ bias,
                     const float* __restrict__ X,
                     float* __restrict__ out)
{
    __shared__ uint4    sW4[STG][1024];       // frag-ordered W chunk (16KB per stage)
    __shared__ uint32_t sY[STG][BK][SYS];     // 32-row Y strip (17.4KB per stage)

    const int tid = threadIdx.x;
    const int lane = tid & 31;
    const int wid = tid >> 5;
    const int wm = wid >> 2;
    const int wn = wid & 3;
    const int t4 = lane & 3;
    const int g  = lane >> 2;

    const int l0 = blockIdx.x * 128;
    const int r0 = blockIdx.y * 64;
    const int bb = blockIdx.z;

    const uint32_t* Yb = g_y + (size_t)bb * Hd * Ls;
    const uint32_t* Wtile = g_WtF + (size_t)blockIdx.y * 65536;

    const uint32_t swb = (uint32_t)__cvta_generic_to_shared(&sW4[0][0]);
    const uint32_t syb = (uint32_t)__cvta_generic_to_shared(&sY[0][0][0]);

    float acc[2][2][4][4];
    #pragma unroll
    for (int a = 0; a < 2; ++a)
        #pragma unroll
        for (int m = 0; m < 2; ++m)
            #pragma unroll
            for (int n = 0; n < 4; ++n)
                #pragma unroll
                for (int q = 0; q < 4; ++q) acc[a][m][n][q] = 0.0f;

    // per chunk: W = 4096 words (1024 uint4), Y = 32x128 words (1024 uint4)
    #define LOAD_CHUNK(KC, BUF) do {                                              \
        int _k0 = (KC) * BK;                                                      \
        _Pragma("unroll")                                                         \
        for (int p = 0; p < 4; ++p) {                                             \
            int f4 = tid + 256 * p;                                               \
            cp_async16(swb + ((BUF) * 1024 + f4) * 16,                            \
                       Wtile + (KC) * 4096 + f4 * 4);                             \
            int row = f4 >> 5, col = (f4 & 31) << 2;                              \
            cp_async16(syb + (((BUF) * BK + row) * SYS + col) * 4,                \
                       Yb + (size_t)(_k0 + row) * Ls + l0 + col);                 \
        }                                                                         \
    } while (0)

    LOAD_CHUNK(0, 0); cp_commit();
    LOAD_CHUNK(1, 1); cp_commit();

    const int NCH = Hd / BK;   // 16
    #pragma unroll 1
    for (int kc = 0; kc < NCH; ++kc) {
        if (kc < NCH - 1) cp_wait<1>(); else cp_wait<0>();
        __syncthreads();
        if (kc + 2 < NCH) { LOAD_CHUNK(kc + 2, (kc + 2) % STG); cp_commit(); }
        int buf = kc % STG;

        #pragma unroll
        for (int kh = 0; kh < 2; ++kh)
            #pragma unroll
            for (int ks = 0; ks < 2; ++ks) {
                int kk = kh * 16 + ks * 8 + t4;
                uint32_t B0[4], B1[4];
                #pragma unroll
                for (int ni = 0; ni < 4; ++ni) {
                    int col = wn * 32 + ni * 8 + g;
                    B0[ni] = sY[buf][kk][col];
                    B1[ni] = sY[buf][kk + 4][col];
                }
                #pragma unroll
                for (int half = 0; half < 2; ++half) {
                    #pragma unroll
                    for (int mi = 0; mi < 2; ++mi) {
                        uint4 av = sW4[buf][kh * 512 +
                                           (ks * 8 + half * 4 + wm * 2 + mi) * 32 + lane];
                        #pragma unroll
                        for (int ni = 0; ni < 4; ++ni)
                            mma_tf32(acc[half][mi][ni], av.x, av.y, av.z, av.w,
                                     B0[ni], B1[ni]);
                    }
                }
            }
    }
    #undef LOAD_CHUNK

    const float* Xb = X   + (size_t)bb * Hd * Ls;
    float*       Ob = out + (size_t)bb * Hd * Ls;

    #pragma unroll
    for (int mi = 0; mi < 2; ++mi) {
        int o = r0 + wm * 32 + mi * 16 + g;
        float ba0 = bias[o];
        float bB0 = bias[o + 512];
        float ba8 = bias[o + 8];
        float bB8 = bias[o + 520];
        #pragma unroll
        for (int ni = 0; ni < 4; ++ni) {
            int l = l0 + wn * 32 + ni * 8 + 2 * t4;
            const float* A = acc[0][mi][ni];
            const float* Bc = acc[1][mi][ni];

            float2 xv0 = *(const float2*)(Xb + (size_t)o * Ls + l);
            float2 xv8 = *(const float2*)(Xb + (size_t)(o + 8) * Ls + l);

            float av, bv, sg;
            float2 ov0, ov8;
            av = A[0] + ba0; bv = Bc[0] + bB0; sg = 1.0f / (1.0f + __expf(-bv));
            ov0.x = xv0.x + av * sg;
            av = A[1] + ba0; bv = Bc[1] + bB0; sg = 1.0f / (1.0f + __expf(-bv));
            ov0.y = xv0.y + av * sg;
            av = A[2] + ba8; bv = Bc[2] + bB8; sg = 1.0f / (1.0f + __expf(-bv));
            ov8.x = xv8.x + av * sg;
            av = A[3] + ba8; bv = Bc[3] + bB8; sg = 1.0f / (1.0f + __expf(-bv));
            ov8.y = xv8.y + av * sg;

            *(float2*)(Ob + (size_t)o * Ls + l) = ov0;
            *(float2*)(Ob + (size_t)(o + 8) * Ls + l) = ov8;
        }
    }
}

// ---------------------------------------------------------------------------
extern "C" void kernel_launch(void* const* d_in, const int* in_sizes, int n_in,
                              void* d_out, int out_size)
{
    const float* x      = (const float*)d_in[0];
    const float* alpha1 = (const float*)d_in[1];
    const float* log_dt = (const float*)d_in[2];
    const float* Ar     = (const float*)d_in[3];
    const float* Ai     = (const float*)d_in[4];
    const float* Cr     = (const float*)d_in[5];
    const float* Ci     = (const float*)d_in[6];
    const float* D      = (const float*)d_in[7];
    const float* alpha2 = (const float*)d_in[8];
    const float* W      = (const float*)d_in[9];
    const float* bconv  = (const float*)d_in[10];
    float* out = (float*)d_out;

    param_kernel<<<(Hd * Nm + 255) / 256, 256>>>(log_dt, Ar, Ai, Cr, Ci);
    param2_kernel<<<Hd, 256>>>(D);
    wconv_kernel<<<(2 * Hd * Hd + 255) / 256, 256>>>(W);

    scanA_kernel<<<Hd * 4, 256>>>(x, alpha1);        // 2 chunks/warp
    scanB_kernel<<<(Hd * 128) / 256, 256>>>();       // 65536 threads
    scanC_kernel<<<Hd * 4, 256>>>(x, alpha1, alpha2);// 2 chunks/warp

    dim3 grid(Ls / 128, Hd / 64, Bsz);
    gemm_glu_kernel<<<grid, 256>>>(bconv, x, out);
}

// round 16
// speedup vs baseline: 1.7880x; 1.3047x over previous
#include <cuda_runtime.h>
#include <cuda_fp16.h>
#include <math.h>
#include <stdint.h>

// Problem constants
#define Bsz 8
#define Hd  512
#define Ls  4096
#define Nm  32
#define CL  64             // chunk length
#define NC  (Ls / CL)      // 64 chunks

// Scratch (allocation-free rule: __device__ globals)
__device__ float    g_wr[Hd * Nm];
__device__ float    g_wi[Hd * Nm];
__device__ float    g_dtar[Hd * Nm];
__device__ float    g_dtai[Hd * Nm];

__device__ uint32_t g_Ktap[Hd * CL];        // Toeplitz taps, tf32 bits, D folded into tap 0
// Fragment tables, reg-contiguous per lane: idx = (frag*32 + lane) -> uint4 of 4 regs
__device__ uint4    g_PrF4[Hd * 512];       // P  = Re(w λ^{j+1}),  A-frag (M=64,K=32), 16 frags
__device__ uint4    g_PinF4[Hd * 512];      // -Im(w λ^{j+1})
__device__ uint4    g_LrF4[Hd * 512];       // Re(λ^{63-i}),        A-frag (M=32,K=64), 16 frags
__device__ uint4    g_LiF4[Hd * 512];       // Im(λ^{63-i})
__device__ float    g_l64r[Hd * Nm];        // Re(λ^64)
__device__ float    g_l64i[Hd * Nm];

__device__ float2   g_slocR2[(size_t)Hd * NC * 128];   // chunk summaries [h][c][n*4+b2]
__device__ float2   g_slocI2[(size_t)Hd * NC * 128];
__device__ uint2    g_carR2[(size_t)Hd * NC * 128];    // incoming carries, tf32 bits
__device__ uint2    g_carI2[(size_t)Hd * NC * 128];

// W as half2, A-frag(m16n8k16) order: i = ((tile*32 + kc16)*8 + m8)*128 + lane*4 + reg
__device__ uint32_t g_Wh2[Hd * Hd];                    // 1024x512 fp16 = 262144 words
// y as fp16, channel-pair interleaved: word (b, hp, l) = {y[2hp], y[2hp+1]}
__device__ uint32_t g_y2[(size_t)Bsz * 256 * Ls];

__device__ __forceinline__ uint32_t f2tf32(float f) {
    uint32_t b;
    asm("cvt.rna.tf32.f32 %0, %1;" : "=r"(b) : "f"(f));
    return b;
}

// validated tf32 mma.sync fragment layout (R5-R14) -- used by the scan:
//  A: reg0=(g,t4) reg1=(g+8,t4) reg2=(g,t4+4) reg3=(g+8,t4+4)
//  B: reg0=B[k=t4][n=g] reg1=B[k=t4+4][n=g]
//  C: c0=(g,2t4) c1=(g,2t4+1) c2=(g+8,2t4) c3=(g+8,2t4+1)
__device__ __forceinline__ void mma_tf32(float* c,
                                         uint32_t a0, uint32_t a1, uint32_t a2, uint32_t a3,
                                         uint32_t b0, uint32_t b1)
{
    asm volatile(
        "mma.sync.aligned.m16n8k8.row.col.f32.tf32.tf32.f32 "
        "{%0,%1,%2,%3}, {%4,%5,%6,%7}, {%8,%9}, {%0,%1,%2,%3};\n"
        : "+f"(c[0]), "+f"(c[1]), "+f"(c[2]), "+f"(c[3])
        : "r"(a0), "r"(a1), "r"(a2), "r"(a3), "r"(b0), "r"(b1));
}

// fp16 m16n8k16 (standard PTX fragment layout):
//  A: a0={A[g][2t4],A[g][2t4+1]} a1={A[g+8][..]} a2={A[g][2t4+8..]} a3={A[g+8][2t4+8..]}
//  B: b0={B[2t4][g],B[2t4+1][g]} b1={B[2t4+8][g],B[2t4+9][g]}
//  C: same as tf32 path.
__device__ __forceinline__ void mma_f16(float* c,
                                        uint32_t a0, uint32_t a1, uint32_t a2, uint32_t a3,
                                        uint32_t b0, uint32_t b1)
{
    asm volatile(
        "mma.sync.aligned.m16n8k16.row.col.f32.f16.f16.f32 "
        "{%0,%1,%2,%3}, {%4,%5,%6,%7}, {%8,%9}, {%0,%1,%2,%3};\n"
        : "+f"(c[0]), "+f"(c[1]), "+f"(c[2]), "+f"(c[3])
        : "r"(a0), "r"(a1), "r"(a2), "r"(a3), "r"(b0), "r"(b1));
}

// ---------------------------------------------------------------------------
// Kernel 1: base discretization.  w = 2*C*(lambda-1)/A, dtA terms.
// ---------------------------------------------------------------------------
__global__ void param_kernel(const float* __restrict__ log_dt,
                             const float* __restrict__ Ar,
                             const float* __restrict__ Ai,
                             const float* __restrict__ Cr,
                             const float* __restrict__ Ci)
{
    int i = blockIdx.x * blockDim.x + threadIdx.x;
    if (i >= Hd * Nm) return;
    int h = i >> 5;
    float dt = expf(log_dt[h]);
    float ar = Ar[i], ai = Ai[i];
    float er = expf(dt * ar);
    float lr = er * cosf(dt * ai);
    float li = er * sinf(dt * ai);
    float nr = lr - 1.0f, ni = li;
    float inv = 1.0f / (ar * ar + ai * ai);
    float qr = (nr * ar + ni * ai) * inv;
    float qi = (ni * ar - nr * ai) * inv;
    float cr = Cr[i], ci = Ci[i];
    g_wr[i] = 2.0f * (cr * qr - ci * qi);
    g_wi[i] = 2.0f * (cr * qi + ci * qr);
    g_dtar[i] = dt * ar;
    g_dtai[i] = dt * ai;
}

// ---------------------------------------------------------------------------
// Kernel 1b: per-h frag tables (CL=64) + taps + lambda^64.  One block per h.
// ---------------------------------------------------------------------------
__global__ void param2_kernel(const float* __restrict__ Dp)
{
    int h = blockIdx.x;
    int tid = threadIdx.x;
    __shared__ float swr[32], swi[32], sar[32], sai[32];
    if (tid < 32) {
        swr[tid] = g_wr[h * 32 + tid];
        swi[tid] = g_wi[h * 32 + tid];
        sar[tid] = g_dtar[h * 32 + tid];
        sai[tid] = g_dtai[h * 32 + tid];
    }
    __syncthreads();

    // P: frag = hh*4+kcf;  q = frag*128 + lane*4 + reg
    for (int q = tid; q < 2048; q += 256) {
        int reg = q & 3, lane = (q >> 2) & 31, frag = q >> 7;
        int hh = frag >> 2, kcf = frag & 3;
        int g = lane >> 2, t4 = lane & 3;
        int row = hh * 16 + g + (reg & 1) * 8;        // j 0..63
        int col = kcf * 8 + t4 + (reg >> 1) * 4;      // n 0..31
        float p = (float)(row + 1);
        float e = expf(p * sar[col]);
        float ss, cc;
        sincosf(p * sai[col], &ss, &cc);
        float lpr = e * cc, lpi = e * ss;
        ((uint32_t*)g_PrF4)[h * 2048 + q]  = f2tf32(swr[col] * lpr - swi[col] * lpi);
        ((uint32_t*)g_PinF4)[h * 2048 + q] = f2tf32(-(swr[col] * lpi + swi[col] * lpr));
    }
    // Lambda: frag = mt*8+kc
    for (int q = tid; q < 2048; q += 256) {
        int reg = q & 3, lane = (q >> 2) & 31, frag = q >> 7;
        int mt = frag >> 3, kc = frag & 7;
        int g = lane >> 2, t4 = lane & 3;
        int row = mt * 16 + g + (reg & 1) * 8;        // n 0..31
        int col = kc * 8 + t4 + (reg >> 1) * 4;       // i 0..63
        float p = (float)(CL - 1 - col);
        float e = expf(p * sar[row]);
        float ss, cc;
        sincosf(p * sai[row], &ss, &cc);
        ((uint32_t*)g_LrF4)[h * 2048 + q] = f2tf32(e * cc);
        ((uint32_t*)g_LiF4)[h * 2048 + q] = f2tf32(e * ss);
    }
    // taps K[d] = sum_n Re(w λ^d), D folded into tap 0
    if (tid < CL) {
        int d = tid;
        float acc = 0.0f;
        for (int n = 0; n < 32; ++n) {
            float e = expf((float)d * sar[n]);
            float ss, cc;
            sincosf((float)d * sai[n], &ss, &cc);
            acc += swr[n] * (e * cc) - swi[n] * (e * ss);
        }
        if (d == 0) acc += Dp[h];
        g_Ktap[h * CL + d] = f2tf32(acc);
    }
    if (tid < 32) {
        float e = expf((float)CL * sar[tid]);
        float ss, cc;
        sincosf((float)CL * sai[tid], &ss, &cc);
        g_l64r[h * 32 + tid] = e * cc;
        g_l64i[h * 32 + tid] = e * ss;
    }
}

// ---------------------------------------------------------------------------
// Kernel 1c: W -> fp16 half2 in m16n8k16 A-fragment order.
// i = ((tile*32 + kc16)*8 + m8)*128 + lane*4 + reg   (262144 words)
//   row = tile*64 + (m8&3)*16 + g + (reg&1)*8 + (m8>>2)*512
//   k0  = kc16*16 + 2*t4 + (reg>>1)*8   (word packs k0, k0+1)
// ---------------------------------------------------------------------------
__global__ void wconv_kernel(const float* __restrict__ W)
{
    int i = blockIdx.x * blockDim.x + threadIdx.x;
    if (i >= Hd * Hd) return;
    int reg = i & 3, lane = (i >> 2) & 31, m8 = (i >> 7) & 7;
    int kc16 = (i >> 10) & 31, tile = i >> 15;
    int g = lane >> 2, t4 = lane & 3;
    int row = tile * 64 + (m8 & 3) * 16 + g + (reg & 1) * 8 + (m8 >> 2) * 512;
    int k0 = kc16 * 16 + 2 * t4 + (reg >> 1) * 8;
    __half2 v = __floats2half2_rn(W[row * Hd + k0], W[row * Hd + k0 + 1]);
    g_Wh2[i] = *(uint32_t*)&v;
}

// ---------------------------------------------------------------------------
// snake1 frag builder for a chunk PAIR (validated R12).
// ---------------------------------------------------------------------------
__device__ __forceinline__ void build_u_frags2(
    const float* __restrict__ x, float* sXw,
    int h, int c0, int lane, int g, int t4,
    float a1v, float inv1, uint32_t* uB0, uint32_t* uB1)
{
    #pragma unroll
    for (int bb = 0; bb < 8; ++bb) {
        float4 v = *(const float4*)(x + ((size_t)bb * Hd + h) * Ls + c0 * CL + lane * 4);
        *(float4*)&sXw[bb * 132 + lane * 4] = v;
    }
    __syncwarp();
    #pragma unroll
    for (int kc = 0; kc < 8; ++kc)
        #pragma unroll
        for (int r = 0; r < 2; ++r) {
            int t = kc * 8 + t4 + 4 * r;
            float xv0 = sXw[g * 132 + t];
            float sn0 = __sinf(a1v * xv0);
            uB0[kc * 2 + r] = f2tf32(fmaf(sn0 * sn0, inv1, xv0));
            float xv1 = sXw[g * 132 + 64 + t];
            float sn1 = __sinf(a1v * xv1);
            uB1[kc * 2 + r] = f2tf32(fmaf(sn1 * sn1, inv1, xv1));
        }
}

// ---------------------------------------------------------------------------
// Kernel A: per warp: TWO chunks: snake1, summaries Lam@U (validated R12).
// ---------------------------------------------------------------------------
__global__ __launch_bounds__(256)
void scanA_kernel(const float* __restrict__ x,
                  const float* __restrict__ alpha1)
{
    __shared__ uint4 sLr[512];
    __shared__ uint4 sLi[512];
    __shared__ float sX[8][8 * 132];

    const int tid  = threadIdx.x;
    const int wp   = tid >> 5;
    const int lane = tid & 31;
    const int g    = lane >> 2;
    const int t4   = lane & 3;
    const int h    = blockIdx.x >> 2;
    const int c0   = (((blockIdx.x & 3) << 3) + wp) * 2;

    #pragma unroll
    for (int i = tid; i < 512; i += 256) {
        sLr[i] = g_LrF4[h * 512 + i];
        sLi[i] = g_LiF4[h * 512 + i];
    }
    __syncthreads();

    const float a1v  = alpha1[h];
    const float inv1 = 1.0f / (a1v + 1e-9f);

    uint32_t uB0[16], uB1[16];
    build_u_frags2(x, sX[wp], h, c0, lane, g, t4, a1v, inv1, uB0, uB1);

    float AccR0[2][4] = {}, AccI0[2][4] = {};
    float AccR1[2][4] = {}, AccI1[2][4] = {};
    #pragma unroll
    for (int kc = 0; kc < 8; ++kc)
        #pragma unroll
        for (int mt = 0; mt < 2; ++mt) {
            uint4 ar = sLr[(mt * 8 + kc) * 32 + lane];
            uint4 ai = sLi[(mt * 8 + kc) * 32 + lane];
            mma_tf32(AccR0[mt], ar.x, ar.y, ar.z, ar.w, uB0[kc * 2], uB0[kc * 2 + 1]);
            mma_tf32(AccI0[mt], ai.x, ai.y, ai.z, ai.w, uB0[kc * 2], uB0[kc * 2 + 1]);
            mma_tf32(AccR1[mt], ar.x, ar.y, ar.z, ar.w, uB1[kc * 2], uB1[kc * 2 + 1]);
            mma_tf32(AccI1[mt], ai.x, ai.y, ai.z, ai.w, uB1[kc * 2], uB1[kc * 2 + 1]);
        }

    #pragma unroll
    for (int ch = 0; ch < 2; ++ch) {
        size_t sbase = (size_t)(h * NC + c0 + ch) * 128;
        float (*AR)[4] = ch ? AccR1 : AccR0;
        float (*AI)[4] = ch ? AccI1 : AccI0;
        #pragma unroll
        for (int mt = 0; mt < 2; ++mt)
            #pragma unroll
            for (int rr = 0; rr < 2; ++rr) {
                int n = mt * 16 + rr * 8 + g;
                g_slocR2[sbase + n * 4 + t4] = make_float2(AR[mt][rr * 2], AR[mt][rr * 2 + 1]);
                g_slocI2[sbase + n * 4 + t4] = make_float2(AI[mt][rr * 2], AI[mt][rr * 2 + 1]);
            }
    }
}

// ---------------------------------------------------------------------------
// Kernel B: exclusive scan of chunk carries (64-chunk chain, λ^64).
// ---------------------------------------------------------------------------
__global__ __launch_bounds__(256)
void scanB_kernel()
{
    int gid = blockIdx.x * 256 + threadIdx.x;
    int h   = gid >> 7;
    int idx = gid & 127;
    int n   = idx >> 2;

    float lr = g_l64r[h * 32 + n];
    float li = g_l64i[h * 32 + n];

    size_t base = (size_t)h * NC * 128 + idx;
    float cr0 = 0.f, ci0 = 0.f, cr1 = 0.f, ci1 = 0.f;

    #pragma unroll 1
    for (int c = 0; c < NC; ++c) {
        size_t k = base + (size_t)c * 128;
        g_carR2[k] = make_uint2(f2tf32(cr0), f2tf32(cr1));
        g_carI2[k] = make_uint2(f2tf32(ci0), f2tf32(ci1));
        float2 slr = g_slocR2[k];
        float2 sli = g_slocI2[k];
        float nr0 = fmaf(lr, cr0, fmaf(-li, ci0, slr.x));
        float ni0 = fmaf(lr, ci0, fmaf( li, cr0, sli.x));
        float nr1 = fmaf(lr, cr1, fmaf(-li, ci1, slr.y));
        float ni1 = fmaf(lr, ci1, fmaf( li, cr1, sli.y));
        cr0 = nr0; ci0 = ni0; cr1 = nr1; ci1 = ni1;
    }
}

// ---------------------------------------------------------------------------
// Kernel C: per warp: TWO chunks: recompute u, Y = T@U + Pr@S + Pin@S,
// snake2, store y as fp16 channel-pair-interleaved (validated R12 math).
// ---------------------------------------------------------------------------
__global__ __launch_bounds__(256)
void scanC_kernel(const float* __restrict__ x,
                  const float* __restrict__ alpha1,
                  const float* __restrict__ alpha2)
{
    __shared__ uint4    sPr[512];
    __shared__ uint4    sPin[512];
    __shared__ float    sX[8][8 * 132];
    __shared__ uint32_t sKt[CL];

    const int tid  = threadIdx.x;
    const int wp   = tid >> 5;
    const int lane = tid & 31;
    const int g    = lane >> 2;
    const int t4   = lane & 3;
    const int h    = blockIdx.x >> 2;
    const int c0   = (((blockIdx.x & 3) << 3) + wp) * 2;

    #pragma unroll
    for (int i = tid; i < 512; i += 256) {
        sPr[i]  = g_PrF4[h * 512 + i];
        sPin[i] = g_PinF4[h * 512 + i];
    }
    if (tid < CL) sKt[tid] = g_Ktap[h * CL + tid];
    __syncthreads();

    const float a1v  = alpha1[h];
    const float inv1 = 1.0f / (a1v + 1e-9f);

    uint32_t uB0[16], uB1[16];
    build_u_frags2(x, sX[wp], h, c0, lane, g, t4, a1v, inv1, uB0, uB1);

    const uint32_t* carR = (const uint32_t*)g_carR2 + (size_t)(h * NC + c0) * 256;
    const uint32_t* carI = (const uint32_t*)g_carI2 + (size_t)(h * NC + c0) * 256;
    uint32_t SrB0[8], SiB0[8], SrB1[8], SiB1[8];
    #pragma unroll
    for (int kc2 = 0; kc2 < 4; ++kc2)
        #pragma unroll
        for (int r = 0; r < 2; ++r) {
            int n = kc2 * 8 + t4 + 4 * r;
            SrB0[kc2 * 2 + r] = carR[n * 8 + g];
            SiB0[kc2 * 2 + r] = carI[n * 8 + g];
            SrB1[kc2 * 2 + r] = carR[256 + n * 8 + g];
            SiB1[kc2 * 2 + r] = carI[256 + n * 8 + g];
        }

    float yC0[4][4] = {}, yC1[4][4] = {};

    // Toeplitz path (taps shared between chunks): 2x20 mmas
    #pragma unroll
    for (int hh = 0; hh < 4; ++hh) {
        const int kmax = 2 * hh + 2;
        #pragma unroll
        for (int kc = 0; kc < 8; ++kc) {
            if (kc >= kmax) break;               // compile-time pruned
            int d0 = hh * 16 + g - (kc * 8 + t4);
            int d1 = d0 + 8, d2 = d0 - 4, d3 = d0 + 4;
            uint32_t a0 = (d0 >= 0) ? sKt[d0] : 0u;
            uint32_t a1 = (d1 >= 0) ? sKt[d1] : 0u;
            uint32_t a2 = (d2 >= 0) ? sKt[d2] : 0u;
            uint32_t a3 = (d3 >= 0) ? sKt[d3] : 0u;
            mma_tf32(yC0[hh], a0, a1, a2, a3, uB0[kc * 2], uB0[kc * 2 + 1]);
            mma_tf32(yC1[hh], a0, a1, a2, a3, uB1[kc * 2], uB1[kc * 2 + 1]);
        }
    }

    // carry path (P frags shared between chunks): 2x32 mmas
    #pragma unroll
    for (int hh = 0; hh < 4; ++hh)
        #pragma unroll
        for (int kc2 = 0; kc2 < 4; ++kc2) {
            uint4 pa = sPr[(hh * 4 + kc2) * 32 + lane];
            uint4 pb = sPin[(hh * 4 + kc2) * 32 + lane];
            mma_tf32(yC0[hh], pa.x, pa.y, pa.z, pa.w, SrB0[kc2 * 2], SrB0[kc2 * 2 + 1]);
            mma_tf32(yC0[hh], pb.x, pb.y, pb.z, pb.w, SiB0[kc2 * 2], SiB0[kc2 * 2 + 1]);
            mma_tf32(yC1[hh], pa.x, pa.y, pa.z, pa.w, SrB1[kc2 * 2], SrB1[kc2 * 2 + 1]);
            mma_tf32(yC1[hh], pb.x, pb.y, pb.z, pb.w, SiB1[kc2 * 2], SiB1[kc2 * 2 + 1]);
        }

    // epilogue: snake2, store fp16 halves into pair-interleaved layout
    const float a2v  = alpha2[h];
    const float inv2 = 1.0f / (a2v + 1e-9f);
    __half* yh = (__half*)g_y2;
    const size_t rowbase = ((size_t)(h >> 1)) * Ls;   // pair row within batch
    const int hpar = h & 1;
    #pragma unroll
    for (int ch = 0; ch < 2; ++ch) {
        float (*yC)[4] = ch ? yC1 : yC0;
        int cbase = (c0 + ch) * CL;
        #pragma unroll
        for (int hh = 0; hh < 4; ++hh)
            #pragma unroll
            for (int cc = 0; cc < 4; ++cc) {
                int j = hh * 16 + g + 8 * (cc >> 1);
                int b = 2 * t4 + (cc & 1);
                float yv = yC[hh][cc];
                float s2 = __sinf(a2v * yv);
                yv = fmaf(s2 * s2, inv2, yv);
                size_t widx = (size_t)b * (256 * Ls) + rowbase + cbase + j;
                yh[widx * 2 + hpar] = __float2half_rn(yv);
            }
    }
}

// ---------------------------------------------------------------------------
// Kernel 3: fused 1x1 conv GEMM (fp16 m16n8k16 mma.sync) + GLU + residual.
// BK=32 channels (= 16 Y pair-rows, 2 k16-steps), 3-stage cp.async pipeline,
// ONE barrier per chunk (16 total).  32 mmas/warp/chunk (half of tf32 path).
// ---------------------------------------------------------------------------
#define BK 32
#define SYS (128 + 8)
#define STG 3

__device__ __forceinline__ void cp_async16(uint32_t smem, const void* gmem) {
    asm volatile("cp.async.cg.shared.global [%0], [%1], 16;\n" :: "r"(smem), "l"(gmem));
}
__device__ __forceinline__ void cp_commit() {
    asm volatile("cp.async.commit_group;\n");
}
template <int N> __device__ __forceinline__ void cp_wait() {
    asm volatile("cp.async.wait_group %0;\n" :: "n"(N));
}

__global__ __launch_bounds__(256, 2)
void gemm_glu_kernel(const float* __restrict__ bias,
                     const float* __restrict__ X,
                     float* __restrict__ out)
{
    __shared__ uint4    sW4[STG][512];        // fp16 W frags: 8KB per stage
    __shared__ uint32_t sY[STG][16][SYS];     // 16 pair-rows x 128 half2 words

    const int tid = threadIdx.x;
    const int lane = tid & 31;
    const int wid = tid >> 5;
    const int wm = wid >> 2;
    const int wn = wid & 3;
    const int t4 = lane & 3;
    const int g  = lane >> 2;

    const int l0 = blockIdx.x * 128;
    const int r0 = blockIdx.y * 64;
    const int bb = blockIdx.z;

    const uint32_t* Yb = g_y2 + (size_t)bb * 256 * Ls;
    const uint32_t* Wtile = g_Wh2 + (size_t)blockIdx.y * 32768;

    const uint32_t swb = (uint32_t)__cvta_generic_to_shared(&sW4[0][0]);
    const uint32_t syb = (uint32_t)__cvta_generic_to_shared(&sY[0][0][0]);

    float acc[2][2][4][4];
    #pragma unroll
    for (int a = 0; a < 2; ++a)
        #pragma unroll
        for (int m = 0; m < 2; ++m)
            #pragma unroll
            for (int n = 0; n < 4; ++n)
                #pragma unroll
                for (int q = 0; q < 4; ++q) acc[a][m][n][q] = 0.0f;

    // per chunk: W = 2048 words (512 uint4), Y = 16x128 words (512 uint4)
    #define LOAD_CHUNK(KC, BUF) do {                                              \
        _Pragma("unroll")                                                         \
        for (int p = 0; p < 2; ++p) {                                             \
            int f4 = tid + 256 * p;                                               \
            cp_async16(swb + ((BUF) * 512 + f4) * 16,                             \
                       Wtile + (KC) * 2048 + f4 * 4);                             \
            int row = f4 >> 5, col = (f4 & 31) << 2;                              \
            cp_async16(syb + (((BUF) * 16 + row) * SYS + col) * 4,                \
                       Yb + (size_t)((KC) * 16 + row) * Ls + l0 + col);           \
        }                                                                         \
    } while (0)

    LOAD_CHUNK(0, 0); cp_commit();
    LOAD_CHUNK(1, 1); cp_commit();

    const int NCH = Hd / BK;   // 16
    #pragma unroll 1
    for (int kc = 0; kc < NCH; ++kc) {
        if (kc < NCH - 1) cp_wait<1>(); else cp_wait<0>();
        __syncthreads();
        if (kc + 2 < NCH) { LOAD_CHUNK(kc + 2, (kc + 2) % STG); cp_commit(); }
        int buf = kc % STG;

        #pragma unroll
        for (int ks = 0; ks < 2; ++ks) {       // two k16 steps per chunk
            uint32_t B0[4], B1[4];
            #pragma unroll
            for (int ni = 0; ni < 4; ++ni) {
                int col = wn * 32 + ni * 8 + g;
                B0[ni] = sY[buf][ks * 8 + t4][col];
                B1[ni] = sY[buf][ks * 8 + t4 + 4][col];
            }
            #pragma unroll
            for (int half = 0; half < 2; ++half) {
                #pragma unroll
                for (int mi = 0; mi < 2; ++mi) {
                    uint4 av = sW4[buf][(ks * 8 + half * 4 + wm * 2 + mi) * 32 + lane];
                    #pragma unroll
                    for (int ni = 0; ni < 4; ++ni)
                        mma_f16(acc[half][mi][ni], av.x, av.y, av.z, av.w,
                                B0[ni], B1[ni]);
                }
            }
        }
    }
    #undef LOAD_CHUNK

    const float* Xb = X   + (size_t)bb * Hd * Ls;
    float*       Ob = out + (size_t)bb * Hd * Ls;

    #pragma unroll
    for (int mi = 0; mi < 2; ++mi) {
        int o = r0 + wm * 32 + mi * 16 + g;
        float ba0 = bias[o];
        float bB0 = bias[o + 512];
        float ba8 = bias[o + 8];
        float bB8 = bias[o + 520];
        #pragma unroll
        for (int ni = 0; ni < 4; ++ni) {
            int l = l0 + wn * 32 + ni * 8 + 2 * t4;
            const float* A = acc[0][mi][ni];
            const float* Bc = acc[1][mi][ni];

            float2 xv0 = *(const float2*)(Xb + (size_t)o * Ls + l);
            float2 xv8 = *(const float2*)(Xb + (size_t)(o + 8) * Ls + l);

            float av, bv, sg;
            float2 ov0, ov8;
            av = A[0] + ba0; bv = Bc[0] + bB0; sg = 1.0f / (1.0f + __expf(-bv));
            ov0.x = xv0.x + av * sg;
            av = A[1] + ba0; bv = Bc[1] + bB0; sg = 1.0f / (1.0f + __expf(-bv));
            ov0.y = xv0.y + av * sg;
            av = A[2] + ba8; bv = Bc[2] + bB8; sg = 1.0f / (1.0f + __expf(-bv));
            ov8.x = xv8.x + av * sg;
            av = A[3] + ba8; bv = Bc[3] + bB8; sg = 1.0f / (1.0f + __expf(-bv));
            ov8.y = xv8.y + av * sg;

            *(float2*)(Ob + (size_t)o * Ls + l) = ov0;
            *(float2*)(Ob + (size_t)(o + 8) * Ls + l) = ov8;
        }
    }
}

// ---------------------------------------------------------------------------
extern "C" void kernel_launch(void* const* d_in, const int* in_sizes, int n_in,
                              void* d_out, int out_size)
{
    const float* x      = (const float*)d_in[0];
    const float* alpha1 = (const float*)d_in[1];
    const float* log_dt = (const float*)d_in[2];
    const float* Ar     = (const float*)d_in[3];
    const float* Ai     = (const float*)d_in[4];
    const float* Cr     = (const float*)d_in[5];
    const float* Ci     = (const float*)d_in[6];
    const float* D      = (const float*)d_in[7];
    const float* alpha2 = (const float*)d_in[8];
    const float* W      = (const float*)d_in[9];
    const float* bconv  = (const float*)d_in[10];
    float* out = (float*)d_out;

    param_kernel<<<(Hd * Nm + 255) / 256, 256>>>(log_dt, Ar, Ai, Cr, Ci);
    param2_kernel<<<Hd, 256>>>(D);
    wconv_kernel<<<(Hd * Hd + 255) / 256, 256>>>(W);

    scanA_kernel<<<Hd * 4, 256>>>(x, alpha1);        // 2 chunks/warp
    scanB_kernel<<<(Hd * 128) / 256, 256>>>();       // 65536 threads
    scanC_kernel<<<Hd * 4, 256>>>(x, alpha1, alpha2);// 2 chunks/warp

    dim3 grid(Ls / 128, Hd / 64, Bsz);
    gemm_glu_kernel<<<grid, 256>>>(bconv, x, out);
}

// round 17
// speedup vs baseline: 1.8648x; 1.0430x over previous
#include <cuda_runtime.h>
#include <cuda_fp16.h>
#include <math.h>
#include <stdint.h>

// Problem constants
#define Bsz 8
#define Hd  512
#define Ls  4096
#define Nm  32
#define CL  64             // chunk length
#define NC  (Ls / CL)      // 64 chunks

// Scratch (allocation-free rule: __device__ globals)
__device__ float    g_wr[Hd * Nm];
__device__ float    g_wi[Hd * Nm];
__device__ float    g_dtar[Hd * Nm];
__device__ float    g_dtai[Hd * Nm];

// scanA tables (tf32, validated R11-R16)
__device__ uint4    g_LrF4[Hd * 512];       // Re(λ^{63-i}), A-frag (M=32,K=64), 16 frags
__device__ uint4    g_LiF4[Hd * 512];       // Im(λ^{63-i})
__device__ float    g_l64r[Hd * Nm];        // Re(λ^64)
__device__ float    g_l64i[Hd * Nm];

// scanC fp16 tables (m16n8k16 A-frag order, validated by R16 GEMM layout)
__device__ uint4    g_TH[Hd * 320];         // Toeplitz frags: 10 frags x 32 lanes (half2 pairs)
__device__ uint4    g_PrH[Hd * 256];        // Re(w λ^{j+1}):  8 frags (4 hh x 2 kc16)
__device__ uint4    g_PinH[Hd * 256];       // -Im(w λ^{j+1})

__device__ float2   g_slocR2[(size_t)Hd * NC * 128];   // chunk summaries [h][c][n*4+b2]
__device__ float2   g_slocI2[(size_t)Hd * NC * 128];
// carries as fp16 pairs {S[2n2][b], S[2n2+1][b]}: word [h][c][n2*8+b]
__device__ uint32_t g_carHR[(size_t)Hd * NC * 128];
__device__ uint32_t g_carHI[(size_t)Hd * NC * 128];

// W as half2, A-frag(m16n8k16) order (validated R16)
__device__ uint32_t g_Wh2[Hd * Hd];
// y as fp16, channel-pair interleaved: word (b, hp, l) = {y[2hp], y[2hp+1]}
__device__ uint32_t g_y2[(size_t)Bsz * 256 * Ls];

__device__ __forceinline__ uint32_t f2tf32(float f) {
    uint32_t b;
    asm("cvt.rna.tf32.f32 %0, %1;" : "=r"(b) : "f"(f));
    return b;
}
__device__ __forceinline__ uint32_t packh2(float lo, float hi) {
    __half2 v = __floats2half2_rn(lo, hi);
    return *(uint32_t*)&v;
}

// tf32 m16n8k8 (scan A path, validated R5-R16)
__device__ __forceinline__ void mma_tf32(float* c,
                                         uint32_t a0, uint32_t a1, uint32_t a2, uint32_t a3,
                                         uint32_t b0, uint32_t b1)
{
    asm volatile(
        "mma.sync.aligned.m16n8k8.row.col.f32.tf32.tf32.f32 "
        "{%0,%1,%2,%3}, {%4,%5,%6,%7}, {%8,%9}, {%0,%1,%2,%3};\n"
        : "+f"(c[0]), "+f"(c[1]), "+f"(c[2]), "+f"(c[3])
        : "r"(a0), "r"(a1), "r"(a2), "r"(a3), "r"(b0), "r"(b1));
}

// fp16 m16n8k16 (validated R16):
//  A: a0={A[g][2t4],A[g][2t4+1]} a1={A[g+8][..]} a2={A[g][2t4+8..]} a3={A[g+8][2t4+8..]}
//  B: b0={B[2t4][col],B[2t4+1][col]} b1={B[2t4+8][col],B[2t4+9][col]}, col=g
//  C: c0=(g,2t4) c1=(g,2t4+1) c2=(g+8,2t4) c3=(g+8,2t4+1)
__device__ __forceinline__ void mma_f16(float* c,
                                        uint32_t a0, uint32_t a1, uint32_t a2, uint32_t a3,
                                        uint32_t b0, uint32_t b1)
{
    asm volatile(
        "mma.sync.aligned.m16n8k16.row.col.f32.f16.f16.f32 "
        "{%0,%1,%2,%3}, {%4,%5,%6,%7}, {%8,%9}, {%0,%1,%2,%3};\n"
        : "+f"(c[0]), "+f"(c[1]), "+f"(c[2]), "+f"(c[3])
        : "r"(a0), "r"(a1), "r"(a2), "r"(a3), "r"(b0), "r"(b1));
}

// ---------------------------------------------------------------------------
// Kernel 1: base discretization.  w = 2*C*(lambda-1)/A, dtA terms.
// ---------------------------------------------------------------------------
__global__ void param_kernel(const float* __restrict__ log_dt,
                             const float* __restrict__ Ar,
                             const float* __restrict__ Ai,
                             const float* __restrict__ Cr,
                             const float* __restrict__ Ci)
{
    int i = blockIdx.x * blockDim.x + threadIdx.x;
    if (i >= Hd * Nm) return;
    int h = i >> 5;
    float dt = expf(log_dt[h]);
    float ar = Ar[i], ai = Ai[i];
    float er = expf(dt * ar);
    float lr = er * cosf(dt * ai);
    float li = er * sinf(dt * ai);
    float nr = lr - 1.0f, ni = li;
    float inv = 1.0f / (ar * ar + ai * ai);
    float qr = (nr * ar + ni * ai) * inv;
    float qi = (ni * ar - nr * ai) * inv;
    float cr = Cr[i], ci = Ci[i];
    g_wr[i] = 2.0f * (cr * qr - ci * qi);
    g_wi[i] = 2.0f * (cr * qi + ci * qr);
    g_dtar[i] = dt * ar;
    g_dtai[i] = dt * ai;
}

// ---------------------------------------------------------------------------
// Kernel 1b: per-h tables.  Lambda (tf32, scanA); T / P frag tables (fp16,
// scanC, m16n8k16 A-frag order); lambda^64.  One block (256 thr) per h.
// ---------------------------------------------------------------------------
__global__ void param2_kernel(const float* __restrict__ Dp)
{
    int h = blockIdx.x;
    int tid = threadIdx.x;
    __shared__ float swr[32], swi[32], sar[32], sai[32];
    __shared__ float sK[64];
    if (tid < 32) {
        swr[tid] = g_wr[h * 32 + tid];
        swi[tid] = g_wi[h * 32 + tid];
        sar[tid] = g_dtar[h * 32 + tid];
        sai[tid] = g_dtai[h * 32 + tid];
    }
    __syncthreads();

    // taps K[d] = sum_n Re(w λ^d), D folded into tap 0
    if (tid < CL) {
        int d = tid;
        float acc = 0.0f;
        for (int n = 0; n < 32; ++n) {
            float e = expf((float)d * sar[n]);
            float ss, cc;
            sincosf((float)d * sai[n], &ss, &cc);
            acc += swr[n] * (e * cc) - swi[n] * (e * ss);
        }
        if (d == 0) acc += Dp[h];
        sK[d] = acc;
    }
    __syncthreads();

    // P fp16 frags: frag = hh*2 + kc16;  q = frag*128 + lane*4 + reg
    for (int q = tid; q < 1024; q += 256) {
        int reg = q & 3, lane = (q >> 2) & 31, frag = q >> 7;
        int hh = frag >> 1, kc16 = frag & 1;
        int g = lane >> 2, t4 = lane & 3;
        int j  = hh * 16 + g + (reg & 1) * 8;          // time row 0..63
        int n0 = kc16 * 16 + 2 * t4 + (reg >> 1) * 8;  // mode 0..31 (pair n0,n0+1)
        float p = (float)(j + 1);
        float prv[2], piv[2];
        #pragma unroll
        for (int s = 0; s < 2; ++s) {
            int n = n0 + s;
            float e = expf(p * sar[n]);
            float ss, cc;
            sincosf(p * sai[n], &ss, &cc);
            float lpr = e * cc, lpi = e * ss;
            prv[s] = swr[n] * lpr - swi[n] * lpi;
            piv[s] = -(swr[n] * lpi + swi[n] * lpr);
        }
        ((uint32_t*)g_PrH)[h * 1024 + q]  = packh2(prv[0], prv[1]);
        ((uint32_t*)g_PinH)[h * 1024 + q] = packh2(piv[0], piv[1]);
    }

    // Toeplitz fp16 frags: 10 lower-tri blocks (hh,kc16), kc16 <= hh
    {
        const int fh[10] = {0,1,1,2,2,2,3,3,3,3};
        const int fk[10] = {0,0,1,0,1,2,0,1,2,3};
        for (int q = tid; q < 1280; q += 256) {
            int reg = q & 3, lane = (q >> 2) & 31, f = q >> 7;
            int g = lane >> 2, t4 = lane & 3;
            int j  = fh[f] * 16 + g + (reg & 1) * 8;
            int i0 = fk[f] * 16 + 2 * t4 + (reg >> 1) * 8;
            int d0 = j - i0, d1 = j - i0 - 1;
            float lo = (d0 >= 0) ? sK[d0] : 0.0f;
            float hi = (d1 >= 0) ? sK[d1] : 0.0f;
            ((uint32_t*)g_TH)[h * 1280 + q] = packh2(lo, hi);
        }
    }

    // Lambda tf32 (scanA, unchanged): frag = mt*8+kc
    for (int q = tid; q < 2048; q += 256) {
        int reg = q & 3, lane = (q >> 2) & 31, frag = q >> 7;
        int mt = frag >> 3, kc = frag & 7;
        int g = lane >> 2, t4 = lane & 3;
        int row = mt * 16 + g + (reg & 1) * 8;        // n 0..31
        int col = kc * 8 + t4 + (reg >> 1) * 4;       // i 0..63
        float p = (float)(CL - 1 - col);
        float e = expf(p * sar[row]);
        float ss, cc;
        sincosf(p * sai[row], &ss, &cc);
        ((uint32_t*)g_LrF4)[h * 2048 + q] = f2tf32(e * cc);
        ((uint32_t*)g_LiF4)[h * 2048 + q] = f2tf32(e * ss);
    }
    if (tid < 32) {
        float e = expf((float)CL * sar[tid]);
        float ss, cc;
        sincosf((float)CL * sai[tid], &ss, &cc);
        g_l64r[h * 32 + tid] = e * cc;
        g_l64i[h * 32 + tid] = e * ss;
    }
}

// ---------------------------------------------------------------------------
// Kernel 1c: W -> fp16 half2 in m16n8k16 A-fragment order (validated R16).
// ---------------------------------------------------------------------------
__global__ void wconv_kernel(const float* __restrict__ W)
{
    int i = blockIdx.x * blockDim.x + threadIdx.x;
    if (i >= Hd * Hd) return;
    int reg = i & 3, lane = (i >> 2) & 31, m8 = (i >> 7) & 7;
    int kc16 = (i >> 10) & 31, tile = i >> 15;
    int g = lane >> 2, t4 = lane & 3;
    int row = tile * 64 + (m8 & 3) * 16 + g + (reg & 1) * 8 + (m8 >> 2) * 512;
    int k0 = kc16 * 16 + 2 * t4 + (reg >> 1) * 8;
    g_Wh2[i] = packh2(W[row * Hd + k0], W[row * Hd + k0 + 1]);
}

// ---------------------------------------------------------------------------
// snake1 tf32 frag builder for a chunk PAIR (scanA, validated R12-R16).
// ---------------------------------------------------------------------------
__device__ __forceinline__ void build_u_frags2(
    const float* __restrict__ x, float* sXw,
    int h, int c0, int lane, int g, int t4,
    float a1v, float inv1, uint32_t* uB0, uint32_t* uB1)
{
    #pragma unroll
    for (int bb = 0; bb < 8; ++bb) {
        float4 v = *(const float4*)(x + ((size_t)bb * Hd + h) * Ls + c0 * CL + lane * 4);
        *(float4*)&sXw[bb * 132 + lane * 4] = v;
    }
    __syncwarp();
    #pragma unroll
    for (int kc = 0; kc < 8; ++kc)
        #pragma unroll
        for (int r = 0; r < 2; ++r) {
            int t = kc * 8 + t4 + 4 * r;
            float xv0 = sXw[g * 132 + t];
            float sn0 = __sinf(a1v * xv0);
            uB0[kc * 2 + r] = f2tf32(fmaf(sn0 * sn0, inv1, xv0));
            float xv1 = sXw[g * 132 + 64 + t];
            float sn1 = __sinf(a1v * xv1);
            uB1[kc * 2 + r] = f2tf32(fmaf(sn1 * sn1, inv1, xv1));
        }
}

// ---------------------------------------------------------------------------
// Kernel A: per warp: TWO chunks: snake1, summaries Lam@U (byte-identical R16).
// ---------------------------------------------------------------------------
__global__ __launch_bounds__(256)
void scanA_kernel(const float* __restrict__ x,
                  const float* __restrict__ alpha1)
{
    __shared__ uint4 sLr[512];
    __shared__ uint4 sLi[512];
    __shared__ float sX[8][8 * 132];

    const int tid  = threadIdx.x;
    const int wp   = tid >> 5;
    const int lane = tid & 31;
    const int g    = lane >> 2;
    const int t4   = lane & 3;
    const int h    = blockIdx.x >> 2;
    const int c0   = (((blockIdx.x & 3) << 3) + wp) * 2;

    #pragma unroll
    for (int i = tid; i < 512; i += 256) {
        sLr[i] = g_LrF4[h * 512 + i];
        sLi[i] = g_LiF4[h * 512 + i];
    }
    __syncthreads();

    const float a1v  = alpha1[h];
    const float inv1 = 1.0f / (a1v + 1e-9f);

    uint32_t uB0[16], uB1[16];
    build_u_frags2(x, sX[wp], h, c0, lane, g, t4, a1v, inv1, uB0, uB1);

    float AccR0[2][4] = {}, AccI0[2][4] = {};
    float AccR1[2][4] = {}, AccI1[2][4] = {};
    #pragma unroll
    for (int kc = 0; kc < 8; ++kc)
        #pragma unroll
        for (int mt = 0; mt < 2; ++mt) {
            uint4 ar = sLr[(mt * 8 + kc) * 32 + lane];
            uint4 ai = sLi[(mt * 8 + kc) * 32 + lane];
            mma_tf32(AccR0[mt], ar.x, ar.y, ar.z, ar.w, uB0[kc * 2], uB0[kc * 2 + 1]);
            mma_tf32(AccI0[mt], ai.x, ai.y, ai.z, ai.w, uB0[kc * 2], uB0[kc * 2 + 1]);
            mma_tf32(AccR1[mt], ar.x, ar.y, ar.z, ar.w, uB1[kc * 2], uB1[kc * 2 + 1]);
            mma_tf32(AccI1[mt], ai.x, ai.y, ai.z, ai.w, uB1[kc * 2], uB1[kc * 2 + 1]);
        }

    #pragma unroll
    for (int ch = 0; ch < 2; ++ch) {
        size_t sbase = (size_t)(h * NC + c0 + ch) * 128;
        float (*AR)[4] = ch ? AccR1 : AccR0;
        float (*AI)[4] = ch ? AccI1 : AccI0;
        #pragma unroll
        for (int mt = 0; mt < 2; ++mt)
            #pragma unroll
            for (int rr = 0; rr < 2; ++rr) {
                int n = mt * 16 + rr * 8 + g;
                g_slocR2[sbase + n * 4 + t4] = make_float2(AR[mt][rr * 2], AR[mt][rr * 2 + 1]);
                g_slocI2[sbase + n * 4 + t4] = make_float2(AI[mt][rr * 2], AI[mt][rr * 2 + 1]);
            }
    }
}

// ---------------------------------------------------------------------------
// Kernel B: exclusive scan of chunk carries.  Thread = (h, n-pair, b).
// fp32 chain (accuracy), emits fp16 pair words {S[2n2][b], S[2n2+1][b]}
// = exactly scanC's B-fragment content.
// ---------------------------------------------------------------------------
__global__ __launch_bounds__(256)
void scanB_kernel()
{
    int gid = blockIdx.x * 256 + threadIdx.x;     // 0..65535
    int h   = gid >> 7;
    int idx = gid & 127;                          // n2*8 + b
    int n2  = idx >> 3;
    int b   = idx & 7;

    float lr0 = g_l64r[h * 32 + 2 * n2],     li0 = g_l64i[h * 32 + 2 * n2];
    float lr1 = g_l64r[h * 32 + 2 * n2 + 1], li1 = g_l64i[h * 32 + 2 * n2 + 1];

    const float* slR = (const float*)g_slocR2 + (size_t)h * NC * 256;
    const float* slI = (const float*)g_slocI2 + (size_t)h * NC * 256;
    size_t cbase = (size_t)h * NC * 128 + idx;

    // float index of S[n][b] within a chunk slab: 8n + b
    int i0 = 16 * n2 + b;        // even mode
    int i1 = 16 * n2 + 8 + b;    // odd mode

    float r0 = 0.f, q0 = 0.f, r1 = 0.f, q1 = 0.f;   // (re,im) even / odd

    #pragma unroll 1
    for (int c = 0; c < NC; ++c) {
        g_carHR[cbase + (size_t)c * 128] = packh2(r0, r1);
        g_carHI[cbase + (size_t)c * 128] = packh2(q0, q1);
        const float* sR = slR + (size_t)c * 256;
        const float* sI = slI + (size_t)c * 256;
        float nr0 = fmaf(lr0, r0, fmaf(-li0, q0, sR[i0]));
        float nq0 = fmaf(lr0, q0, fmaf( li0, r0, sI[i0]));
        float nr1 = fmaf(lr1, r1, fmaf(-li1, q1, sR[i1]));
        float nq1 = fmaf(lr1, q1, fmaf( li1, r1, sI[i1]));
        r0 = nr0; q0 = nq0; r1 = nr1; q1 = nq1;
    }
}

// ---------------------------------------------------------------------------
// Kernel C: per warp: TWO chunks: recompute u (fp16 pairs),
// Y = T@U + Pr@S + Pin@S via m16n8k16, snake2.  26 mmas/chunk (was 52).
// ---------------------------------------------------------------------------
__global__ __launch_bounds__(256)
void scanC_kernel(const float* __restrict__ x,
                  const float* __restrict__ alpha1,
                  const float* __restrict__ alpha2)
{
    __shared__ uint4 sT[320];
    __shared__ uint4 sPr[256];
    __shared__ uint4 sPin[256];
    __shared__ float sX[8][8 * 132];

    const int tid  = threadIdx.x;
    const int wp   = tid >> 5;
    const int lane = tid & 31;
    const int g    = lane >> 2;
    const int t4   = lane & 3;
    const int h    = blockIdx.x >> 2;
    const int c0   = (((blockIdx.x & 3) << 3) + wp) * 2;

    #pragma unroll
    for (int i = tid; i < 320; i += 256) sT[i] = g_TH[h * 320 + i];
    if (tid < 256) {
        sPr[tid]  = g_PrH[h * 256 + tid];
        sPin[tid] = g_PinH[h * 256 + tid];
    }
    __syncthreads();

    const float a1v  = alpha1[h];
    const float inv1 = 1.0f / (a1v + 1e-9f);

    // stage x pair (coalesced) + build u fp16 B-frags (time pairs)
    float* sXw = sX[wp];
    #pragma unroll
    for (int bb = 0; bb < 8; ++bb) {
        float4 v = *(const float4*)(x + ((size_t)bb * Hd + h) * Ls + c0 * CL + lane * 4);
        *(float4*)&sXw[bb * 132 + lane * 4] = v;
    }
    __syncwarp();

    uint32_t uH0[8], uH1[8];
    #pragma unroll
    for (int kc16 = 0; kc16 < 4; ++kc16)
        #pragma unroll
        for (int r = 0; r < 2; ++r) {
            int t = kc16 * 16 + 2 * t4 + 8 * r;
            float xa = sXw[g * 132 + t];
            float xb = sXw[g * 132 + t + 1];
            float sa = __sinf(a1v * xa);
            float sb = __sinf(a1v * xb);
            uH0[kc16 * 2 + r] = packh2(fmaf(sa * sa, inv1, xa), fmaf(sb * sb, inv1, xb));
            float xc = sXw[g * 132 + 64 + t];
            float xd = sXw[g * 132 + 64 + t + 1];
            float sc = __sinf(a1v * xc);
            float sd = __sinf(a1v * xd);
            uH1[kc16 * 2 + r] = packh2(fmaf(sc * sc, inv1, xc), fmaf(sd * sd, inv1, xd));
        }

    // carry B-frags (fp16 pair words written by scanB)
    const uint32_t* carR = g_carHR + (size_t)(h * NC + c0) * 128;
    const uint32_t* carI = g_carHI + (size_t)(h * NC + c0) * 128;
    uint32_t SrB0[4], SiB0[4], SrB1[4], SiB1[4];
    #pragma unroll
    for (int kc16 = 0; kc16 < 2; ++kc16)
        #pragma unroll
        for (int r = 0; r < 2; ++r) {
            int w = (kc16 * 8 + t4 + 4 * r) * 8 + g;
            SrB0[kc16 * 2 + r] = carR[w];
            SiB0[kc16 * 2 + r] = carI[w];
            SrB1[kc16 * 2 + r] = carR[128 + w];
            SiB1[kc16 * 2 + r] = carI[128 + w];
        }

    float yC0[4][4] = {}, yC1[4][4] = {};

    // Toeplitz path: 10 lower-tri frags, shared between chunks
    {
        int fi = 0;
        #pragma unroll
        for (int hh = 0; hh < 4; ++hh)
            #pragma unroll
            for (int kc16 = 0; kc16 < 4; ++kc16) {
                if (kc16 > hh) break;            // compile-time pruned
                uint4 a = sT[fi * 32 + lane];
                ++fi;
                mma_f16(yC0[hh], a.x, a.y, a.z, a.w, uH0[kc16 * 2], uH0[kc16 * 2 + 1]);
                mma_f16(yC1[hh], a.x, a.y, a.z, a.w, uH1[kc16 * 2], uH1[kc16 * 2 + 1]);
            }
    }

    // carry path: 16 mmas/chunk
    #pragma unroll
    for (int hh = 0; hh < 4; ++hh)
        #pragma unroll
        for (int kc16 = 0; kc16 < 2; ++kc16) {
            uint4 pa = sPr[(hh * 2 + kc16) * 32 + lane];
            uint4 pb = sPin[(hh * 2 + kc16) * 32 + lane];
            mma_f16(yC0[hh], pa.x, pa.y, pa.z, pa.w, SrB0[kc16 * 2], SrB0[kc16 * 2 + 1]);
            mma_f16(yC0[hh], pb.x, pb.y, pb.z, pb.w, SiB0[kc16 * 2], SiB0[kc16 * 2 + 1]);
            mma_f16(yC1[hh], pa.x, pa.y, pa.z, pa.w, SrB1[kc16 * 2], SrB1[kc16 * 2 + 1]);
            mma_f16(yC1[hh], pb.x, pb.y, pb.z, pb.w, SiB1[kc16 * 2], SiB1[kc16 * 2 + 1]);
        }

    // epilogue: snake2, store fp16 halves into pair-interleaved layout (R16)
    const float a2v  = alpha2[h];
    const float inv2 = 1.0f / (a2v + 1e-9f);
    __half* yh = (__half*)g_y2;
    const size_t rowbase = ((size_t)(h >> 1)) * Ls;
    const int hpar = h & 1;
    #pragma unroll
    for (int ch = 0; ch < 2; ++ch) {
        float (*yC)[4] = ch ? yC1 : yC0;
        int cbase = (c0 + ch) * CL;
        #pragma unroll
        for (int hh = 0; hh < 4; ++hh)
            #pragma unroll
            for (int cc = 0; cc < 4; ++cc) {
                int j = hh * 16 + g + 8 * (cc >> 1);
                int b = 2 * t4 + (cc & 1);
                float yv = yC[hh][cc];
                float s2 = __sinf(a2v * yv);
                yv = fmaf(s2 * s2, inv2, yv);
                size_t widx = (size_t)b * (256 * Ls) + rowbase + cbase + j;
                yh[widx * 2 + hpar] = __float2half_rn(yv);
            }
    }
}

// ---------------------------------------------------------------------------
// Kernel 3: fused 1x1 conv GEMM (fp16 m16n8k16) + GLU + residual
// (byte-identical to validated R16 version).
// ---------------------------------------------------------------------------
#define BK 32
#define SYS (128 + 8)
#define STG 3

__device__ __forceinline__ void cp_async16(uint32_t smem, const void* gmem) {
    asm volatile("cp.async.cg.shared.global [%0], [%1], 16;\n" :: "r"(smem), "l"(gmem));
}
__device__ __forceinline__ void cp_commit() {
    asm volatile("cp.async.commit_group;\n");
}
template <int N> __device__ __forceinline__ void cp_wait() {
    asm volatile("cp.async.wait_group %0;\n" :: "n"(N));
}

__global__ __launch_bounds__(256, 2)
void gemm_glu_kernel(const float* __restrict__ bias,
                     const float* __restrict__ X,
                     float* __restrict__ out)
{
    __shared__ uint4    sW4[STG][512];
    __shared__ uint32_t sY[STG][16][SYS];

    const int tid = threadIdx.x;
    const int lane = tid & 31;
    const int wid = tid >> 5;
    const int wm = wid >> 2;
    const int wn = wid & 3;
    const int t4 = lane & 3;
    const int g  = lane >> 2;

    const int l0 = blockIdx.x * 128;
    const int r0 = blockIdx.y * 64;
    const int bb = blockIdx.z;

    const uint32_t* Yb = g_y2 + (size_t)bb * 256 * Ls;
    const uint32_t* Wtile = g_Wh2 + (size_t)blockIdx.y * 32768;

    const uint32_t swb = (uint32_t)__cvta_generic_to_shared(&sW4[0][0]);
    const uint32_t syb = (uint32_t)__cvta_generic_to_shared(&sY[0][0][0]);

    float acc[2][2][4][4];
    #pragma unroll
    for (int a = 0; a < 2; ++a)
        #pragma unroll
        for (int m = 0; m < 2; ++m)
            #pragma unroll
            for (int n = 0; n < 4; ++n)
                #pragma unroll
                for (int q = 0; q < 4; ++q) acc[a][m][n][q] = 0.0f;

    #define LOAD_CHUNK(KC, BUF) do {                                              \
        _Pragma("unroll")                                                         \
        for (int p = 0; p < 2; ++p) {                                             \
            int f4 = tid + 256 * p;                                               \
            cp_async16(swb + ((BUF) * 512 + f4) * 16,                             \
                       Wtile + (KC) * 2048 + f4 * 4);                             \
            int row = f4 >> 5, col = (f4 & 31) << 2;                              \
            cp_async16(syb + (((BUF) * 16 + row) * SYS + col) * 4,                \
                       Yb + (size_t)((KC) * 16 + row) * Ls + l0 + col);           \
        }                                                                         \
    } while (0)

    LOAD_CHUNK(0, 0); cp_commit();
    LOAD_CHUNK(1, 1); cp_commit();

    const int NCH = Hd / BK;   // 16
    #pragma unroll 1
    for (int kc = 0; kc < NCH; ++kc) {
        if (kc < NCH - 1) cp_wait<1>(); else cp_wait<0>();
        __syncthreads();
        if (kc + 2 < NCH) { LOAD_CHUNK(kc + 2, (kc + 2) % STG); cp_commit(); }
        int buf = kc % STG;

        #pragma unroll
        for (int ks = 0; ks < 2; ++ks) {
            uint32_t B0[4], B1[4];
            #pragma unroll
            for (int ni = 0; ni < 4; ++ni) {
                int col = wn * 32 + ni * 8 + g;
                B0[ni] = sY[buf][ks * 8 + t4][col];
                B1[ni] = sY[buf][ks * 8 + t4 + 4][col];
            }
            #pragma unroll
            for (int half = 0; half < 2; ++half) {
                #pragma unroll
                for (int mi = 0; mi < 2; ++mi) {
                    uint4 av = sW4[buf][(ks * 8 + half * 4 + wm * 2 + mi) * 32 + lane];
                    #pragma unroll
                    for (int ni = 0; ni < 4; ++ni)
                        mma_f16(acc[half][mi][ni], av.x, av.y, av.z, av.w,
                                B0[ni], B1[ni]);
                }
            }
        }
    }
    #undef LOAD_CHUNK

    const float* Xb = X   + (size_t)bb * Hd * Ls;
    float*       Ob = out + (size_t)bb * Hd * Ls;

    #pragma unroll
    for (int mi = 0; mi < 2; ++mi) {
        int o = r0 + wm * 32 + mi * 16 + g;
        float ba0 = bias[o];
        float bB0 = bias[o + 512];
        float ba8 = bias[o + 8];
        float bB8 = bias[o + 520];
        #pragma unroll
        for (int ni = 0; ni < 4; ++ni) {
            int l = l0 + wn * 32 + ni * 8 + 2 * t4;
            const float* A = acc[0][mi][ni];
            const float* Bc = acc[1][mi][ni];

            float2 xv0 = *(const float2*)(Xb + (size_t)o * Ls + l);
            float2 xv8 = *(const float2*)(Xb + (size_t)(o + 8) * Ls + l);

            float av, bv, sg;
            float2 ov0, ov8;
            av = A[0] + ba0; bv = Bc[0] + bB0; sg = 1.0f / (1.0f + __expf(-bv));
            ov0.x = xv0.x + av * sg;
            av = A[1] + ba0; bv = Bc[1] + bB0; sg = 1.0f / (1.0f + __expf(-bv));
            ov0.y = xv0.y + av * sg;
            av = A[2] + ba8; bv = Bc[2] + bB8; sg = 1.0f / (1.0f + __expf(-bv));
            ov8.x = xv8.x + av * sg;
            av = A[3] + ba8; bv = Bc[3] + bB8; sg = 1.0f / (1.0f + __expf(-bv));
            ov8.y = xv8.y + av * sg;

            *(float2*)(Ob + (size_t)o * Ls + l) = ov0;
            *(float2*)(Ob + (size_t)(o + 8) * Ls + l) = ov8;
        }
    }
}

// ---------------------------------------------------------------------------
extern "C" void kernel_launch(void* const* d_in, const int* in_sizes, int n_in,
                              void* d_out, int out_size)
{
    const float* x      = (const float*)d_in[0];
    const float* alpha1 = (const float*)d_in[1];
    const float* log_dt = (const float*)d_in[2];
    const float* Ar     = (const float*)d_in[3];
    const float* Ai     = (const float*)d_in[4];
    const float* Cr     = (const float*)d_in[5];
    const float* Ci     = (const float*)d_in[6];
    const float* D      = (const float*)d_in[7];
    const float* alpha2 = (const float*)d_in[8];
    const float* W      = (const float*)d_in[9];
    const float* bconv  = (const float*)d_in[10];
    float* out = (float*)d_out;

    param_kernel<<<(Hd * Nm + 255) / 256, 256>>>(log_dt, Ar, Ai, Cr, Ci);
    param2_kernel<<<Hd, 256>>>(D);
    wconv_kernel<<<(Hd * Hd + 255) / 256, 256>>>(W);

    scanA_kernel<<<Hd * 4, 256>>>(x, alpha1);        // 2 chunks/warp (tf32)
    scanB_kernel<<<(Hd * 128) / 256, 256>>>();       // fp32 chain -> fp16 carries
    scanC_kernel<<<Hd * 4, 256>>>(x, alpha1, alpha2);// 2 chunks/warp (fp16)

    dim3 grid(Ls / 128, Hd / 64, Bsz);
    gemm_glu_kernel<<<grid, 256>>>(bconv, x, out);
}